// round 1
// baseline (speedup 1.0000x reference)
#include <cuda_runtime.h>
#include <math.h>

#define BB 128
#define LL 64
#define HH 512
#define VOCAB 32000
#define TT 32
#define NSTEP 31
#define BL (BB*LL)   // 8192

// ---------------- scratch (device globals; no allocation) ----------------
__device__ float g_encpart[BL*HH];   // enc @ W1a.T + b1 (step-invariant)
__device__ float g_a1[BL*HH];
__device__ float g_a2[BL*HH];
__device__ float g_hid[BB*HH];
__device__ float g_hidatt[BB*HH];
__device__ float g_ctx[BB*HH];
__device__ float g_xcat[BB*2*HH];
__device__ float g_gi[BB*3*HH];
__device__ float g_gh[BB*3*HH];
__device__ float g_logits[BB*VOCAB];
__device__ int   g_tgt[BB*TT];

// ---------------- targets dtype detection + conversion ----------------
// If targets arrived as int64 (little-endian), every odd 32-bit word of the
// first 4096 words is a high half of a value < 32000 -> zero. If int32, the
// odd words are random values in [0,32000) -> essentially surely nonzero.
__global__ void convert_targets_k(const int* __restrict__ raw, int* __restrict__ tgt, int n)
{
    __shared__ int nonzero;
    if (threadIdx.x == 0) nonzero = 0;
    __syncthreads();
    int bad = 0;
    for (int i = 2*threadIdx.x + 1; i < n; i += 2*blockDim.x) bad |= raw[i];
    if (bad) atomicOr(&nonzero, 1);
    __syncthreads();
    int is64 = (nonzero == 0);
    for (int i = threadIdx.x; i < n; i += blockDim.x)
        tgt[i] = is64 ? raw[2*i] : raw[i];
}

__global__ void copyf_k(float* __restrict__ dst, const float* __restrict__ src, int n)
{
    int i = blockIdx.x*blockDim.x + threadIdx.x;
    if (i < n) dst[i] = src[i];
}

// ---------------- GEMM: C[M,N] = act(A[M,K] @ W[N,K]^T + bias) ----------------
// 128x128 tile, BK=8, 256 threads, 8x8 per thread.
__global__ __launch_bounds__(256)
void gemm_k(const float* __restrict__ A, const float* __restrict__ W,
            const float* __restrict__ bias, float* __restrict__ C,
            int M, int N, int K, int ldA, int ldW, int act)
{
    __shared__ float As[8][128];
    __shared__ float Ws[8][128];
    const int tid  = threadIdx.x;
    const int tx   = tid & 15;
    const int ty   = tid >> 4;
    const int bm   = blockIdx.y * 128;
    const int bn   = blockIdx.x * 128;
    const int lrow = tid >> 1;
    const int lcol = (tid & 1) * 4;

    const float* Aptr = A + (size_t)(bm + lrow) * ldA + lcol;
    const float* Wptr = W + (size_t)(bn + lrow) * ldW + lcol;

    float acc[8][8];
#pragma unroll
    for (int i = 0; i < 8; i++)
#pragma unroll
        for (int j = 0; j < 8; j++) acc[i][j] = 0.f;

    for (int k0 = 0; k0 < K; k0 += 8) {
        float4 av = *reinterpret_cast<const float4*>(Aptr + k0);
        float4 wv = *reinterpret_cast<const float4*>(Wptr + k0);
        __syncthreads();
        As[lcol+0][lrow] = av.x; As[lcol+1][lrow] = av.y;
        As[lcol+2][lrow] = av.z; As[lcol+3][lrow] = av.w;
        Ws[lcol+0][lrow] = wv.x; Ws[lcol+1][lrow] = wv.y;
        Ws[lcol+2][lrow] = wv.z; Ws[lcol+3][lrow] = wv.w;
        __syncthreads();
#pragma unroll
        for (int kk = 0; kk < 8; kk++) {
            float4 a0 = *reinterpret_cast<const float4*>(&As[kk][ty*8]);
            float4 a1 = *reinterpret_cast<const float4*>(&As[kk][ty*8+4]);
            float4 w0 = *reinterpret_cast<const float4*>(&Ws[kk][tx*8]);
            float4 w1 = *reinterpret_cast<const float4*>(&Ws[kk][tx*8+4]);
            float a[8] = {a0.x,a0.y,a0.z,a0.w,a1.x,a1.y,a1.z,a1.w};
            float w[8] = {w0.x,w0.y,w0.z,w0.w,w1.x,w1.y,w1.z,w1.w};
#pragma unroll
            for (int i = 0; i < 8; i++)
#pragma unroll
                for (int j = 0; j < 8; j++)
                    acc[i][j] = fmaf(a[i], w[j], acc[i][j]);
        }
    }

    const int row = bm + ty*8;
    const int col = bn + tx*8;
#pragma unroll
    for (int i = 0; i < 8; i++) {
#pragma unroll
        for (int j = 0; j < 8; j++) {
            float v = acc[i][j];
            if (bias) v += bias[col + j];
            if (act)  v = tanhf(v);
            C[(size_t)(row + i) * N + col + j] = v;
        }
    }
}

// a1[bl,j] = tanh(encpart[bl,j] + hidatt[b,j]),  b = bl/64
__global__ void bcast_tanh_k(const float* __restrict__ ep, const float* __restrict__ ha,
                             float* __restrict__ a1)
{
    int idx = blockIdx.x * 256 + threadIdx.x;   // < BL*HH
    int bl = idx >> 9, j = idx & 511;
    int b  = bl >> 6;
    a1[idx] = tanhf(ep[idx] + ha[(b << 9) + j]);
}

// per-batch: e = a3 . v  -> softmax over L -> ctx = sum_l alpha * enc
__global__ void attention_ctx_k(const float* __restrict__ a3, const float* __restrict__ v,
                                const float* __restrict__ enc, float* __restrict__ ctx)
{
    int b = blockIdx.x, tid = threadIdx.x;
    int warp = tid >> 5, lane = tid & 31;
    __shared__ float e[LL];
    for (int l = warp; l < LL; l += 8) {
        const float* arow = a3 + (size_t)(b*LL + l) * HH;
        float s = 0.f;
        for (int j = lane; j < HH; j += 32) s += arow[j] * v[j];
#pragma unroll
        for (int o = 16; o > 0; o >>= 1) s += __shfl_down_sync(0xffffffffu, s, o);
        if (lane == 0) e[l] = s;
    }
    __syncthreads();
    if (tid == 0) {
        float mx = -1e30f;
        for (int l = 0; l < LL; l++) mx = fmaxf(mx, e[l]);
        float sum = 0.f;
        for (int l = 0; l < LL; l++) { e[l] = expf(e[l] - mx); sum += e[l]; }
        float inv = 1.f / sum;
        for (int l = 0; l < LL; l++) e[l] *= inv;
    }
    __syncthreads();
    for (int j = tid; j < HH; j += 256) {
        const float* ep = enc + (size_t)b*LL*HH + j;
        float s = 0.f;
#pragma unroll 8
        for (int l = 0; l < LL; l++) s = fmaf(e[l], ep[l*HH], s);
        ctx[b*HH + j] = s;
    }
}

// xcat[b] = [ embed_W[tgt[b,t]] , ctx[b] ]
__global__ void build_xcat_k(const float* __restrict__ embed_W, const int* __restrict__ tgt,
                             const float* __restrict__ ctx, float* __restrict__ xcat, int t)
{
    int b = blockIdx.x;
    int row = tgt[b*TT + t];
    for (int c = threadIdx.x; c < 2*HH; c += 256)
        xcat[b*2*HH + c] = (c < HH) ? embed_W[(size_t)row*HH + c] : ctx[b*HH + (c - HH)];
}

// GRU gates, in-place hidden update (elementwise per (b,j))
__global__ void gru_gates_k(const float* __restrict__ gi, const float* __restrict__ gh,
                            float* __restrict__ hid)
{
    int idx = blockIdx.x * 256 + threadIdx.x;  // < BB*HH
    int b = idx >> 9, j = idx & 511;
    const float* gib = gi + b*3*HH;
    const float* ghb = gh + b*3*HH;
    float r = 1.f / (1.f + expf(-(gib[j]        + ghb[j])));
    float z = 1.f / (1.f + expf(-(gib[HH + j]   + ghb[HH + j])));
    float n = tanhf(gib[2*HH + j] + r * ghb[2*HH + j]);
    hid[idx] = (1.f - z) * n + z * hid[idx];
}

__global__ void logsoftmax_k(const float* __restrict__ logits, float* __restrict__ out, int t)
{
    int b = blockIdx.x, tid = threadIdx.x;
    const float* row = logits + (size_t)b * VOCAB;
    __shared__ float red[256];
    float mx = -1e30f;
    for (int i = tid; i < VOCAB; i += 256) mx = fmaxf(mx, row[i]);
    red[tid] = mx; __syncthreads();
    for (int s = 128; s > 0; s >>= 1) { if (tid < s) red[tid] = fmaxf(red[tid], red[tid+s]); __syncthreads(); }
    mx = red[0]; __syncthreads();
    float sum = 0.f;
    for (int i = tid; i < VOCAB; i += 256) sum += expf(row[i] - mx);
    red[tid] = sum; __syncthreads();
    for (int s = 128; s > 0; s >>= 1) { if (tid < s) red[tid] += red[tid+s]; __syncthreads(); }
    float lse = mx + logf(red[0]);
    float* orow = out + ((size_t)b * NSTEP + t) * VOCAB;
    for (int i = tid; i < VOCAB; i += 256) orow[i] = row[i] - lse;
}

// ---------------- launch ----------------
extern "C" void kernel_launch(void* const* d_in, const int* in_sizes, int n_in,
                              void* d_out, int out_size)
{
    const float* enc     = (const float*)d_in[0];
    const float* enc_hid = (const float*)d_in[1];
    const int*   traw    = (const int*)  d_in[2];
    const float* embed_W = (const float*)d_in[3];
    const float* att_W1  = (const float*)d_in[4];
    const float* att_b1  = (const float*)d_in[5];
    const float* att_W2  = (const float*)d_in[6];
    const float* att_b2  = (const float*)d_in[7];
    const float* att_W3  = (const float*)d_in[8];
    const float* att_b3  = (const float*)d_in[9];
    const float* att_v   = (const float*)d_in[10];
    const float* gru_Wih = (const float*)d_in[11];
    const float* gru_Whh = (const float*)d_in[12];
    const float* gru_bih = (const float*)d_in[13];
    const float* gru_bhh = (const float*)d_in[14];
    const float* out_W   = (const float*)d_in[15];
    const float* out_b   = (const float*)d_in[16];
    float* out = (float*)d_out;

    float *encpart, *a1, *a2, *hid, *hidatt, *ctx, *xcat, *gi, *gh, *logits;
    int *tgt;
    cudaGetSymbolAddress((void**)&encpart, g_encpart);
    cudaGetSymbolAddress((void**)&a1,      g_a1);
    cudaGetSymbolAddress((void**)&a2,      g_a2);
    cudaGetSymbolAddress((void**)&hid,     g_hid);
    cudaGetSymbolAddress((void**)&hidatt,  g_hidatt);
    cudaGetSymbolAddress((void**)&ctx,     g_ctx);
    cudaGetSymbolAddress((void**)&xcat,    g_xcat);
    cudaGetSymbolAddress((void**)&gi,      g_gi);
    cudaGetSymbolAddress((void**)&gh,      g_gh);
    cudaGetSymbolAddress((void**)&logits,  g_logits);
    cudaGetSymbolAddress((void**)&tgt,     g_tgt);

    convert_targets_k<<<1, 256>>>(traw, tgt, BB*TT);
    copyf_k<<<(BB*HH + 255)/256, 256>>>(hid, enc_hid, BB*HH);

    // step-invariant: encpart = enc @ W1[:, :H]^T + b1   (W1 rows have ld 2H)
    gemm_k<<<dim3(HH/128, BL/128), 256>>>(enc, att_W1, att_b1, encpart,
                                          BL, HH, HH, HH, 2*HH, 0);

    for (int t = 0; t < NSTEP; t++) {
        // hid part of attention layer 1
        gemm_k<<<dim3(HH/128, 1), 256>>>(hid, att_W1 + HH, nullptr, hidatt,
                                         BB, HH, HH, HH, 2*HH, 0);
        bcast_tanh_k<<<(BL*HH)/256, 256>>>(encpart, hidatt, a1);
        // layers 2, 3
        gemm_k<<<dim3(HH/128, BL/128), 256>>>(a1, att_W2, att_b2, a2,
                                              BL, HH, HH, HH, HH, 1);
        gemm_k<<<dim3(HH/128, BL/128), 256>>>(a2, att_W3, att_b3, a1,
                                              BL, HH, HH, HH, HH, 1);
        attention_ctx_k<<<BB, 256>>>(a1, att_v, enc, ctx);
        build_xcat_k<<<BB, 256>>>(embed_W, tgt, ctx, xcat, t);
        // GRU
        gemm_k<<<dim3(3*HH/128, 1), 256>>>(xcat, gru_Wih, gru_bih, gi,
                                           BB, 3*HH, 2*HH, 2*HH, 2*HH, 0);
        gemm_k<<<dim3(3*HH/128, 1), 256>>>(hid, gru_Whh, gru_bhh, gh,
                                           BB, 3*HH, HH, HH, HH, 0);
        gru_gates_k<<<(BB*HH)/256, 256>>>(gi, gh, hid);
        // output projection + log-softmax straight into d_out
        gemm_k<<<dim3(VOCAB/128, 1), 256>>>(hid, out_W, out_b, logits,
                                            BB, VOCAB, HH, HH, HH, 0);
        logsoftmax_k<<<BB, 256>>>(logits, out, t);
    }
    (void)in_sizes; (void)n_in; (void)out_size; (void)att_v;
}

// round 2
// speedup vs baseline: 1.8765x; 1.8765x over previous
#include <cuda_runtime.h>
#include <math.h>
#include <stdint.h>

#define BB 128
#define LL 64
#define HH 512
#define VOCAB 32000
#define TT 32
#define NSTEP 31
#define BL (BB*LL)   // 8192

// ---------------- scratch (device globals; no allocation) ----------------
__device__ float g_encpart[BL*HH];   // enc @ W1a.T + b1 (step-invariant)
__device__ float g_a1[BL*HH];
__device__ float g_a2[BL*HH];
__device__ float g_hid[BB*HH];
__device__ float g_hidatt[BB*HH];
__device__ float g_ctx[BB*HH];
__device__ float g_xcat[BB*2*HH];
__device__ float g_gi[BB*3*HH];
__device__ float g_gh[BB*3*HH];
__device__ float g_logits[BB*VOCAB];
__device__ int   g_tgt[BB*TT];

// ---------------- targets dtype detection + conversion ----------------
__global__ void convert_targets_k(const int* __restrict__ raw, int* __restrict__ tgt, int n)
{
    __shared__ int nonzero;
    if (threadIdx.x == 0) nonzero = 0;
    __syncthreads();
    int bad = 0;
    for (int i = 2*threadIdx.x + 1; i < n; i += 2*blockDim.x) bad |= raw[i];
    if (bad) atomicOr(&nonzero, 1);
    __syncthreads();
    int is64 = (nonzero == 0);
    for (int i = threadIdx.x; i < n; i += blockDim.x)
        tgt[i] = is64 ? raw[2*i] : raw[i];
}

__global__ void copyf_k(float* __restrict__ dst, const float* __restrict__ src, int n)
{
    int i = blockIdx.x*blockDim.x + threadIdx.x;
    if (i < n) dst[i] = src[i];
}

// ---------------- TF32 tensor-core GEMM ----------------
// C[M,N] = act(A[M,K] @ W[N,K]^T + bias)
// BM=BN=128, BK=16, 256 threads = 8 warps (2 x 4), warp tile 64x32,
// mma.m16n8k8 tf32. M,N multiples of 128; K multiple of 16.
#define PITCH 20   // floats per smem row (16 data + 4 pad) -> conflict-free frags

__device__ __forceinline__ uint32_t f2tf(float x) {
    uint32_t u; asm("cvt.rna.tf32.f32 %0, %1;" : "=r"(u) : "f"(x)); return u;
}

__global__ __launch_bounds__(256)
void gemm_tf32_k(const float* __restrict__ A, const float* __restrict__ W,
                 const float* __restrict__ bias, float* __restrict__ C,
                 int M, int N, int K, int ldA, int ldW, int act)
{
    __shared__ float As[128*PITCH];
    __shared__ float Ws[128*PITCH];
    const int tid  = threadIdx.x;
    const int lane = tid & 31;
    const int wid  = tid >> 5;
    const int warpM = wid >> 2;   // 0..1
    const int warpN = wid & 3;    // 0..3
    const int gid = lane >> 2;    // 0..7
    const int tig = lane & 3;     // 0..3
    const int bm = blockIdx.y * 128;
    const int bn = blockIdx.x * 128;

    // global <-> smem mapping: each thread owns rows r0 and r0+64, quarter q0
    const int r0 = tid >> 2;
    const int q0 = (tid & 3) * 4;
    const float* Ag0 = A + (size_t)(bm + r0)      * ldA + q0;
    const float* Ag1 = A + (size_t)(bm + r0 + 64) * ldA + q0;
    const float* Wg0 = W + (size_t)(bn + r0)      * ldW + q0;
    const float* Wg1 = W + (size_t)(bn + r0 + 64) * ldW + q0;
    const int s0 = r0 * PITCH + q0;
    const int s1 = s0 + 64 * PITCH;

    float acc[4][4][4];
#pragma unroll
    for (int mt = 0; mt < 4; mt++)
#pragma unroll
        for (int nt = 0; nt < 4; nt++)
#pragma unroll
            for (int r = 0; r < 4; r++) acc[mt][nt][r] = 0.f;

    const int KT = K >> 4;
    float4 av0, av1, wv0, wv1;

    // prologue: tile 0
    av0 = *(const float4*)(Ag0); av1 = *(const float4*)(Ag1);
    wv0 = *(const float4*)(Wg0); wv1 = *(const float4*)(Wg1);
    {
        uint4 t;
        t.x=f2tf(av0.x); t.y=f2tf(av0.y); t.z=f2tf(av0.z); t.w=f2tf(av0.w);
        *(uint4*)(As + s0) = t;
        t.x=f2tf(av1.x); t.y=f2tf(av1.y); t.z=f2tf(av1.z); t.w=f2tf(av1.w);
        *(uint4*)(As + s1) = t;
        t.x=f2tf(wv0.x); t.y=f2tf(wv0.y); t.z=f2tf(wv0.z); t.w=f2tf(wv0.w);
        *(uint4*)(Ws + s0) = t;
        t.x=f2tf(wv1.x); t.y=f2tf(wv1.y); t.z=f2tf(wv1.z); t.w=f2tf(wv1.w);
        *(uint4*)(Ws + s1) = t;
    }

    for (int kt = 0; kt < KT; kt++) {
        __syncthreads();
        if (kt + 1 < KT) {
            int k0 = (kt + 1) << 4;
            av0 = *(const float4*)(Ag0 + k0); av1 = *(const float4*)(Ag1 + k0);
            wv0 = *(const float4*)(Wg0 + k0); wv1 = *(const float4*)(Wg1 + k0);
        }
#pragma unroll
        for (int ks = 0; ks < 16; ks += 8) {
            uint32_t af[4][4], bf[4][2];
#pragma unroll
            for (int mt = 0; mt < 4; mt++) {
                const float* p = &As[(warpM*64 + mt*16 + gid) * PITCH + ks + tig];
                af[mt][0] = __float_as_uint(p[0]);
                af[mt][1] = __float_as_uint(p[8*PITCH]);
                af[mt][2] = __float_as_uint(p[4]);
                af[mt][3] = __float_as_uint(p[8*PITCH + 4]);
            }
#pragma unroll
            for (int nt = 0; nt < 4; nt++) {
                const float* p = &Ws[(warpN*32 + nt*8 + gid) * PITCH + ks + tig];
                bf[nt][0] = __float_as_uint(p[0]);
                bf[nt][1] = __float_as_uint(p[4]);
            }
#pragma unroll
            for (int mt = 0; mt < 4; mt++)
#pragma unroll
                for (int nt = 0; nt < 4; nt++) {
                    float* d = acc[mt][nt];
                    asm volatile(
                        "mma.sync.aligned.m16n8k8.row.col.f32.tf32.tf32.f32 "
                        "{%0,%1,%2,%3},{%4,%5,%6,%7},{%8,%9},{%0,%1,%2,%3};"
                        : "+f"(d[0]), "+f"(d[1]), "+f"(d[2]), "+f"(d[3])
                        : "r"(af[mt][0]), "r"(af[mt][1]), "r"(af[mt][2]), "r"(af[mt][3]),
                          "r"(bf[nt][0]), "r"(bf[nt][1]));
                }
        }
        __syncthreads();
        if (kt + 1 < KT) {
            uint4 t;
            t.x=f2tf(av0.x); t.y=f2tf(av0.y); t.z=f2tf(av0.z); t.w=f2tf(av0.w);
            *(uint4*)(As + s0) = t;
            t.x=f2tf(av1.x); t.y=f2tf(av1.y); t.z=f2tf(av1.z); t.w=f2tf(av1.w);
            *(uint4*)(As + s1) = t;
            t.x=f2tf(wv0.x); t.y=f2tf(wv0.y); t.z=f2tf(wv0.z); t.w=f2tf(wv0.w);
            *(uint4*)(Ws + s0) = t;
            t.x=f2tf(wv1.x); t.y=f2tf(wv1.y); t.z=f2tf(wv1.z); t.w=f2tf(wv1.w);
            *(uint4*)(Ws + s1) = t;
        }
    }

    // epilogue
#pragma unroll
    for (int mt = 0; mt < 4; mt++) {
        int row = bm + warpM*64 + mt*16 + gid;
#pragma unroll
        for (int nt = 0; nt < 4; nt++) {
            int col = bn + warpN*32 + nt*8 + tig*2;
            float b0 = bias ? bias[col]     : 0.f;
            float b1 = bias ? bias[col + 1] : 0.f;
            float v0 = acc[mt][nt][0] + b0;
            float v1 = acc[mt][nt][1] + b1;
            float v2 = acc[mt][nt][2] + b0;
            float v3 = acc[mt][nt][3] + b1;
            if (act) { v0 = tanhf(v0); v1 = tanhf(v1); v2 = tanhf(v2); v3 = tanhf(v3); }
            float2 lo = make_float2(v0, v1);
            float2 hi = make_float2(v2, v3);
            *(float2*)&C[(size_t)row       * N + col] = lo;
            *(float2*)&C[(size_t)(row + 8) * N + col] = hi;
        }
    }
}

// ---------------- small fp32 GEMM (M=128 path, high block count) ----------------
// C[M,N] = A[M,K] @ W[N,K]^T + bias. Tile 128x64, BK=8, 256 threads, 8x4/thread.
__global__ __launch_bounds__(256)
void gemm_small_k(const float* __restrict__ A, const float* __restrict__ W,
                  const float* __restrict__ bias, float* __restrict__ C,
                  int M, int N, int K, int ldA, int ldW)
{
    __shared__ float As[8][128];
    __shared__ float Ws[8][72];
    const int tid = threadIdx.x;
    const int tx = tid & 15;   // n: 4 cols each
    const int ty = tid >> 4;   // m: 8 rows each
    const int bn = blockIdx.x * 64;
    const int bm = blockIdx.y * 128;

    float acc[8][4];
#pragma unroll
    for (int i = 0; i < 8; i++)
#pragma unroll
        for (int j = 0; j < 4; j++) acc[i][j] = 0.f;

    const int arow = tid >> 1, ac = (tid & 1) * 4;
    const float* Aptr = A + (size_t)(bm + arow) * ldA + ac;
    const int wrow = (tid & 127) >> 1, wc = (tid & 1) * 4;
    const float* Wptr = W + (size_t)(bn + wrow) * ldW + wc;

    for (int k0 = 0; k0 < K; k0 += 8) {
        float4 av = *(const float4*)(Aptr + k0);
        float4 wv = make_float4(0.f, 0.f, 0.f, 0.f);
        if (tid < 128) wv = *(const float4*)(Wptr + k0);
        __syncthreads();
        As[ac+0][arow] = av.x; As[ac+1][arow] = av.y;
        As[ac+2][arow] = av.z; As[ac+3][arow] = av.w;
        if (tid < 128) {
            Ws[wc+0][wrow] = wv.x; Ws[wc+1][wrow] = wv.y;
            Ws[wc+2][wrow] = wv.z; Ws[wc+3][wrow] = wv.w;
        }
        __syncthreads();
#pragma unroll
        for (int kk = 0; kk < 8; kk++) {
            float4 a0 = *(const float4*)&As[kk][ty*8];
            float4 a1 = *(const float4*)&As[kk][ty*8+4];
            float4 w0 = *(const float4*)&Ws[kk][tx*4];
            float a[8] = {a0.x,a0.y,a0.z,a0.w,a1.x,a1.y,a1.z,a1.w};
            float w[4] = {w0.x,w0.y,w0.z,w0.w};
#pragma unroll
            for (int i = 0; i < 8; i++)
#pragma unroll
                for (int j = 0; j < 4; j++)
                    acc[i][j] = fmaf(a[i], w[j], acc[i][j]);
        }
    }

    const int row = bm + ty*8;
    const int col = bn + tx*4;
#pragma unroll
    for (int i = 0; i < 8; i++) {
#pragma unroll
        for (int j = 0; j < 4; j++) {
            float v = acc[i][j];
            if (bias) v += bias[col + j];
            C[(size_t)(row + i) * N + col + j] = v;
        }
    }
}

// a1[bl,j] = tanh(encpart[bl,j] + hidatt[b,j]),  b = bl/64
__global__ void bcast_tanh_k(const float* __restrict__ ep, const float* __restrict__ ha,
                             float* __restrict__ a1)
{
    int idx = blockIdx.x * 256 + threadIdx.x;   // < BL*HH
    int bl = idx >> 9, j = idx & 511;
    int b  = bl >> 6;
    a1[idx] = tanhf(ep[idx] + ha[(b << 9) + j]);
}

// per-batch: e = a3 . v  -> softmax over L -> ctx = sum_l alpha * enc
__global__ void attention_ctx_k(const float* __restrict__ a3, const float* __restrict__ v,
                                const float* __restrict__ enc, float* __restrict__ ctx)
{
    int b = blockIdx.x, tid = threadIdx.x;
    int warp = tid >> 5, lane = tid & 31;
    __shared__ float e[LL];
    for (int l = warp; l < LL; l += 8) {
        const float* arow = a3 + (size_t)(b*LL + l) * HH;
        float s = 0.f;
        for (int j = lane; j < HH; j += 32) s += arow[j] * v[j];
#pragma unroll
        for (int o = 16; o > 0; o >>= 1) s += __shfl_down_sync(0xffffffffu, s, o);
        if (lane == 0) e[l] = s;
    }
    __syncthreads();
    if (tid == 0) {
        float mx = -1e30f;
        for (int l = 0; l < LL; l++) mx = fmaxf(mx, e[l]);
        float sum = 0.f;
        for (int l = 0; l < LL; l++) { e[l] = expf(e[l] - mx); sum += e[l]; }
        float inv = 1.f / sum;
        for (int l = 0; l < LL; l++) e[l] *= inv;
    }
    __syncthreads();
    for (int j = tid; j < HH; j += 256) {
        const float* ep = enc + (size_t)b*LL*HH + j;
        float s = 0.f;
#pragma unroll 8
        for (int l = 0; l < LL; l++) s = fmaf(e[l], ep[l*HH], s);
        ctx[b*HH + j] = s;
    }
}

// xcat[b] = [ embed_W[tgt[b,t]] , ctx[b] ]
__global__ void build_xcat_k(const float* __restrict__ embed_W, const int* __restrict__ tgt,
                             const float* __restrict__ ctx, float* __restrict__ xcat, int t)
{
    int b = blockIdx.x;
    int row = tgt[b*TT + t];
    for (int c = threadIdx.x; c < 2*HH; c += 256)
        xcat[b*2*HH + c] = (c < HH) ? embed_W[(size_t)row*HH + c] : ctx[b*HH + (c - HH)];
}

// GRU gates, in-place hidden update (elementwise per (b,j))
__global__ void gru_gates_k(const float* __restrict__ gi, const float* __restrict__ gh,
                            float* __restrict__ hid)
{
    int idx = blockIdx.x * 256 + threadIdx.x;  // < BB*HH
    int b = idx >> 9, j = idx & 511;
    const float* gib = gi + b*3*HH;
    const float* ghb = gh + b*3*HH;
    float r = 1.f / (1.f + expf(-(gib[j]        + ghb[j])));
    float z = 1.f / (1.f + expf(-(gib[HH + j]   + ghb[HH + j])));
    float n = tanhf(gib[2*HH + j] + r * ghb[2*HH + j]);
    hid[idx] = (1.f - z) * n + z * hid[idx];
}

__global__ void logsoftmax_k(const float* __restrict__ logits, float* __restrict__ out, int t)
{
    int b = blockIdx.x, tid = threadIdx.x;
    const float* row = logits + (size_t)b * VOCAB;
    __shared__ float red[256];
    float mx = -1e30f;
    for (int i = tid; i < VOCAB; i += 256) mx = fmaxf(mx, row[i]);
    red[tid] = mx; __syncthreads();
    for (int s = 128; s > 0; s >>= 1) { if (tid < s) red[tid] = fmaxf(red[tid], red[tid+s]); __syncthreads(); }
    mx = red[0]; __syncthreads();
    float sum = 0.f;
    for (int i = tid; i < VOCAB; i += 256) sum += expf(row[i] - mx);
    red[tid] = sum; __syncthreads();
    for (int s = 128; s > 0; s >>= 1) { if (tid < s) red[tid] += red[tid+s]; __syncthreads(); }
    float lse = mx + logf(red[0]);
    float* orow = out + ((size_t)b * NSTEP + t) * VOCAB;
    for (int i = tid; i < VOCAB; i += 256) orow[i] = row[i] - lse;
}

// ---------------- launch ----------------
extern "C" void kernel_launch(void* const* d_in, const int* in_sizes, int n_in,
                              void* d_out, int out_size)
{
    const float* enc     = (const float*)d_in[0];
    const float* enc_hid = (const float*)d_in[1];
    const int*   traw    = (const int*)  d_in[2];
    const float* embed_W = (const float*)d_in[3];
    const float* att_W1  = (const float*)d_in[4];
    const float* att_b1  = (const float*)d_in[5];
    const float* att_W2  = (const float*)d_in[6];
    const float* att_b2  = (const float*)d_in[7];
    const float* att_W3  = (const float*)d_in[8];
    const float* att_b3  = (const float*)d_in[9];
    const float* att_v   = (const float*)d_in[10];
    const float* gru_Wih = (const float*)d_in[11];
    const float* gru_Whh = (const float*)d_in[12];
    const float* gru_bih = (const float*)d_in[13];
    const float* gru_bhh = (const float*)d_in[14];
    const float* out_W   = (const float*)d_in[15];
    const float* out_b   = (const float*)d_in[16];
    float* out = (float*)d_out;

    float *encpart, *a1, *a2, *hid, *hidatt, *ctx, *xcat, *gi, *gh, *logits;
    int *tgt;
    cudaGetSymbolAddress((void**)&encpart, g_encpart);
    cudaGetSymbolAddress((void**)&a1,      g_a1);
    cudaGetSymbolAddress((void**)&a2,      g_a2);
    cudaGetSymbolAddress((void**)&hid,     g_hid);
    cudaGetSymbolAddress((void**)&hidatt,  g_hidatt);
    cudaGetSymbolAddress((void**)&ctx,     g_ctx);
    cudaGetSymbolAddress((void**)&xcat,    g_xcat);
    cudaGetSymbolAddress((void**)&gi,      g_gi);
    cudaGetSymbolAddress((void**)&gh,      g_gh);
    cudaGetSymbolAddress((void**)&logits,  g_logits);
    cudaGetSymbolAddress((void**)&tgt,     g_tgt);

    convert_targets_k<<<1, 256>>>(traw, tgt, BB*TT);
    copyf_k<<<(BB*HH + 255)/256, 256>>>(hid, enc_hid, BB*HH);

    // step-invariant: encpart = enc @ W1[:, :H]^T + b1  (tf32)
    gemm_tf32_k<<<dim3(HH/128, BL/128), 256>>>(enc, att_W1, att_b1, encpart,
                                               BL, HH, HH, HH, 2*HH, 0);

    for (int t = 0; t < NSTEP; t++) {
        // hid part of attention layer 1 (fp32, recurrent path)
        gemm_small_k<<<dim3(HH/64, 1), 256>>>(hid, att_W1 + HH, nullptr, hidatt,
                                              BB, HH, HH, HH, 2*HH);
        bcast_tanh_k<<<(BL*HH)/256, 256>>>(encpart, hidatt, a1);
        // attention layers 2, 3 (tf32 + fused tanh)
        gemm_tf32_k<<<dim3(HH/128, BL/128), 256>>>(a1, att_W2, att_b2, a2,
                                                   BL, HH, HH, HH, HH, 1);
        gemm_tf32_k<<<dim3(HH/128, BL/128), 256>>>(a2, att_W3, att_b3, a1,
                                                   BL, HH, HH, HH, HH, 1);
        attention_ctx_k<<<BB, 256>>>(a1, att_v, enc, ctx);
        build_xcat_k<<<BB, 256>>>(embed_W, tgt, ctx, xcat, t);
        // GRU (fp32, recurrent path)
        gemm_small_k<<<dim3(3*HH/64, 1), 256>>>(xcat, gru_Wih, gru_bih, gi,
                                                BB, 3*HH, 2*HH, 2*HH, 2*HH);
        gemm_small_k<<<dim3(3*HH/64, 1), 256>>>(hid, gru_Whh, gru_bhh, gh,
                                                BB, 3*HH, HH, HH, HH);
        gru_gates_k<<<(BB*HH)/256, 256>>>(gi, gh, hid);
        // output projection (tf32) + log-softmax straight into d_out
        gemm_tf32_k<<<dim3(VOCAB/128, 1), 256>>>(hid, out_W, out_b, logits,
                                                 BB, VOCAB, HH, HH, HH, 0);
        logsoftmax_k<<<BB, 256>>>(logits, out, t);
    }
    (void)in_sizes; (void)n_in; (void)out_size;
}

// round 3
// speedup vs baseline: 2.8377x; 1.5122x over previous
#include <cuda_runtime.h>
#include <math.h>
#include <stdint.h>

#define BB 128
#define LL 64
#define HH 512
#define VOCAB 32000
#define TT 32
#define NSTEP 31
#define BL (BB*LL)   // 8192

// ---------------- scratch (device globals; no allocation) ----------------
__device__ float g_encpart[BL*HH];   // enc @ W1a.T + b1 (step-invariant)
__device__ float g_a2[BL*HH];
__device__ float g_a3[BL*HH];
__device__ float g_hid[BB*HH];
__device__ float g_hgh[BB*2048];     // [hidatt(512) | gh(1536)]
__device__ float g_ctx[BB*HH];
__device__ float g_xcat[BB*2*HH];
__device__ float g_gi[BB*3*HH];
__device__ float g_logits[BB*VOCAB];
__device__ float g_Wpack[2048*HH];   // [W1_hid(512) ; Whh(1536)] rows x 512
__device__ float g_bpack[2048];
__device__ int   g_tgt[BB*TT];

// ---------------- targets dtype detection + conversion ----------------
__global__ void convert_targets_k(const int* __restrict__ raw, int* __restrict__ tgt, int n)
{
    __shared__ int nonzero;
    if (threadIdx.x == 0) nonzero = 0;
    __syncthreads();
    int bad = 0;
    for (int i = 2*threadIdx.x + 1; i < n; i += 2*blockDim.x) bad |= raw[i];
    if (bad) atomicOr(&nonzero, 1);
    __syncthreads();
    int is64 = (nonzero == 0);
    for (int i = threadIdx.x; i < n; i += blockDim.x)
        tgt[i] = is64 ? raw[2*i] : raw[i];
}

__global__ void copyf_k(float* __restrict__ dst, const float* __restrict__ src, int n)
{
    int i = blockIdx.x*blockDim.x + threadIdx.x;
    if (i < n) dst[i] = src[i];
}

// pack [att_W1[:,512:1024] ; gru_Whh] into g_Wpack; bias [0 ; gru_bhh]
__global__ void pack_whh_k(const float* __restrict__ W1, const float* __restrict__ Whh,
                           const float* __restrict__ bhh,
                           float* __restrict__ Wp, float* __restrict__ bp)
{
    int idx = blockIdx.x * 256 + threadIdx.x;   // < 2048*512
    int nn = idx >> 9, k = idx & 511;
    Wp[idx] = (nn < 512) ? W1[nn*1024 + 512 + k] : Whh[(nn-512)*512 + k];
    if (idx < 2048) bp[idx] = (idx < 512) ? 0.f : bhh[idx - 512];
}

// ---------------- TF32 tensor-core GEMM ----------------
// C[M,N] = act(A'[M,K] @ W[N,K]^T + bias)
// where A'[r,k] = ha ? tanh(A[r,k] + ha[(r>>6)*ha_ld + k]) : A[r,k]
// BM=BN=128, BK=16, 256 threads = 8 warps (2x4), warp tile 64x32, mma.m16n8k8 tf32.
#define PITCH 20

__device__ __forceinline__ uint32_t f2tf(float x) {
    uint32_t u; asm("cvt.rna.tf32.f32 %0, %1;" : "=r"(u) : "f"(x)); return u;
}
__device__ __forceinline__ float4 tanh4(float4 a, float4 h) {
    a.x = tanhf(a.x + h.x); a.y = tanhf(a.y + h.y);
    a.z = tanhf(a.z + h.z); a.w = tanhf(a.w + h.w);
    return a;
}

__global__ __launch_bounds__(256)
void gemm_tf32_k(const float* __restrict__ A, const float* __restrict__ W,
                 const float* __restrict__ bias, float* __restrict__ C,
                 int M, int N, int K, int ldA, int ldW, int act,
                 const float* __restrict__ ha, int ha_ld)
{
    __shared__ float As[128*PITCH];
    __shared__ float Ws[128*PITCH];
    const int tid  = threadIdx.x;
    const int lane = tid & 31;
    const int wid  = tid >> 5;
    const int warpM = wid >> 2;
    const int warpN = wid & 3;
    const int gid = lane >> 2;
    const int tig = lane & 3;
    const int bm = blockIdx.y * 128;
    const int bn = blockIdx.x * 128;

    const int r0 = tid >> 2;
    const int q0 = (tid & 3) * 4;
    const float* Ag0 = A + (size_t)(bm + r0)      * ldA + q0;
    const float* Ag1 = A + (size_t)(bm + r0 + 64) * ldA + q0;
    const float* Wg0 = W + (size_t)(bn + r0)      * ldW + q0;
    const float* Wg1 = W + (size_t)(bn + r0 + 64) * ldW + q0;
    const float* Hg0 = ha ? ha + (size_t)((bm + r0)      >> 6) * ha_ld + q0 : nullptr;
    const float* Hg1 = ha ? ha + (size_t)((bm + r0 + 64) >> 6) * ha_ld + q0 : nullptr;
    const int s0 = r0 * PITCH + q0;
    const int s1 = s0 + 64 * PITCH;

    float acc[4][4][4];
#pragma unroll
    for (int mt = 0; mt < 4; mt++)
#pragma unroll
        for (int nt = 0; nt < 4; nt++)
#pragma unroll
            for (int r = 0; r < 4; r++) acc[mt][nt][r] = 0.f;

    const int KT = K >> 4;
    float4 av0, av1, wv0, wv1;

    av0 = *(const float4*)(Ag0); av1 = *(const float4*)(Ag1);
    wv0 = *(const float4*)(Wg0); wv1 = *(const float4*)(Wg1);
    if (ha) { av0 = tanh4(av0, *(const float4*)(Hg0)); av1 = tanh4(av1, *(const float4*)(Hg1)); }
    {
        uint4 t;
        t.x=f2tf(av0.x); t.y=f2tf(av0.y); t.z=f2tf(av0.z); t.w=f2tf(av0.w);
        *(uint4*)(As + s0) = t;
        t.x=f2tf(av1.x); t.y=f2tf(av1.y); t.z=f2tf(av1.z); t.w=f2tf(av1.w);
        *(uint4*)(As + s1) = t;
        t.x=f2tf(wv0.x); t.y=f2tf(wv0.y); t.z=f2tf(wv0.z); t.w=f2tf(wv0.w);
        *(uint4*)(Ws + s0) = t;
        t.x=f2tf(wv1.x); t.y=f2tf(wv1.y); t.z=f2tf(wv1.z); t.w=f2tf(wv1.w);
        *(uint4*)(Ws + s1) = t;
    }

    for (int kt = 0; kt < KT; kt++) {
        __syncthreads();
        if (kt + 1 < KT) {
            int k0 = (kt + 1) << 4;
            av0 = *(const float4*)(Ag0 + k0); av1 = *(const float4*)(Ag1 + k0);
            wv0 = *(const float4*)(Wg0 + k0); wv1 = *(const float4*)(Wg1 + k0);
            if (ha) { av0 = tanh4(av0, *(const float4*)(Hg0 + k0));
                      av1 = tanh4(av1, *(const float4*)(Hg1 + k0)); }
        }
#pragma unroll
        for (int ks = 0; ks < 16; ks += 8) {
            uint32_t af[4][4], bf[4][2];
#pragma unroll
            for (int mt = 0; mt < 4; mt++) {
                const float* p = &As[(warpM*64 + mt*16 + gid) * PITCH + ks + tig];
                af[mt][0] = __float_as_uint(p[0]);
                af[mt][1] = __float_as_uint(p[8*PITCH]);
                af[mt][2] = __float_as_uint(p[4]);
                af[mt][3] = __float_as_uint(p[8*PITCH + 4]);
            }
#pragma unroll
            for (int nt = 0; nt < 4; nt++) {
                const float* p = &Ws[(warpN*32 + nt*8 + gid) * PITCH + ks + tig];
                bf[nt][0] = __float_as_uint(p[0]);
                bf[nt][1] = __float_as_uint(p[4]);
            }
#pragma unroll
            for (int mt = 0; mt < 4; mt++)
#pragma unroll
                for (int nt = 0; nt < 4; nt++) {
                    float* d = acc[mt][nt];
                    asm volatile(
                        "mma.sync.aligned.m16n8k8.row.col.f32.tf32.tf32.f32 "
                        "{%0,%1,%2,%3},{%4,%5,%6,%7},{%8,%9},{%0,%1,%2,%3};"
                        : "+f"(d[0]), "+f"(d[1]), "+f"(d[2]), "+f"(d[3])
                        : "r"(af[mt][0]), "r"(af[mt][1]), "r"(af[mt][2]), "r"(af[mt][3]),
                          "r"(bf[nt][0]), "r"(bf[nt][1]));
                }
        }
        __syncthreads();
        if (kt + 1 < KT) {
            uint4 t;
            t.x=f2tf(av0.x); t.y=f2tf(av0.y); t.z=f2tf(av0.z); t.w=f2tf(av0.w);
            *(uint4*)(As + s0) = t;
            t.x=f2tf(av1.x); t.y=f2tf(av1.y); t.z=f2tf(av1.z); t.w=f2tf(av1.w);
            *(uint4*)(As + s1) = t;
            t.x=f2tf(wv0.x); t.y=f2tf(wv0.y); t.z=f2tf(wv0.z); t.w=f2tf(wv0.w);
            *(uint4*)(Ws + s0) = t;
            t.x=f2tf(wv1.x); t.y=f2tf(wv1.y); t.z=f2tf(wv1.z); t.w=f2tf(wv1.w);
            *(uint4*)(Ws + s1) = t;
        }
    }

#pragma unroll
    for (int mt = 0; mt < 4; mt++) {
        int row = bm + warpM*64 + mt*16 + gid;
#pragma unroll
        for (int nt = 0; nt < 4; nt++) {
            int col = bn + warpN*32 + nt*8 + tig*2;
            float b0 = bias ? bias[col]     : 0.f;
            float b1 = bias ? bias[col + 1] : 0.f;
            float v0 = acc[mt][nt][0] + b0;
            float v1 = acc[mt][nt][1] + b1;
            float v2 = acc[mt][nt][2] + b0;
            float v3 = acc[mt][nt][3] + b1;
            if (act) { v0 = tanhf(v0); v1 = tanhf(v1); v2 = tanhf(v2); v3 = tanhf(v3); }
            *(float2*)&C[(size_t)row       * N + col] = make_float2(v0, v1);
            *(float2*)&C[(size_t)(row + 8) * N + col] = make_float2(v2, v3);
        }
    }
}

// per-batch: e = a3 . v  -> softmax over L -> ctx = sum_l alpha * enc
__global__ void attention_ctx_k(const float* __restrict__ a3, const float* __restrict__ v,
                                const float* __restrict__ enc, float* __restrict__ ctx)
{
    int b = blockIdx.x, tid = threadIdx.x;
    int warp = tid >> 5, lane = tid & 31;
    __shared__ float e[LL];
    for (int l = warp; l < LL; l += 8) {
        const float* arow = a3 + (size_t)(b*LL + l) * HH;
        float s = 0.f;
        for (int j = lane; j < HH; j += 32) s += arow[j] * v[j];
#pragma unroll
        for (int o = 16; o > 0; o >>= 1) s += __shfl_down_sync(0xffffffffu, s, o);
        if (lane == 0) e[l] = s;
    }
    __syncthreads();
    if (tid == 0) {
        float mx = -1e30f;
        for (int l = 0; l < LL; l++) mx = fmaxf(mx, e[l]);
        float sum = 0.f;
        for (int l = 0; l < LL; l++) { e[l] = expf(e[l] - mx); sum += e[l]; }
        float inv = 1.f / sum;
        for (int l = 0; l < LL; l++) e[l] *= inv;
    }
    __syncthreads();
    for (int j = tid; j < HH; j += 256) {
        const float* ep = enc + (size_t)b*LL*HH + j;
        float s = 0.f;
#pragma unroll 8
        for (int l = 0; l < LL; l++) s = fmaf(e[l], ep[l*HH], s);
        ctx[b*HH + j] = s;
    }
}

// xcat[b] = [ embed_W[tgt[b,t]] , ctx[b] ]
__global__ void build_xcat_k(const float* __restrict__ embed_W, const int* __restrict__ tgt,
                             const float* __restrict__ ctx, float* __restrict__ xcat, int t)
{
    int b = blockIdx.x;
    int row = tgt[b*TT + t];
    for (int c = threadIdx.x; c < 2*HH; c += 256)
        xcat[b*2*HH + c] = (c < HH) ? embed_W[(size_t)row*HH + c] : ctx[b*HH + (c - HH)];
}

// GRU gates, in-place hidden update. gh lives in hgh cols [512:2048), ld 2048.
__global__ void gru_gates_k(const float* __restrict__ gi, const float* __restrict__ hgh,
                            float* __restrict__ hid)
{
    int idx = blockIdx.x * 256 + threadIdx.x;  // < BB*HH
    int b = idx >> 9, j = idx & 511;
    const float* gib = gi  + b*3*HH;
    const float* ghb = hgh + b*2048 + 512;
    float r = 1.f / (1.f + expf(-(gib[j]        + ghb[j])));
    float z = 1.f / (1.f + expf(-(gib[HH + j]   + ghb[HH + j])));
    float n = tanhf(gib[2*HH + j] + r * ghb[2*HH + j]);
    hid[idx] = (1.f - z) * n + z * hid[idx];
}

__global__ void logsoftmax_k(const float* __restrict__ logits, float* __restrict__ out, int t)
{
    int b = blockIdx.x, tid = threadIdx.x;
    const float* row = logits + (size_t)b * VOCAB;
    __shared__ float red[256];
    float mx = -1e30f;
    for (int i = tid; i < VOCAB; i += 256) mx = fmaxf(mx, row[i]);
    red[tid] = mx; __syncthreads();
    for (int s = 128; s > 0; s >>= 1) { if (tid < s) red[tid] = fmaxf(red[tid], red[tid+s]); __syncthreads(); }
    mx = red[0]; __syncthreads();
    float sum = 0.f;
    for (int i = tid; i < VOCAB; i += 256) sum += expf(row[i] - mx);
    red[tid] = sum; __syncthreads();
    for (int s = 128; s > 0; s >>= 1) { if (tid < s) red[tid] += red[tid+s]; __syncthreads(); }
    float lse = mx + logf(red[0]);
    float* orow = out + ((size_t)b * NSTEP + t) * VOCAB;
    for (int i = tid; i < VOCAB; i += 256) orow[i] = row[i] - lse;
}

// ---------------- launch ----------------
extern "C" void kernel_launch(void* const* d_in, const int* in_sizes, int n_in,
                              void* d_out, int out_size)
{
    const float* enc     = (const float*)d_in[0];
    const float* enc_hid = (const float*)d_in[1];
    const int*   traw    = (const int*)  d_in[2];
    const float* embed_W = (const float*)d_in[3];
    const float* att_W1  = (const float*)d_in[4];
    const float* att_b1  = (const float*)d_in[5];
    const float* att_W2  = (const float*)d_in[6];
    const float* att_b2  = (const float*)d_in[7];
    const float* att_W3  = (const float*)d_in[8];
    const float* att_b3  = (const float*)d_in[9];
    const float* att_v   = (const float*)d_in[10];
    const float* gru_Wih = (const float*)d_in[11];
    const float* gru_Whh = (const float*)d_in[12];
    const float* gru_bih = (const float*)d_in[13];
    const float* gru_bhh = (const float*)d_in[14];
    const float* out_W   = (const float*)d_in[15];
    const float* out_b   = (const float*)d_in[16];
    float* out = (float*)d_out;

    float *encpart, *a2, *a3, *hid, *hgh, *ctx, *xcat, *gi, *logits, *Wpack, *bpack;
    int *tgt;
    cudaGetSymbolAddress((void**)&encpart, g_encpart);
    cudaGetSymbolAddress((void**)&a2,      g_a2);
    cudaGetSymbolAddress((void**)&a3,      g_a3);
    cudaGetSymbolAddress((void**)&hid,     g_hid);
    cudaGetSymbolAddress((void**)&hgh,     g_hgh);
    cudaGetSymbolAddress((void**)&ctx,     g_ctx);
    cudaGetSymbolAddress((void**)&xcat,    g_xcat);
    cudaGetSymbolAddress((void**)&gi,      g_gi);
    cudaGetSymbolAddress((void**)&logits,  g_logits);
    cudaGetSymbolAddress((void**)&Wpack,   g_Wpack);
    cudaGetSymbolAddress((void**)&bpack,   g_bpack);
    cudaGetSymbolAddress((void**)&tgt,     g_tgt);

    convert_targets_k<<<1, 256>>>(traw, tgt, BB*TT);
    copyf_k<<<(BB*HH + 255)/256, 256>>>(hid, enc_hid, BB*HH);
    pack_whh_k<<<(2048*HH)/256, 256>>>(att_W1, gru_Whh, gru_bhh, Wpack, bpack);

    // step-invariant: encpart = enc @ W1[:, :H]^T + b1  (tf32, no act)
    gemm_tf32_k<<<dim3(HH/128, BL/128), 256>>>(enc, att_W1, att_b1, encpart,
                                               BL, HH, HH, HH, 2*HH, 0, nullptr, 0);

    for (int t = 0; t < NSTEP; t++) {
        // [hidatt | gh] = hid @ [W1_hid ; Whh]^T + [0 ; bhh]   (one GEMM)
        gemm_tf32_k<<<dim3(2048/128, 1), 256>>>(hid, Wpack, bpack, hgh,
                                                BB, 2048, HH, HH, HH, 0, nullptr, 0);
        // layer 2 with fused A-side tanh(encpart + hidatt_b), output tanh
        gemm_tf32_k<<<dim3(HH/128, BL/128), 256>>>(encpart, att_W2, att_b2, a2,
                                                   BL, HH, HH, HH, HH, 1, hgh, 2048);
        // layer 3, output tanh
        gemm_tf32_k<<<dim3(HH/128, BL/128), 256>>>(a2, att_W3, att_b3, a3,
                                                   BL, HH, HH, HH, HH, 1, nullptr, 0);
        attention_ctx_k<<<BB, 256>>>(a3, att_v, enc, ctx);
        build_xcat_k<<<BB, 256>>>(embed_W, tgt, ctx, xcat, t);
        // gi = xcat @ Wih^T + bih
        gemm_tf32_k<<<dim3(3*HH/128, 1), 256>>>(xcat, gru_Wih, gru_bih, gi,
                                                BB, 3*HH, 2*HH, 2*HH, 2*HH, 0, nullptr, 0);
        gru_gates_k<<<(BB*HH)/256, 256>>>(gi, hgh, hid);
        // output projection + log-softmax
        gemm_tf32_k<<<dim3(VOCAB/128, 1), 256>>>(hid, out_W, out_b, logits,
                                                 BB, VOCAB, HH, HH, HH, 0, nullptr, 0);
        logsoftmax_k<<<BB, 256>>>(logits, out, t);
    }
    (void)in_sizes; (void)n_in; (void)out_size;
}

// round 4
// speedup vs baseline: 3.6083x; 1.2716x over previous
#include <cuda_runtime.h>
#include <cuda_bf16.h>
#include <math.h>
#include <stdint.h>

#define BB 128
#define LL 64
#define HH 512
#define VOCAB 32000
#define TT 32
#define NSTEP 31
#define BL (BB*LL)   // 8192

// ---------------- scratch (device globals; no allocation) ----------------
__device__ float g_encpart[BL*HH];            // fp32, once
__device__ __nv_bfloat16 g_encpb[BL*HH];      // encpart bf16
__device__ __nv_bfloat16 g_encb[BL*HH];       // enc bf16
__device__ __nv_bfloat16 g_a1b[BL*HH];
__device__ __nv_bfloat16 g_a2b[BL*HH];
__device__ __nv_bfloat16 g_a3b[BL*HH];
__device__ __nv_bfloat16 g_W2b[HH*HH];
__device__ __nv_bfloat16 g_W3b[HH*HH];
__device__ __nv_bfloat16 g_outWb[(size_t)VOCAB*HH];
__device__ __nv_bfloat16 g_hidb[BB*HH];
__device__ float g_hid[BB*HH];
__device__ float g_hgh[BB*2048];     // [hidatt(512) | gh(1536)]
__device__ float g_ctx[BB*HH];
__device__ float g_xcat[BB*2*HH];
__device__ float g_gi[BB*3*HH];
__device__ float g_logits[BB*VOCAB];
__device__ float g_Wpack[2048*HH];
__device__ float g_bpack[2048];
__device__ int   g_tgt[BB*TT];

// ---------------- helpers ----------------
__global__ void convert_targets_k(const int* __restrict__ raw, int* __restrict__ tgt, int n)
{
    __shared__ int nonzero;
    if (threadIdx.x == 0) nonzero = 0;
    __syncthreads();
    int bad = 0;
    for (int i = 2*threadIdx.x + 1; i < n; i += 2*blockDim.x) bad |= raw[i];
    if (bad) atomicOr(&nonzero, 1);
    __syncthreads();
    int is64 = (nonzero == 0);
    for (int i = threadIdx.x; i < n; i += blockDim.x)
        tgt[i] = is64 ? raw[2*i] : raw[i];
}

__global__ void copyf_k(float* __restrict__ dst, const float* __restrict__ src, int n)
{
    int i = blockIdx.x*blockDim.x + threadIdx.x;
    if (i < n) dst[i] = src[i];
}

__global__ void cvtf2b_k(const float* __restrict__ src, __nv_bfloat16* __restrict__ dst, int n)
{
    int i = blockIdx.x*256 + threadIdx.x;
    if (i < n) dst[i] = __float2bfloat16(src[i]);
}

__global__ void pack_whh_k(const float* __restrict__ W1, const float* __restrict__ Whh,
                           const float* __restrict__ bhh,
                           float* __restrict__ Wp, float* __restrict__ bp)
{
    int idx = blockIdx.x * 256 + threadIdx.x;   // < 2048*512
    int nn = idx >> 9, k = idx & 511;
    Wp[idx] = (nn < 512) ? W1[nn*1024 + 512 + k] : Whh[(nn-512)*512 + k];
    if (idx < 2048) bp[idx] = (idx < 512) ? 0.f : bhh[idx - 512];
}

// ---------------- TF32 GEMM (small recurrent-path GEMMs) ----------------
#define PITCH 20
__device__ __forceinline__ uint32_t f2tf(float x) {
    uint32_t u; asm("cvt.rna.tf32.f32 %0, %1;" : "=r"(u) : "f"(x)); return u;
}

__global__ __launch_bounds__(256)
void gemm_tf32_k(const float* __restrict__ A, const float* __restrict__ W,
                 const float* __restrict__ bias, float* __restrict__ C,
                 int M, int N, int K, int ldA, int ldW, int act)
{
    __shared__ float As[128*PITCH];
    __shared__ float Ws[128*PITCH];
    const int tid  = threadIdx.x;
    const int lane = tid & 31;
    const int wid  = tid >> 5;
    const int warpM = wid >> 2;
    const int warpN = wid & 3;
    const int gid = lane >> 2;
    const int tig = lane & 3;
    const int bm = blockIdx.y * 128;
    const int bn = blockIdx.x * 128;

    const int r0 = tid >> 2;
    const int q0 = (tid & 3) * 4;
    const float* Ag0 = A + (size_t)(bm + r0)      * ldA + q0;
    const float* Ag1 = A + (size_t)(bm + r0 + 64) * ldA + q0;
    const float* Wg0 = W + (size_t)(bn + r0)      * ldW + q0;
    const float* Wg1 = W + (size_t)(bn + r0 + 64) * ldW + q0;
    const int s0 = r0 * PITCH + q0;
    const int s1 = s0 + 64 * PITCH;

    float acc[4][4][4];
#pragma unroll
    for (int mt = 0; mt < 4; mt++)
#pragma unroll
        for (int nt = 0; nt < 4; nt++)
#pragma unroll
            for (int r = 0; r < 4; r++) acc[mt][nt][r] = 0.f;

    const int KT = K >> 4;
    float4 av0, av1, wv0, wv1;
    av0 = *(const float4*)(Ag0); av1 = *(const float4*)(Ag1);
    wv0 = *(const float4*)(Wg0); wv1 = *(const float4*)(Wg1);
    {
        uint4 t;
        t.x=f2tf(av0.x); t.y=f2tf(av0.y); t.z=f2tf(av0.z); t.w=f2tf(av0.w);
        *(uint4*)(As + s0) = t;
        t.x=f2tf(av1.x); t.y=f2tf(av1.y); t.z=f2tf(av1.z); t.w=f2tf(av1.w);
        *(uint4*)(As + s1) = t;
        t.x=f2tf(wv0.x); t.y=f2tf(wv0.y); t.z=f2tf(wv0.z); t.w=f2tf(wv0.w);
        *(uint4*)(Ws + s0) = t;
        t.x=f2tf(wv1.x); t.y=f2tf(wv1.y); t.z=f2tf(wv1.z); t.w=f2tf(wv1.w);
        *(uint4*)(Ws + s1) = t;
    }

    for (int kt = 0; kt < KT; kt++) {
        __syncthreads();
        if (kt + 1 < KT) {
            int k0 = (kt + 1) << 4;
            av0 = *(const float4*)(Ag0 + k0); av1 = *(const float4*)(Ag1 + k0);
            wv0 = *(const float4*)(Wg0 + k0); wv1 = *(const float4*)(Wg1 + k0);
        }
#pragma unroll
        for (int ks = 0; ks < 16; ks += 8) {
            uint32_t af[4][4], bf[4][2];
#pragma unroll
            for (int mt = 0; mt < 4; mt++) {
                const float* p = &As[(warpM*64 + mt*16 + gid) * PITCH + ks + tig];
                af[mt][0] = __float_as_uint(p[0]);
                af[mt][1] = __float_as_uint(p[8*PITCH]);
                af[mt][2] = __float_as_uint(p[4]);
                af[mt][3] = __float_as_uint(p[8*PITCH + 4]);
            }
#pragma unroll
            for (int nt = 0; nt < 4; nt++) {
                const float* p = &Ws[(warpN*32 + nt*8 + gid) * PITCH + ks + tig];
                bf[nt][0] = __float_as_uint(p[0]);
                bf[nt][1] = __float_as_uint(p[4]);
            }
#pragma unroll
            for (int mt = 0; mt < 4; mt++)
#pragma unroll
                for (int nt = 0; nt < 4; nt++) {
                    float* d = acc[mt][nt];
                    asm volatile(
                        "mma.sync.aligned.m16n8k8.row.col.f32.tf32.tf32.f32 "
                        "{%0,%1,%2,%3},{%4,%5,%6,%7},{%8,%9},{%0,%1,%2,%3};"
                        : "+f"(d[0]), "+f"(d[1]), "+f"(d[2]), "+f"(d[3])
                        : "r"(af[mt][0]), "r"(af[mt][1]), "r"(af[mt][2]), "r"(af[mt][3]),
                          "r"(bf[nt][0]), "r"(bf[nt][1]));
                }
        }
        __syncthreads();
        if (kt + 1 < KT) {
            uint4 t;
            t.x=f2tf(av0.x); t.y=f2tf(av0.y); t.z=f2tf(av0.z); t.w=f2tf(av0.w);
            *(uint4*)(As + s0) = t;
            t.x=f2tf(av1.x); t.y=f2tf(av1.y); t.z=f2tf(av1.z); t.w=f2tf(av1.w);
            *(uint4*)(As + s1) = t;
            t.x=f2tf(wv0.x); t.y=f2tf(wv0.y); t.z=f2tf(wv0.z); t.w=f2tf(wv0.w);
            *(uint4*)(Ws + s0) = t;
            t.x=f2tf(wv1.x); t.y=f2tf(wv1.y); t.z=f2tf(wv1.z); t.w=f2tf(wv1.w);
            *(uint4*)(Ws + s1) = t;
        }
    }

#pragma unroll
    for (int mt = 0; mt < 4; mt++) {
        int row = bm + warpM*64 + mt*16 + gid;
#pragma unroll
        for (int nt = 0; nt < 4; nt++) {
            int col = bn + warpN*32 + nt*8 + tig*2;
            float b0 = bias ? bias[col]     : 0.f;
            float b1 = bias ? bias[col + 1] : 0.f;
            float v0 = acc[mt][nt][0] + b0;
            float v1 = acc[mt][nt][1] + b1;
            float v2 = acc[mt][nt][2] + b0;
            float v3 = acc[mt][nt][3] + b1;
            if (act) { v0 = tanhf(v0); v1 = tanhf(v1); v2 = tanhf(v2); v3 = tanhf(v3); }
            *(float2*)&C[(size_t)row       * N + col] = make_float2(v0, v1);
            *(float2*)&C[(size_t)(row + 8) * N + col] = make_float2(v2, v3);
        }
    }
}

// ---------------- BF16 GEMM, cp.async 2-stage ----------------
// C[M,N] = act(A[M,K] @ W[N,K]^T + bias); A,W bf16; out fp32 or bf16.
// BM=BN=128, BK=32, 256 threads = 8 warps (2x4), warp tile 64x32, mma m16n8k16.
#define PB 40                 // bf16 pitch (20 words) -> conflict-free
#define STAGE_ELEMS (128*PB)  // 5120 bf16 per operand per stage

__device__ __forceinline__ void cp16(uint32_t dst, const void* src) {
    asm volatile("cp.async.cg.shared.global [%0], [%1], 16;" :: "r"(dst), "l"(src));
}

__global__ __launch_bounds__(256)
void gemm_bf16_k(const __nv_bfloat16* __restrict__ A, const __nv_bfloat16* __restrict__ W,
                 const float* __restrict__ bias, void* __restrict__ Cout,
                 int M, int N, int K, int ldA, int ldW, int act, int out_bf16)
{
    __shared__ __nv_bfloat16 As[2*STAGE_ELEMS];
    __shared__ __nv_bfloat16 Ws[2*STAGE_ELEMS];
    const int tid  = threadIdx.x;
    const int lane = tid & 31;
    const int wid  = tid >> 5;
    const int warpM = wid >> 2;
    const int warpN = wid & 3;
    const int gid = lane >> 2;
    const int tig = lane & 3;
    const int bm = blockIdx.y * 128;
    const int bn = blockIdx.x * 128;

    // loader mapping: 2 threads per row, each 16 bf16 (two 16B cp.async)
    const int row_ld = tid >> 1;
    const int col_ld = (tid & 1) * 16;
    const __nv_bfloat16* Ag = A + (size_t)(bm + row_ld) * ldA + col_ld;
    const __nv_bfloat16* Wg = W + (size_t)(bn + row_ld) * ldW + col_ld;
    const uint32_t sAbase = (uint32_t)__cvta_generic_to_shared(As) + (row_ld*PB + col_ld)*2;
    const uint32_t sWbase = (uint32_t)__cvta_generic_to_shared(Ws) + (row_ld*PB + col_ld)*2;
    const uint32_t stageB = STAGE_ELEMS*2;

    float acc[4][4][4];
#pragma unroll
    for (int mt = 0; mt < 4; mt++)
#pragma unroll
        for (int nt = 0; nt < 4; nt++)
#pragma unroll
            for (int r = 0; r < 4; r++) acc[mt][nt][r] = 0.f;

    const int KT = K >> 5;   // BK=32

    // prologue: stage 0
    cp16(sAbase,            Ag);
    cp16(sAbase + 16,       Ag + 8);
    cp16(sWbase,            Wg);
    cp16(sWbase + 16,       Wg + 8);
    asm volatile("cp.async.commit_group;" ::: "memory");

    for (int kt = 0; kt < KT; kt++) {
        const int buf = kt & 1;
        if (kt + 1 < KT) {
            const int nb = (kt + 1) & 1;
            const __nv_bfloat16* ag = Ag + (kt + 1) * 32;
            const __nv_bfloat16* wg = Wg + (kt + 1) * 32;
            cp16(sAbase + nb*stageB,      ag);
            cp16(sAbase + nb*stageB + 16, ag + 8);
            cp16(sWbase + nb*stageB,      wg);
            cp16(sWbase + nb*stageB + 16, wg + 8);
            asm volatile("cp.async.commit_group;" ::: "memory");
            asm volatile("cp.async.wait_group 1;" ::: "memory");
        } else {
            asm volatile("cp.async.wait_group 0;" ::: "memory");
        }
        __syncthreads();

        const __nv_bfloat16* Ab = As + buf*STAGE_ELEMS;
        const __nv_bfloat16* Wb = Ws + buf*STAGE_ELEMS;
#pragma unroll
        for (int ks = 0; ks < 2; ks++) {
            uint32_t af[4][4], bf[4][2];
#pragma unroll
            for (int mt = 0; mt < 4; mt++) {
                const __nv_bfloat16* p = &Ab[(warpM*64 + mt*16 + gid)*PB + ks*16 + tig*2];
                af[mt][0] = *(const uint32_t*)(p);
                af[mt][1] = *(const uint32_t*)(p + 8*PB);
                af[mt][2] = *(const uint32_t*)(p + 8);
                af[mt][3] = *(const uint32_t*)(p + 8*PB + 8);
            }
#pragma unroll
            for (int nt = 0; nt < 4; nt++) {
                const __nv_bfloat16* p = &Wb[(warpN*32 + nt*8 + gid)*PB + ks*16 + tig*2];
                bf[nt][0] = *(const uint32_t*)(p);
                bf[nt][1] = *(const uint32_t*)(p + 8);
            }
#pragma unroll
            for (int mt = 0; mt < 4; mt++)
#pragma unroll
                for (int nt = 0; nt < 4; nt++) {
                    float* d = acc[mt][nt];
                    asm volatile(
                        "mma.sync.aligned.m16n8k16.row.col.f32.bf16.bf16.f32 "
                        "{%0,%1,%2,%3},{%4,%5,%6,%7},{%8,%9},{%0,%1,%2,%3};"
                        : "+f"(d[0]), "+f"(d[1]), "+f"(d[2]), "+f"(d[3])
                        : "r"(af[mt][0]), "r"(af[mt][1]), "r"(af[mt][2]), "r"(af[mt][3]),
                          "r"(bf[nt][0]), "r"(bf[nt][1]));
                }
        }
        __syncthreads();
    }

#pragma unroll
    for (int mt = 0; mt < 4; mt++) {
        int row = bm + warpM*64 + mt*16 + gid;
#pragma unroll
        for (int nt = 0; nt < 4; nt++) {
            int col = bn + warpN*32 + nt*8 + tig*2;
            float b0 = bias ? bias[col]     : 0.f;
            float b1 = bias ? bias[col + 1] : 0.f;
            float v0 = acc[mt][nt][0] + b0;
            float v1 = acc[mt][nt][1] + b1;
            float v2 = acc[mt][nt][2] + b0;
            float v3 = acc[mt][nt][3] + b1;
            if (act) { v0 = tanhf(v0); v1 = tanhf(v1); v2 = tanhf(v2); v3 = tanhf(v3); }
            if (out_bf16) {
                __nv_bfloat16* Cb = (__nv_bfloat16*)Cout;
                __nv_bfloat162 lo; lo.x = __float2bfloat16(v0); lo.y = __float2bfloat16(v1);
                __nv_bfloat162 hi; hi.x = __float2bfloat16(v2); hi.y = __float2bfloat16(v3);
                *(__nv_bfloat162*)&Cb[(size_t)row       * N + col] = lo;
                *(__nv_bfloat162*)&Cb[(size_t)(row + 8) * N + col] = hi;
            } else {
                float* Cf = (float*)Cout;
                *(float2*)&Cf[(size_t)row       * N + col] = make_float2(v0, v1);
                *(float2*)&Cf[(size_t)(row + 8) * N + col] = make_float2(v2, v3);
            }
        }
    }
}

// a1b[bl,j] = bf16(tanh(encpb[bl,j] + hgh[b, j]))   (hidatt = hgh cols [0,512))
__global__ void bcast_tanh_bf16_k(const __nv_bfloat16* __restrict__ ep,
                                  const float* __restrict__ hgh,
                                  __nv_bfloat16* __restrict__ a1b)
{
    int idx = blockIdx.x * 256 + threadIdx.x;   // < BL*HH
    int bl = idx >> 9, j = idx & 511;
    int b  = bl >> 6;
    float x = __bfloat162float(ep[idx]) + hgh[b*2048 + j];
    a1b[idx] = __float2bfloat16(tanhf(x));
}

// per-batch: e = a3 . v -> softmax over L -> ctx = sum_l alpha * enc (bf16 in)
__global__ void attention_ctx_k(const __nv_bfloat16* __restrict__ a3, const float* __restrict__ v,
                                const __nv_bfloat16* __restrict__ enc, float* __restrict__ ctx)
{
    int b = blockIdx.x, tid = threadIdx.x;
    int warp = tid >> 5, lane = tid & 31;
    __shared__ float e[LL];
    for (int l = warp; l < LL; l += 8) {
        const __nv_bfloat16* arow = a3 + (size_t)(b*LL + l) * HH;
        float s = 0.f;
        for (int j = lane; j < HH; j += 32) s += __bfloat162float(arow[j]) * v[j];
#pragma unroll
        for (int o = 16; o > 0; o >>= 1) s += __shfl_down_sync(0xffffffffu, s, o);
        if (lane == 0) e[l] = s;
    }
    __syncthreads();
    if (tid == 0) {
        float mx = -1e30f;
        for (int l = 0; l < LL; l++) mx = fmaxf(mx, e[l]);
        float sum = 0.f;
        for (int l = 0; l < LL; l++) { e[l] = expf(e[l] - mx); sum += e[l]; }
        float inv = 1.f / sum;
        for (int l = 0; l < LL; l++) e[l] *= inv;
    }
    __syncthreads();
    for (int j = tid; j < HH; j += 256) {
        const __nv_bfloat16* ep = enc + (size_t)b*LL*HH + j;
        float s = 0.f;
#pragma unroll 8
        for (int l = 0; l < LL; l++) s = fmaf(e[l], __bfloat162float(ep[l*HH]), s);
        ctx[b*HH + j] = s;
    }
}

__global__ void build_xcat_k(const float* __restrict__ embed_W, const int* __restrict__ tgt,
                             const float* __restrict__ ctx, float* __restrict__ xcat, int t)
{
    int b = blockIdx.x;
    int row = tgt[b*TT + t];
    for (int c = threadIdx.x; c < 2*HH; c += 256)
        xcat[b*2*HH + c] = (c < HH) ? embed_W[(size_t)row*HH + c] : ctx[b*HH + (c - HH)];
}

// GRU gates (gh in hgh cols [512:2048)); writes hid fp32 and hidb bf16
__global__ void gru_gates_k(const float* __restrict__ gi, const float* __restrict__ hgh,
                            float* __restrict__ hid, __nv_bfloat16* __restrict__ hidb)
{
    int idx = blockIdx.x * 256 + threadIdx.x;  // < BB*HH
    int b = idx >> 9, j = idx & 511;
    const float* gib = gi  + b*3*HH;
    const float* ghb = hgh + b*2048 + 512;
    float r = 1.f / (1.f + expf(-(gib[j]        + ghb[j])));
    float z = 1.f / (1.f + expf(-(gib[HH + j]   + ghb[HH + j])));
    float n = tanhf(gib[2*HH + j] + r * ghb[2*HH + j]);
    float h = (1.f - z) * n + z * hid[idx];
    hid[idx]  = h;
    hidb[idx] = __float2bfloat16(h);
}

__global__ void logsoftmax_k(const float* __restrict__ logits, float* __restrict__ out, int t)
{
    int b = blockIdx.x, tid = threadIdx.x;
    const float4* row = (const float4*)(logits + (size_t)b * VOCAB);
    __shared__ float red[256];
    float mx = -1e30f;
    for (int i = tid; i < VOCAB/4; i += 256) {
        float4 v = row[i];
        mx = fmaxf(mx, fmaxf(fmaxf(v.x, v.y), fmaxf(v.z, v.w)));
    }
    red[tid] = mx; __syncthreads();
    for (int s = 128; s > 0; s >>= 1) { if (tid < s) red[tid] = fmaxf(red[tid], red[tid+s]); __syncthreads(); }
    mx = red[0]; __syncthreads();
    float sum = 0.f;
    for (int i = tid; i < VOCAB/4; i += 256) {
        float4 v = row[i];
        sum += expf(v.x - mx) + expf(v.y - mx) + expf(v.z - mx) + expf(v.w - mx);
    }
    red[tid] = sum; __syncthreads();
    for (int s = 128; s > 0; s >>= 1) { if (tid < s) red[tid] += red[tid+s]; __syncthreads(); }
    float lse = mx + logf(red[0]);
    float4* orow = (float4*)(out + ((size_t)b * NSTEP + t) * VOCAB);
    for (int i = tid; i < VOCAB/4; i += 256) {
        float4 v = row[i];
        v.x -= lse; v.y -= lse; v.z -= lse; v.w -= lse;
        orow[i] = v;
    }
}

// ---------------- launch ----------------
extern "C" void kernel_launch(void* const* d_in, const int* in_sizes, int n_in,
                              void* d_out, int out_size)
{
    const float* enc     = (const float*)d_in[0];
    const float* enc_hid = (const float*)d_in[1];
    const int*   traw    = (const int*)  d_in[2];
    const float* embed_W = (const float*)d_in[3];
    const float* att_W1  = (const float*)d_in[4];
    const float* att_b1  = (const float*)d_in[5];
    const float* att_W2  = (const float*)d_in[6];
    const float* att_b2  = (const float*)d_in[7];
    const float* att_W3  = (const float*)d_in[8];
    const float* att_b3  = (const float*)d_in[9];
    const float* att_v   = (const float*)d_in[10];
    const float* gru_Wih = (const float*)d_in[11];
    const float* gru_Whh = (const float*)d_in[12];
    const float* gru_bih = (const float*)d_in[13];
    const float* gru_bhh = (const float*)d_in[14];
    const float* out_W   = (const float*)d_in[15];
    const float* out_b   = (const float*)d_in[16];
    float* out = (float*)d_out;

    float *encpart, *hid, *hgh, *ctx, *xcat, *gi, *logits, *Wpack, *bpack;
    __nv_bfloat16 *encpb, *encb, *a1b, *a2b, *a3b, *W2b, *W3b, *outWb, *hidb;
    int *tgt;
    cudaGetSymbolAddress((void**)&encpart, g_encpart);
    cudaGetSymbolAddress((void**)&encpb,   g_encpb);
    cudaGetSymbolAddress((void**)&encb,    g_encb);
    cudaGetSymbolAddress((void**)&a1b,     g_a1b);
    cudaGetSymbolAddress((void**)&a2b,     g_a2b);
    cudaGetSymbolAddress((void**)&a3b,     g_a3b);
    cudaGetSymbolAddress((void**)&W2b,     g_W2b);
    cudaGetSymbolAddress((void**)&W3b,     g_W3b);
    cudaGetSymbolAddress((void**)&outWb,   g_outWb);
    cudaGetSymbolAddress((void**)&hidb,    g_hidb);
    cudaGetSymbolAddress((void**)&hid,     g_hid);
    cudaGetSymbolAddress((void**)&hgh,     g_hgh);
    cudaGetSymbolAddress((void**)&ctx,     g_ctx);
    cudaGetSymbolAddress((void**)&xcat,    g_xcat);
    cudaGetSymbolAddress((void**)&gi,      g_gi);
    cudaGetSymbolAddress((void**)&logits,  g_logits);
    cudaGetSymbolAddress((void**)&Wpack,   g_Wpack);
    cudaGetSymbolAddress((void**)&bpack,   g_bpack);
    cudaGetSymbolAddress((void**)&tgt,     g_tgt);

    convert_targets_k<<<1, 256>>>(traw, tgt, BB*TT);
    copyf_k<<<(BB*HH + 255)/256, 256>>>(hid, enc_hid, BB*HH);
    pack_whh_k<<<(2048*HH)/256, 256>>>(att_W1, gru_Whh, gru_bhh, Wpack, bpack);

    // one-time bf16 conversions
    cvtf2b_k<<<(HH*HH)/256, 256>>>(att_W2, W2b, HH*HH);
    cvtf2b_k<<<(HH*HH)/256, 256>>>(att_W3, W3b, HH*HH);
    cvtf2b_k<<<(VOCAB*HH)/256, 256>>>(out_W, outWb, VOCAB*HH);
    cvtf2b_k<<<(BL*HH)/256, 256>>>(enc, encb, BL*HH);

    // step-invariant: encpart = enc @ W1[:, :H]^T + b1 (tf32), then -> bf16
    gemm_tf32_k<<<dim3(HH/128, BL/128), 256>>>(enc, att_W1, att_b1, encpart,
                                               BL, HH, HH, HH, 2*HH, 0);
    cvtf2b_k<<<(BL*HH)/256, 256>>>(encpart, encpb, BL*HH);

    // initial hid -> bf16 for first vocab GEMM... (done per-step by gru; need t=0 value)
    cvtf2b_k<<<(BB*HH)/256, 256>>>(hid, hidb, BB*HH);

    for (int t = 0; t < NSTEP; t++) {
        // [hidatt | gh] = hid @ [W1_hid ; Whh]^T + [0 ; bhh]
        gemm_tf32_k<<<dim3(2048/128, 1), 256>>>(hid, Wpack, bpack, hgh,
                                                BB, 2048, HH, HH, HH, 0);
        bcast_tanh_bf16_k<<<(BL*HH)/256, 256>>>(encpb, hgh, a1b);
        // layers 2, 3 (bf16 tensor cores, tanh fused, bf16 out)
        gemm_bf16_k<<<dim3(HH/128, BL/128), 256>>>(a1b, W2b, att_b2, a2b,
                                                   BL, HH, HH, HH, HH, 1, 1);
        gemm_bf16_k<<<dim3(HH/128, BL/128), 256>>>(a2b, W3b, att_b3, a3b,
                                                   BL, HH, HH, HH, HH, 1, 1);
        attention_ctx_k<<<BB, 256>>>(a3b, att_v, encb, ctx);
        build_xcat_k<<<BB, 256>>>(embed_W, tgt, ctx, xcat, t);
        // gi = xcat @ Wih^T + bih (tf32)
        gemm_tf32_k<<<dim3(3*HH/128, 1), 256>>>(xcat, gru_Wih, gru_bih, gi,
                                                BB, 3*HH, 2*HH, 2*HH, 2*HH, 0);
        gru_gates_k<<<(BB*HH)/256, 256>>>(gi, hgh, hid, hidb);
        // vocab projection (bf16), fp32 logits
        gemm_bf16_k<<<dim3(VOCAB/128, 1), 256>>>(hidb, outWb, out_b, logits,
                                                 BB, VOCAB, HH, HH, HH, 0, 0);
        logsoftmax_k<<<BB, 256>>>(logits, out, t);
    }
    (void)in_sizes; (void)n_in; (void)out_size;
}

// round 5
// speedup vs baseline: 5.4620x; 1.5137x over previous
#include <cuda_runtime.h>
#include <cuda_bf16.h>
#include <math.h>
#include <stdint.h>

#define BB 128
#define LL 64
#define HH 512
#define VOCAB 32000
#define TT 32
#define NSTEP 31
#define BL (BB*LL)   // 8192
#define NVB (VOCAB/128)  // 250

// ---------------- scratch (device globals; no allocation) ----------------
__device__ float g_encpart[BL*HH];
__device__ __nv_bfloat16 g_encpb[BL*HH];
__device__ __nv_bfloat16 g_encb[BL*HH];
__device__ __nv_bfloat16 g_a1b[BL*HH];
__device__ __nv_bfloat16 g_a2b[BL*HH];
__device__ __nv_bfloat16 g_a3b[BL*HH];
__device__ __nv_bfloat16 g_W2b[HH*HH];
__device__ __nv_bfloat16 g_W3b[HH*HH];
__device__ __nv_bfloat16 g_outWb[(size_t)VOCAB*HH];
__device__ __nv_bfloat16 g_Wpackb[2048*HH];      // [W1_hid ; Whh] bf16
__device__ float g_bpack[2048];
__device__ __nv_bfloat16 g_Wihx[3*HH*HH];        // Wih[:, :512] bf16
__device__ __nv_bfloat16 g_Wihc[3*HH*HH];        // Wih[:, 512:] bf16
__device__ __nv_bfloat16 g_ebx[NSTEP*BB*HH];     // embedded inputs, all steps
__device__ float g_gix[(size_t)NSTEP*BB*3*HH];   // gi embed-part, all steps
__device__ float g_gic[BB*3*HH];
__device__ __nv_bfloat16 g_hidb[BB*HH];
__device__ float g_hid[BB*HH];
__device__ float g_hgh[BB*2048];                 // [hidatt(512) | gh(1536)]
__device__ __nv_bfloat16 g_ctxb[BB*HH];
__device__ float g_logits[BB*VOCAB];
__device__ int   g_tgt[BB*TT];

// ---------------- setup helpers ----------------
__global__ void convert_targets_k(const int* __restrict__ raw, int* __restrict__ tgt, int n)
{
    __shared__ int nonzero;
    if (threadIdx.x == 0) nonzero = 0;
    __syncthreads();
    int bad = 0;
    for (int i = 2*threadIdx.x + 1; i < n; i += 2*blockDim.x) bad |= raw[i];
    if (bad) atomicOr(&nonzero, 1);
    __syncthreads();
    int is64 = (nonzero == 0);
    for (int i = threadIdx.x; i < n; i += blockDim.x)
        tgt[i] = is64 ? raw[2*i] : raw[i];
}

__global__ void copyf_k(float* __restrict__ dst, const float* __restrict__ src, int n)
{
    int i = blockIdx.x*blockDim.x + threadIdx.x;
    if (i < n) dst[i] = src[i];
}

__global__ void cvtf2b_k(const float* __restrict__ src, __nv_bfloat16* __restrict__ dst, int n)
{
    int i = blockIdx.x*256 + threadIdx.x;
    if (i < n) dst[i] = __float2bfloat16(src[i]);
}

__global__ void pack_whhb_k(const float* __restrict__ W1, const float* __restrict__ Whh,
                            const float* __restrict__ bhh,
                            __nv_bfloat16* __restrict__ Wp, float* __restrict__ bp)
{
    int idx = blockIdx.x * 256 + threadIdx.x;   // < 2048*512
    int nn = idx >> 9, k = idx & 511;
    float v = (nn < 512) ? W1[nn*1024 + 512 + k] : Whh[(nn-512)*512 + k];
    Wp[idx] = __float2bfloat16(v);
    if (idx < 2048) bp[idx] = (idx < 512) ? 0.f : bhh[idx - 512];
}

__global__ void pack_wih_k(const float* __restrict__ Wih,
                           __nv_bfloat16* __restrict__ Wx, __nv_bfloat16* __restrict__ Wc)
{
    int idx = blockIdx.x * 256 + threadIdx.x;   // < 1536*512
    int n = idx >> 9, k = idx & 511;
    Wx[idx] = __float2bfloat16(Wih[n*1024 + k]);
    Wc[idx] = __float2bfloat16(Wih[n*1024 + 512 + k]);
}

__global__ void gather_embed_k(const float* __restrict__ embed_W, const int* __restrict__ tgt,
                               __nv_bfloat16* __restrict__ ebx)
{
    int r = blockIdx.x;          // t*BB + b, < NSTEP*BB
    int t = r >> 7, b = r & 127;
    int row = tgt[b*TT + t];
    const float4* src = (const float4*)(embed_W + (size_t)row*HH);
    __nv_bfloat16* dst = ebx + (size_t)r*HH;
    for (int c = threadIdx.x; c < HH/4; c += 128) {
        float4 v = src[c];
        __nv_bfloat162 p0; p0.x = __float2bfloat16(v.x); p0.y = __float2bfloat16(v.y);
        __nv_bfloat162 p1; p1.x = __float2bfloat16(v.z); p1.y = __float2bfloat16(v.w);
        *(__nv_bfloat162*)(dst + c*4)     = p0;
        *(__nv_bfloat162*)(dst + c*4 + 2) = p1;
    }
}

// ---------------- TF32 GEMM (one-time encpart only) ----------------
#define PITCH 20
__device__ __forceinline__ uint32_t f2tf(float x) {
    uint32_t u; asm("cvt.rna.tf32.f32 %0, %1;" : "=r"(u) : "f"(x)); return u;
}

__global__ __launch_bounds__(256)
void gemm_tf32_k(const float* __restrict__ A, const float* __restrict__ W,
                 const float* __restrict__ bias, float* __restrict__ C,
                 int M, int N, int K, int ldA, int ldW, int act)
{
    __shared__ float As[128*PITCH];
    __shared__ float Ws[128*PITCH];
    const int tid  = threadIdx.x;
    const int lane = tid & 31;
    const int wid  = tid >> 5;
    const int warpM = wid >> 2;
    const int warpN = wid & 3;
    const int gid = lane >> 2;
    const int tig = lane & 3;
    const int bm = blockIdx.y * 128;
    const int bn = blockIdx.x * 128;

    const int r0 = tid >> 2;
    const int q0 = (tid & 3) * 4;
    const float* Ag0 = A + (size_t)(bm + r0)      * ldA + q0;
    const float* Ag1 = A + (size_t)(bm + r0 + 64) * ldA + q0;
    const float* Wg0 = W + (size_t)(bn + r0)      * ldW + q0;
    const float* Wg1 = W + (size_t)(bn + r0 + 64) * ldW + q0;
    const int s0 = r0 * PITCH + q0;
    const int s1 = s0 + 64 * PITCH;

    float acc[4][4][4];
#pragma unroll
    for (int mt = 0; mt < 4; mt++)
#pragma unroll
        for (int nt = 0; nt < 4; nt++)
#pragma unroll
            for (int r = 0; r < 4; r++) acc[mt][nt][r] = 0.f;

    const int KT = K >> 4;
    float4 av0, av1, wv0, wv1;
    av0 = *(const float4*)(Ag0); av1 = *(const float4*)(Ag1);
    wv0 = *(const float4*)(Wg0); wv1 = *(const float4*)(Wg1);
    {
        uint4 t;
        t.x=f2tf(av0.x); t.y=f2tf(av0.y); t.z=f2tf(av0.z); t.w=f2tf(av0.w);
        *(uint4*)(As + s0) = t;
        t.x=f2tf(av1.x); t.y=f2tf(av1.y); t.z=f2tf(av1.z); t.w=f2tf(av1.w);
        *(uint4*)(As + s1) = t;
        t.x=f2tf(wv0.x); t.y=f2tf(wv0.y); t.z=f2tf(wv0.z); t.w=f2tf(wv0.w);
        *(uint4*)(Ws + s0) = t;
        t.x=f2tf(wv1.x); t.y=f2tf(wv1.y); t.z=f2tf(wv1.z); t.w=f2tf(wv1.w);
        *(uint4*)(Ws + s1) = t;
    }

    for (int kt = 0; kt < KT; kt++) {
        __syncthreads();
        if (kt + 1 < KT) {
            int k0 = (kt + 1) << 4;
            av0 = *(const float4*)(Ag0 + k0); av1 = *(const float4*)(Ag1 + k0);
            wv0 = *(const float4*)(Wg0 + k0); wv1 = *(const float4*)(Wg1 + k0);
        }
#pragma unroll
        for (int ks = 0; ks < 16; ks += 8) {
            uint32_t af[4][4], bf[4][2];
#pragma unroll
            for (int mt = 0; mt < 4; mt++) {
                const float* p = &As[(warpM*64 + mt*16 + gid) * PITCH + ks + tig];
                af[mt][0] = __float_as_uint(p[0]);
                af[mt][1] = __float_as_uint(p[8*PITCH]);
                af[mt][2] = __float_as_uint(p[4]);
                af[mt][3] = __float_as_uint(p[8*PITCH + 4]);
            }
#pragma unroll
            for (int nt = 0; nt < 4; nt++) {
                const float* p = &Ws[(warpN*32 + nt*8 + gid) * PITCH + ks + tig];
                bf[nt][0] = __float_as_uint(p[0]);
                bf[nt][1] = __float_as_uint(p[4]);
            }
#pragma unroll
            for (int mt = 0; mt < 4; mt++)
#pragma unroll
                for (int nt = 0; nt < 4; nt++) {
                    float* d = acc[mt][nt];
                    asm volatile(
                        "mma.sync.aligned.m16n8k8.row.col.f32.tf32.tf32.f32 "
                        "{%0,%1,%2,%3},{%4,%5,%6,%7},{%8,%9},{%0,%1,%2,%3};"
                        : "+f"(d[0]), "+f"(d[1]), "+f"(d[2]), "+f"(d[3])
                        : "r"(af[mt][0]), "r"(af[mt][1]), "r"(af[mt][2]), "r"(af[mt][3]),
                          "r"(bf[nt][0]), "r"(bf[nt][1]));
                }
        }
        __syncthreads();
        if (kt + 1 < KT) {
            uint4 t;
            t.x=f2tf(av0.x); t.y=f2tf(av0.y); t.z=f2tf(av0.z); t.w=f2tf(av0.w);
            *(uint4*)(As + s0) = t;
            t.x=f2tf(av1.x); t.y=f2tf(av1.y); t.z=f2tf(av1.z); t.w=f2tf(av1.w);
            *(uint4*)(As + s1) = t;
            t.x=f2tf(wv0.x); t.y=f2tf(wv0.y); t.z=f2tf(wv0.z); t.w=f2tf(wv0.w);
            *(uint4*)(Ws + s0) = t;
            t.x=f2tf(wv1.x); t.y=f2tf(wv1.y); t.z=f2tf(wv1.z); t.w=f2tf(wv1.w);
            *(uint4*)(Ws + s1) = t;
        }
    }

#pragma unroll
    for (int mt = 0; mt < 4; mt++) {
        int row = bm + warpM*64 + mt*16 + gid;
#pragma unroll
        for (int nt = 0; nt < 4; nt++) {
            int col = bn + warpN*32 + nt*8 + tig*2;
            float b0 = bias ? bias[col]     : 0.f;
            float b1 = bias ? bias[col + 1] : 0.f;
            float v0 = acc[mt][nt][0] + b0;
            float v1 = acc[mt][nt][1] + b1;
            float v2 = acc[mt][nt][2] + b0;
            float v3 = acc[mt][nt][3] + b1;
            if (act) { v0 = tanhf(v0); v1 = tanhf(v1); v2 = tanhf(v2); v3 = tanhf(v3); }
            *(float2*)&C[(size_t)row       * N + col] = make_float2(v0, v1);
            *(float2*)&C[(size_t)(row + 8) * N + col] = make_float2(v2, v3);
        }
    }
}

// ---------------- BF16 GEMM core (cp.async 2-stage) ----------------
#define PB 40
#define STAGE_ELEMS (128*PB)

__device__ __forceinline__ void cp16(uint32_t dst, const void* src) {
    asm volatile("cp.async.cg.shared.global [%0], [%1], 16;" :: "r"(dst), "l"(src));
}

__device__ __forceinline__ void gemm_bf16_body(
    const __nv_bfloat16* __restrict__ A, const __nv_bfloat16* __restrict__ W,
    const float* __restrict__ bias, void* __restrict__ Cout,
    int N, int K, int ldA, int ldW, int act, int out_bf16, int bm, int bn)
{
    __shared__ __nv_bfloat16 As[2*STAGE_ELEMS];
    __shared__ __nv_bfloat16 Ws[2*STAGE_ELEMS];
    const int tid  = threadIdx.x;
    const int lane = tid & 31;
    const int wid  = tid >> 5;
    const int warpM = wid >> 2;
    const int warpN = wid & 3;
    const int gid = lane >> 2;
    const int tig = lane & 3;

    const int row_ld = tid >> 1;
    const int col_ld = (tid & 1) * 16;
    const __nv_bfloat16* Ag = A + (size_t)(bm + row_ld) * ldA + col_ld;
    const __nv_bfloat16* Wg = W + (size_t)(bn + row_ld) * ldW + col_ld;
    const uint32_t sAbase = (uint32_t)__cvta_generic_to_shared(As) + (row_ld*PB + col_ld)*2;
    const uint32_t sWbase = (uint32_t)__cvta_generic_to_shared(Ws) + (row_ld*PB + col_ld)*2;
    const uint32_t stageB = STAGE_ELEMS*2;

    float acc[4][4][4];
#pragma unroll
    for (int mt = 0; mt < 4; mt++)
#pragma unroll
        for (int nt = 0; nt < 4; nt++)
#pragma unroll
            for (int r = 0; r < 4; r++) acc[mt][nt][r] = 0.f;

    const int KT = K >> 5;

    cp16(sAbase,      Ag);
    cp16(sAbase + 16, Ag + 8);
    cp16(sWbase,      Wg);
    cp16(sWbase + 16, Wg + 8);
    asm volatile("cp.async.commit_group;" ::: "memory");

    for (int kt = 0; kt < KT; kt++) {
        const int buf = kt & 1;
        if (kt + 1 < KT) {
            const int nb = (kt + 1) & 1;
            const __nv_bfloat16* ag = Ag + (kt + 1) * 32;
            const __nv_bfloat16* wg = Wg + (kt + 1) * 32;
            cp16(sAbase + nb*stageB,      ag);
            cp16(sAbase + nb*stageB + 16, ag + 8);
            cp16(sWbase + nb*stageB,      wg);
            cp16(sWbase + nb*stageB + 16, wg + 8);
            asm volatile("cp.async.commit_group;" ::: "memory");
            asm volatile("cp.async.wait_group 1;" ::: "memory");
        } else {
            asm volatile("cp.async.wait_group 0;" ::: "memory");
        }
        __syncthreads();

        const __nv_bfloat16* Ab = As + buf*STAGE_ELEMS;
        const __nv_bfloat16* Wb = Ws + buf*STAGE_ELEMS;
#pragma unroll
        for (int ks = 0; ks < 2; ks++) {
            uint32_t af[4][4], bf[4][2];
#pragma unroll
            for (int mt = 0; mt < 4; mt++) {
                const __nv_bfloat16* p = &Ab[(warpM*64 + mt*16 + gid)*PB + ks*16 + tig*2];
                af[mt][0] = *(const uint32_t*)(p);
                af[mt][1] = *(const uint32_t*)(p + 8*PB);
                af[mt][2] = *(const uint32_t*)(p + 8);
                af[mt][3] = *(const uint32_t*)(p + 8*PB + 8);
            }
#pragma unroll
            for (int nt = 0; nt < 4; nt++) {
                const __nv_bfloat16* p = &Wb[(warpN*32 + nt*8 + gid)*PB + ks*16 + tig*2];
                bf[nt][0] = *(const uint32_t*)(p);
                bf[nt][1] = *(const uint32_t*)(p + 8);
            }
#pragma unroll
            for (int mt = 0; mt < 4; mt++)
#pragma unroll
                for (int nt = 0; nt < 4; nt++) {
                    float* d = acc[mt][nt];
                    asm volatile(
                        "mma.sync.aligned.m16n8k16.row.col.f32.bf16.bf16.f32 "
                        "{%0,%1,%2,%3},{%4,%5,%6,%7},{%8,%9},{%0,%1,%2,%3};"
                        : "+f"(d[0]), "+f"(d[1]), "+f"(d[2]), "+f"(d[3])
                        : "r"(af[nt&0?0:mt][0]), "r"(af[mt][1]), "r"(af[mt][2]), "r"(af[mt][3]),
                          "r"(bf[nt][0]), "r"(bf[nt][1]));
                }
        }
        __syncthreads();
    }

#pragma unroll
    for (int mt = 0; mt < 4; mt++) {
        int row = bm + warpM*64 + mt*16 + gid;
#pragma unroll
        for (int nt = 0; nt < 4; nt++) {
            int col = bn + warpN*32 + nt*8 + tig*2;
            float b0 = bias ? bias[col]     : 0.f;
            float b1 = bias ? bias[col + 1] : 0.f;
            float v0 = acc[mt][nt][0] + b0;
            float v1 = acc[mt][nt][1] + b1;
            float v2 = acc[mt][nt][2] + b0;
            float v3 = acc[mt][nt][3] + b1;
            if (act) { v0 = tanhf(v0); v1 = tanhf(v1); v2 = tanhf(v2); v3 = tanhf(v3); }
            if (out_bf16) {
                __nv_bfloat16* Cb = (__nv_bfloat16*)Cout;
                __nv_bfloat162 lo; lo.x = __float2bfloat16(v0); lo.y = __float2bfloat16(v1);
                __nv_bfloat162 hi; hi.x = __float2bfloat16(v2); hi.y = __float2bfloat16(v3);
                *(__nv_bfloat162*)&Cb[(size_t)row       * N + col] = lo;
                *(__nv_bfloat162*)&Cb[(size_t)(row + 8) * N + col] = hi;
            } else {
                float* Cf = (float*)Cout;
                *(float2*)&Cf[(size_t)row       * N + col] = make_float2(v0, v1);
                *(float2*)&Cf[(size_t)(row + 8) * N + col] = make_float2(v2, v3);
            }
        }
    }
}

__global__ __launch_bounds__(256)
void gemm_bf16_k(const __nv_bfloat16* __restrict__ A, const __nv_bfloat16* __restrict__ W,
                 const float* __restrict__ bias, void* __restrict__ Cout,
                 int N, int K, int ldA, int ldW, int act, int out_bf16)
{
    gemm_bf16_body(A, W, bias, Cout, N, K, ldA, ldW, act, out_bf16,
                   blockIdx.y*128, blockIdx.x*128);
}

// grouped: vocab projection (250 blocks) + [hidatt|gh] GEMM (16 blocks)
__global__ __launch_bounds__(256)
void gemm_dual_k(const __nv_bfloat16* __restrict__ hidb,
                 const __nv_bfloat16* __restrict__ outWb, const float* __restrict__ out_b,
                 float* __restrict__ logits,
                 const __nv_bfloat16* __restrict__ Wpackb, const float* __restrict__ bpack,
                 float* __restrict__ hgh)
{
    if (blockIdx.x < NVB)
        gemm_bf16_body(hidb, outWb, out_b, logits, VOCAB, HH, HH, HH, 0, 0,
                       0, blockIdx.x*128);
    else
        gemm_bf16_body(hidb, Wpackb, bpack, hgh, 2048, HH, HH, HH, 0, 0,
                       0, (blockIdx.x - NVB)*128);
}

// ---------------- heterogeneous: logsoftmax(t-1) + bcast_tanh(t) ----------------
__global__ void hetero_k(const float* __restrict__ logits, float* __restrict__ out, int t_lsm,
                         const __nv_bfloat16* __restrict__ encpb, const float* __restrict__ hgh,
                         __nv_bfloat16* __restrict__ a1b)
{
    const int tid = threadIdx.x;
    if (blockIdx.x < BB) {
        if (t_lsm < 0) return;
        int b = blockIdx.x;
        const float4* row = (const float4*)(logits + (size_t)b * VOCAB);
        __shared__ float rm[256], rs[256];
        float m = -1e30f, s = 0.f;
        for (int i = tid; i < VOCAB/4; i += 256) {
            float4 v = row[i];
#define ONLN(x) { float d = (x) - m; if (d > 0.f) { s = s*expf(-d) + 1.f; m = (x); } else s += expf(d); }
            ONLN(v.x) ONLN(v.y) ONLN(v.z) ONLN(v.w)
#undef ONLN
        }
        rm[tid] = m; rs[tid] = s; __syncthreads();
        for (int st = 128; st > 0; st >>= 1) {
            if (tid < st) {
                float m2 = rm[tid+st], s2 = rs[tid+st];
                float M = fmaxf(rm[tid], m2);
                rs[tid] = rs[tid]*expf(rm[tid]-M) + s2*expf(m2-M);
                rm[tid] = M;
            }
            __syncthreads();
        }
        float lse = rm[0] + logf(rs[0]);
        float4* orow = (float4*)(out + ((size_t)b * NSTEP + t_lsm) * VOCAB);
        for (int i = tid; i < VOCAB/4; i += 256) {
            float4 v = row[i];
            v.x -= lse; v.y -= lse; v.z -= lse; v.w -= lse;
            orow[i] = v;
        }
    } else {
        // bcast_tanh: a1b = bf16(tanh(encpb + hidatt_b)), 8 elems per thread
        int idx = (blockIdx.x - BB)*256 + tid;
        int base = idx * 8;                 // < BL*HH
        int b  = base >> 15;                // /(LL*HH)
        int j0 = base & 511;
        uint4 ev = *(const uint4*)(encpb + base);
        float4 h0 = *(const float4*)(hgh + b*2048 + j0);
        float4 h1 = *(const float4*)(hgh + b*2048 + j0 + 4);
        const __nv_bfloat162* e2 = (const __nv_bfloat162*)&ev;
        float hf[8] = {h0.x,h0.y,h0.z,h0.w,h1.x,h1.y,h1.z,h1.w};
        uint4 ov;
        __nv_bfloat162* o2 = (__nv_bfloat162*)&ov;
#pragma unroll
        for (int q = 0; q < 4; q++) {
            float2 ef = __bfloat1622float2(e2[q]);
            __nv_bfloat162 r;
            r.x = __float2bfloat16(tanhf(ef.x + hf[q*2]));
            r.y = __float2bfloat16(tanhf(ef.y + hf[q*2+1]));
            o2[q] = r;
        }
        *(uint4*)(a1b + base) = ov;
    }
}

// per-batch: e = a3 . v -> softmax over L -> ctxb = bf16(sum_l alpha * enc)
__global__ void attention_ctx_k(const __nv_bfloat16* __restrict__ a3, const float* __restrict__ v,
                                const __nv_bfloat16* __restrict__ enc, __nv_bfloat16* __restrict__ ctxb)
{
    int b = blockIdx.x, tid = threadIdx.x;
    int warp = tid >> 5, lane = tid & 31;
    __shared__ float e[LL];
    for (int l = warp; l < LL; l += 8) {
        const __nv_bfloat16* arow = a3 + (size_t)(b*LL + l) * HH;
        float s = 0.f;
        for (int j = lane; j < HH; j += 32) s += __bfloat162float(arow[j]) * v[j];
#pragma unroll
        for (int o = 16; o > 0; o >>= 1) s += __shfl_down_sync(0xffffffffu, s, o);
        if (lane == 0) e[l] = s;
    }
    __syncthreads();
    if (tid == 0) {
        float mx = -1e30f;
        for (int l = 0; l < LL; l++) mx = fmaxf(mx, e[l]);
        float sum = 0.f;
        for (int l = 0; l < LL; l++) { e[l] = expf(e[l] - mx); sum += e[l]; }
        float inv = 1.f / sum;
        for (int l = 0; l < LL; l++) e[l] *= inv;
    }
    __syncthreads();
    for (int j = tid; j < HH; j += 256) {
        const __nv_bfloat16* ep = enc + (size_t)b*LL*HH + j;
        float s = 0.f;
#pragma unroll 8
        for (int l = 0; l < LL; l++) s = fmaf(e[l], __bfloat162float(ep[l*HH]), s);
        ctxb[b*HH + j] = __float2bfloat16(s);
    }
}

// GRU gates: gi = gix[t] + gic, gh from hgh; updates hid fp32 + hidb bf16
__global__ void gru_gates_k(const float* __restrict__ gix, const float* __restrict__ gic,
                            const float* __restrict__ hgh,
                            float* __restrict__ hid, __nv_bfloat16* __restrict__ hidb, int t)
{
    int idx = blockIdx.x * 256 + threadIdx.x;  // < BB*HH
    int b = idx >> 9, j = idx & 511;
    const float* gx = gix + ((size_t)t*BB + b)*1536;
    const float* gc = gic + b*1536;
    const float* gh = hgh + b*2048 + 512;
    float rr = gx[j]        + gc[j]        + gh[j];
    float zz = gx[512 + j]  + gc[512 + j]  + gh[512 + j];
    float nn = gx[1024 + j] + gc[1024 + j];
    float r = 1.f / (1.f + expf(-rr));
    float z = 1.f / (1.f + expf(-zz));
    float n = tanhf(nn + r * gh[1024 + j]);
    float h = (1.f - z) * n + z * hid[idx];
    hid[idx]  = h;
    hidb[idx] = __float2bfloat16(h);
}

// ---------------- launch ----------------
extern "C" void kernel_launch(void* const* d_in, const int* in_sizes, int n_in,
                              void* d_out, int out_size)
{
    const float* enc     = (const float*)d_in[0];
    const float* enc_hid = (const float*)d_in[1];
    const int*   traw    = (const int*)  d_in[2];
    const float* embed_W = (const float*)d_in[3];
    const float* att_W1  = (const float*)d_in[4];
    const float* att_b1  = (const float*)d_in[5];
    const float* att_W2  = (const float*)d_in[6];
    const float* att_b2  = (const float*)d_in[7];
    const float* att_W3  = (const float*)d_in[8];
    const float* att_b3  = (const float*)d_in[9];
    const float* att_v   = (const float*)d_in[10];
    const float* gru_Wih = (const float*)d_in[11];
    const float* gru_Whh = (const float*)d_in[12];
    const float* gru_bih = (const float*)d_in[13];
    const float* gru_bhh = (const float*)d_in[14];
    const float* out_W   = (const float*)d_in[15];
    const float* out_b   = (const float*)d_in[16];
    float* out = (float*)d_out;

    float *encpart, *hid, *hgh, *gix, *gic, *logits, *bpack;
    __nv_bfloat16 *encpb, *encb, *a1b, *a2b, *a3b, *W2b, *W3b, *outWb, *hidb;
    __nv_bfloat16 *Wpackb, *Wihx, *Wihc, *ebx, *ctxb;
    int *tgt;
    cudaGetSymbolAddress((void**)&encpart, g_encpart);
    cudaGetSymbolAddress((void**)&encpb,   g_encpb);
    cudaGetSymbolAddress((void**)&encb,    g_encb);
    cudaGetSymbolAddress((void**)&a1b,     g_a1b);
    cudaGetSymbolAddress((void**)&a2b,     g_a2b);
    cudaGetSymbolAddress((void**)&a3b,     g_a3b);
    cudaGetSymbolAddress((void**)&W2b,     g_W2b);
    cudaGetSymbolAddress((void**)&W3b,     g_W3b);
    cudaGetSymbolAddress((void**)&outWb,   g_outWb);
    cudaGetSymbolAddress((void**)&Wpackb,  g_Wpackb);
    cudaGetSymbolAddress((void**)&bpack,   g_bpack);
    cudaGetSymbolAddress((void**)&Wihx,    g_Wihx);
    cudaGetSymbolAddress((void**)&Wihc,    g_Wihc);
    cudaGetSymbolAddress((void**)&ebx,     g_ebx);
    cudaGetSymbolAddress((void**)&gix,     g_gix);
    cudaGetSymbolAddress((void**)&gic,     g_gic);
    cudaGetSymbolAddress((void**)&hidb,    g_hidb);
    cudaGetSymbolAddress((void**)&hid,     g_hid);
    cudaGetSymbolAddress((void**)&hgh,     g_hgh);
    cudaGetSymbolAddress((void**)&ctxb,    g_ctxb);
    cudaGetSymbolAddress((void**)&logits,  g_logits);
    cudaGetSymbolAddress((void**)&tgt,     g_tgt);

    // ---- setup (once per call, outside the recurrent loop) ----
    convert_targets_k<<<1, 256>>>(traw, tgt, BB*TT);
    copyf_k<<<(BB*HH + 255)/256, 256>>>(hid, enc_hid, BB*HH);
    cvtf2b_k<<<(BB*HH)/256, 256>>>(enc_hid, hidb, BB*HH);
    pack_whhb_k<<<(2048*HH)/256, 256>>>(att_W1, gru_Whh, gru_bhh, Wpackb, bpack);
    pack_wih_k<<<(3*HH*HH)/256, 256>>>(gru_Wih, Wihx, Wihc);
    cvtf2b_k<<<(HH*HH)/256, 256>>>(att_W2, W2b, HH*HH);
    cvtf2b_k<<<(HH*HH)/256, 256>>>(att_W3, W3b, HH*HH);
    cvtf2b_k<<<(VOCAB*HH)/256, 256>>>(out_W, outWb, VOCAB*HH);
    cvtf2b_k<<<(BL*HH)/256, 256>>>(enc, encb, BL*HH);

    // embed all steps + gi embed-part for all steps (one big GEMM)
    gather_embed_k<<<NSTEP*BB, 128>>>(embed_W, tgt, ebx);
    gemm_bf16_k<<<dim3(1536/128, NSTEP*BB/128), 256>>>(ebx, Wihx, gru_bih, gix,
                                                       1536, HH, HH, HH, 0, 0);

    // step-invariant encpart (tf32 for precision), then bf16
    gemm_tf32_k<<<dim3(HH/128, BL/128), 256>>>(enc, att_W1, att_b1, encpart,
                                               BL, HH, HH, HH, 2*HH, 0);
    cvtf2b_k<<<(BL*HH)/256, 256>>>(encpart, encpb, BL*HH);

    // hgh for t=0
    gemm_bf16_k<<<dim3(2048/128, 1), 256>>>(hidb, Wpackb, bpack, hgh,
                                            2048, HH, HH, HH, 0, 0);

    // ---- recurrent loop ----
    for (int t = 0; t < NSTEP; t++) {
        // logsoftmax(t-1) + bcast_tanh(t) in one launch
        hetero_k<<<BB + 2048, 256>>>(logits, out, t - 1, encpb, hgh, a1b);
        // attention layers 2,3 (bf16, fused tanh)
        gemm_bf16_k<<<dim3(HH/128, BL/128), 256>>>(a1b, W2b, att_b2, a2b,
                                                   HH, HH, HH, HH, 1, 1);
        gemm_bf16_k<<<dim3(HH/128, BL/128), 256>>>(a2b, W3b, att_b3, a3b,
                                                   HH, HH, HH, HH, 1, 1);
        attention_ctx_k<<<BB, 256>>>(a3b, att_v, encb, ctxb);
        // gi ctx-part (embed part precomputed)
        gemm_bf16_k<<<dim3(1536/128, 1), 256>>>(ctxb, Wihc, nullptr, gic,
                                                1536, HH, HH, HH, 0, 0);
        gru_gates_k<<<(BB*HH)/256, 256>>>(gix, gic, hgh, hid, hidb, t);
        // grouped: vocab logits(t) + hgh(t+1), both from new hidden
        gemm_dual_k<<<NVB + 16, 256>>>(hidb, outWb, out_b, logits, Wpackb, bpack, hgh);
    }
    // final logsoftmax for t = NSTEP-1 (lsm blocks only)
    hetero_k<<<BB, 256>>>(logits, out, NSTEP - 1, encpb, hgh, a1b);

    (void)in_sizes; (void)n_in; (void)out_size;
}

// round 6
// speedup vs baseline: 5.5180x; 1.0103x over previous
#include <cuda_runtime.h>
#include <cuda_bf16.h>
#include <math.h>
#include <stdint.h>

#define BB 128
#define LL 64
#define HH 512
#define VOCAB 32000
#define TT 32
#define NSTEP 31
#define BL (BB*LL)       // 8192
#define NVB (VOCAB/128)  // 250

// ---------------- scratch (device globals; no allocation) ----------------
__device__ float g_encpart[BL*HH];
__device__ __nv_bfloat16 g_encpb[BL*HH];
__device__ __nv_bfloat16 g_encb[BL*HH];
__device__ __nv_bfloat16 g_a1b[BL*HH];
__device__ __nv_bfloat16 g_a2b[BL*HH];
__device__ __nv_bfloat16 g_a3b[BL*HH];
__device__ __nv_bfloat16 g_W2b[HH*HH];
__device__ __nv_bfloat16 g_W3b[HH*HH];
__device__ __nv_bfloat16 g_outWb[(size_t)VOCAB*HH];
__device__ __nv_bfloat16 g_Wpackb[2048*HH];
__device__ float g_bpack[2048];
__device__ __nv_bfloat16 g_Wihx[3*HH*HH];
__device__ __nv_bfloat16 g_Wihc[3*HH*HH];
__device__ __nv_bfloat16 g_ebx[NSTEP*BB*HH];
__device__ float g_gix[(size_t)NSTEP*BB*3*HH];
__device__ __nv_bfloat16 g_encWc[(size_t)BL*3*HH];   // enc @ Wihc^T, bf16
__device__ __nv_bfloat16 g_hidb[BB*HH];
__device__ float g_hid[BB*HH];
__device__ float g_hgh[BB*2048];                     // [hidatt(512) | gh(1536)]
__device__ float g_logits[BB*VOCAB];
__device__ int   g_tgt[BB*TT];

// ---------------- setup helpers ----------------
__global__ void convert_targets_k(const int* __restrict__ raw, int* __restrict__ tgt, int n)
{
    __shared__ int nonzero;
    if (threadIdx.x == 0) nonzero = 0;
    __syncthreads();
    int bad = 0;
    for (int i = 2*threadIdx.x + 1; i < n; i += 2*blockDim.x) bad |= raw[i];
    if (bad) atomicOr(&nonzero, 1);
    __syncthreads();
    int is64 = (nonzero == 0);
    for (int i = threadIdx.x; i < n; i += blockDim.x)
        tgt[i] = is64 ? raw[2*i] : raw[i];
}

__global__ void copyf_k(float* __restrict__ dst, const float* __restrict__ src, int n)
{
    int i = blockIdx.x*blockDim.x + threadIdx.x;
    if (i < n) dst[i] = src[i];
}

__global__ void cvtf2b_k(const float* __restrict__ src, __nv_bfloat16* __restrict__ dst, int n)
{
    int i = blockIdx.x*256 + threadIdx.x;
    if (i < n) dst[i] = __float2bfloat16(src[i]);
}

__global__ void pack_whhb_k(const float* __restrict__ W1, const float* __restrict__ Whh,
                            const float* __restrict__ bhh,
                            __nv_bfloat16* __restrict__ Wp, float* __restrict__ bp)
{
    int idx = blockIdx.x * 256 + threadIdx.x;   // < 2048*512
    int nn = idx >> 9, k = idx & 511;
    float v = (nn < 512) ? W1[nn*1024 + 512 + k] : Whh[(nn-512)*512 + k];
    Wp[idx] = __float2bfloat16(v);
    if (idx < 2048) bp[idx] = (idx < 512) ? 0.f : bhh[idx - 512];
}

__global__ void pack_wih_k(const float* __restrict__ Wih,
                           __nv_bfloat16* __restrict__ Wx, __nv_bfloat16* __restrict__ Wc)
{
    int idx = blockIdx.x * 256 + threadIdx.x;   // < 1536*512
    int n = idx >> 9, k = idx & 511;
    Wx[idx] = __float2bfloat16(Wih[n*1024 + k]);
    Wc[idx] = __float2bfloat16(Wih[n*1024 + 512 + k]);
}

__global__ void gather_embed_k(const float* __restrict__ embed_W, const int* __restrict__ tgt,
                               __nv_bfloat16* __restrict__ ebx)
{
    int r = blockIdx.x;          // t*BB + b
    int t = r >> 7, b = r & 127;
    int row = tgt[b*TT + t];
    const float4* src = (const float4*)(embed_W + (size_t)row*HH);
    __nv_bfloat16* dst = ebx + (size_t)r*HH;
    for (int c = threadIdx.x; c < HH/4; c += 128) {
        float4 v = src[c];
        __nv_bfloat162 p0; p0.x = __float2bfloat16(v.x); p0.y = __float2bfloat16(v.y);
        __nv_bfloat162 p1; p1.x = __float2bfloat16(v.z); p1.y = __float2bfloat16(v.w);
        *(__nv_bfloat162*)(dst + c*4)     = p0;
        *(__nv_bfloat162*)(dst + c*4 + 2) = p1;
    }
}

// ---------------- TF32 GEMM (one-time encpart only) ----------------
#define PITCH 20
__device__ __forceinline__ uint32_t f2tf(float x) {
    uint32_t u; asm("cvt.rna.tf32.f32 %0, %1;" : "=r"(u) : "f"(x)); return u;
}

__global__ __launch_bounds__(256)
void gemm_tf32_k(const float* __restrict__ A, const float* __restrict__ W,
                 const float* __restrict__ bias, float* __restrict__ C,
                 int M, int N, int K, int ldA, int ldW, int act)
{
    __shared__ float As[128*PITCH];
    __shared__ float Ws[128*PITCH];
    const int tid  = threadIdx.x;
    const int lane = tid & 31;
    const int wid  = tid >> 5;
    const int warpM = wid >> 2;
    const int warpN = wid & 3;
    const int gid = lane >> 2;
    const int tig = lane & 3;
    const int bm = blockIdx.y * 128;
    const int bn = blockIdx.x * 128;

    const int r0 = tid >> 2;
    const int q0 = (tid & 3) * 4;
    const float* Ag0 = A + (size_t)(bm + r0)      * ldA + q0;
    const float* Ag1 = A + (size_t)(bm + r0 + 64) * ldA + q0;
    const float* Wg0 = W + (size_t)(bn + r0)      * ldW + q0;
    const float* Wg1 = W + (size_t)(bn + r0 + 64) * ldW + q0;
    const int s0 = r0 * PITCH + q0;
    const int s1 = s0 + 64 * PITCH;

    float acc[4][4][4];
#pragma unroll
    for (int mt = 0; mt < 4; mt++)
#pragma unroll
        for (int nt = 0; nt < 4; nt++)
#pragma unroll
            for (int r = 0; r < 4; r++) acc[mt][nt][r] = 0.f;

    const int KT = K >> 4;
    float4 av0, av1, wv0, wv1;
    av0 = *(const float4*)(Ag0); av1 = *(const float4*)(Ag1);
    wv0 = *(const float4*)(Wg0); wv1 = *(const float4*)(Wg1);
    {
        uint4 t;
        t.x=f2tf(av0.x); t.y=f2tf(av0.y); t.z=f2tf(av0.z); t.w=f2tf(av0.w);
        *(uint4*)(As + s0) = t;
        t.x=f2tf(av1.x); t.y=f2tf(av1.y); t.z=f2tf(av1.z); t.w=f2tf(av1.w);
        *(uint4*)(As + s1) = t;
        t.x=f2tf(wv0.x); t.y=f2tf(wv0.y); t.z=f2tf(wv0.z); t.w=f2tf(wv0.w);
        *(uint4*)(Ws + s0) = t;
        t.x=f2tf(wv1.x); t.y=f2tf(wv1.y); t.z=f2tf(wv1.z); t.w=f2tf(wv1.w);
        *(uint4*)(Ws + s1) = t;
    }

    for (int kt = 0; kt < KT; kt++) {
        __syncthreads();
        if (kt + 1 < KT) {
            int k0 = (kt + 1) << 4;
            av0 = *(const float4*)(Ag0 + k0); av1 = *(const float4*)(Ag1 + k0);
            wv0 = *(const float4*)(Wg0 + k0); wv1 = *(const float4*)(Wg1 + k0);
        }
#pragma unroll
        for (int ks = 0; ks < 16; ks += 8) {
            uint32_t af[4][4], bf[4][2];
#pragma unroll
            for (int mt = 0; mt < 4; mt++) {
                const float* p = &As[(warpM*64 + mt*16 + gid) * PITCH + ks + tig];
                af[mt][0] = __float_as_uint(p[0]);
                af[mt][1] = __float_as_uint(p[8*PITCH]);
                af[mt][2] = __float_as_uint(p[4]);
                af[mt][3] = __float_as_uint(p[8*PITCH + 4]);
            }
#pragma unroll
            for (int nt = 0; nt < 4; nt++) {
                const float* p = &Ws[(warpN*32 + nt*8 + gid) * PITCH + ks + tig];
                bf[nt][0] = __float_as_uint(p[0]);
                bf[nt][1] = __float_as_uint(p[4]);
            }
#pragma unroll
            for (int mt = 0; mt < 4; mt++)
#pragma unroll
                for (int nt = 0; nt < 4; nt++) {
                    float* d = acc[mt][nt];
                    asm volatile(
                        "mma.sync.aligned.m16n8k8.row.col.f32.tf32.tf32.f32 "
                        "{%0,%1,%2,%3},{%4,%5,%6,%7},{%8,%9},{%0,%1,%2,%3};"
                        : "+f"(d[0]), "+f"(d[1]), "+f"(d[2]), "+f"(d[3])
                        : "r"(af[mt][0]), "r"(af[mt][1]), "r"(af[mt][2]), "r"(af[mt][3]),
                          "r"(bf[nt][0]), "r"(bf[nt][1]));
                }
        }
        __syncthreads();
        if (kt + 1 < KT) {
            uint4 t;
            t.x=f2tf(av0.x); t.y=f2tf(av0.y); t.z=f2tf(av0.z); t.w=f2tf(av0.w);
            *(uint4*)(As + s0) = t;
            t.x=f2tf(av1.x); t.y=f2tf(av1.y); t.z=f2tf(av1.z); t.w=f2tf(av1.w);
            *(uint4*)(As + s1) = t;
            t.x=f2tf(wv0.x); t.y=f2tf(wv0.y); t.z=f2tf(wv0.z); t.w=f2tf(wv0.w);
            *(uint4*)(Ws + s0) = t;
            t.x=f2tf(wv1.x); t.y=f2tf(wv1.y); t.z=f2tf(wv1.z); t.w=f2tf(wv1.w);
            *(uint4*)(Ws + s1) = t;
        }
    }

#pragma unroll
    for (int mt = 0; mt < 4; mt++) {
        int row = bm + warpM*64 + mt*16 + gid;
#pragma unroll
        for (int nt = 0; nt < 4; nt++) {
            int col = bn + warpN*32 + nt*8 + tig*2;
            float b0 = bias ? bias[col]     : 0.f;
            float b1 = bias ? bias[col + 1] : 0.f;
            float v0 = acc[mt][nt][0] + b0;
            float v1 = acc[mt][nt][1] + b1;
            float v2 = acc[mt][nt][2] + b0;
            float v3 = acc[mt][nt][3] + b1;
            if (act) { v0 = tanhf(v0); v1 = tanhf(v1); v2 = tanhf(v2); v3 = tanhf(v3); }
            *(float2*)&C[(size_t)row       * N + col] = make_float2(v0, v1);
            *(float2*)&C[(size_t)(row + 8) * N + col] = make_float2(v2, v3);
        }
    }
}

// ---------------- BF16 GEMM core (cp.async 2-stage + ldmatrix) ----------------
#define PB 40
#define STAGE_ELEMS (128*PB)

__device__ __forceinline__ void cp16(uint32_t dst, const void* src) {
    asm volatile("cp.async.cg.shared.global [%0], [%1], 16;" :: "r"(dst), "l"(src));
}
__device__ __forceinline__ void ldsm4(uint32_t* r, uint32_t addr) {
    asm volatile("ldmatrix.sync.aligned.m8n8.x4.shared.b16 {%0,%1,%2,%3}, [%4];"
        : "=r"(r[0]), "=r"(r[1]), "=r"(r[2]), "=r"(r[3]) : "r"(addr));
}

__device__ __forceinline__ void gemm_bf16_body(
    const __nv_bfloat16* __restrict__ A, const __nv_bfloat16* __restrict__ W,
    const float* __restrict__ bias, void* __restrict__ Cout,
    int N, int K, int ldA, int ldW, int act, int out_bf16, int bm, int bn)
{
    __shared__ __nv_bfloat16 As[2*STAGE_ELEMS];
    __shared__ __nv_bfloat16 Ws[2*STAGE_ELEMS];
    const int tid  = threadIdx.x;
    const int lane = tid & 31;
    const int wid  = tid >> 5;
    const int warpM = wid >> 2;
    const int warpN = wid & 3;
    const int gid = lane >> 2;
    const int tig = lane & 3;

    const int row_ld = tid >> 1;
    const int col_ld = (tid & 1) * 16;
    const __nv_bfloat16* Ag = A + (size_t)(bm + row_ld) * ldA + col_ld;
    const __nv_bfloat16* Wg = W + (size_t)(bn + row_ld) * ldW + col_ld;
    const uint32_t sA0 = (uint32_t)__cvta_generic_to_shared(As);
    const uint32_t sW0 = (uint32_t)__cvta_generic_to_shared(Ws);
    const uint32_t sAst = sA0 + (row_ld*PB + col_ld)*2;
    const uint32_t sWst = sW0 + (row_ld*PB + col_ld)*2;
    const uint32_t stageB = STAGE_ELEMS*2;

    // ldmatrix lane addressing (stage 0 base)
    const int a_row = lane & 15;
    const int a_k   = (lane >> 4) << 3;
    const int b_row = (lane & 7) | ((lane & 16) >> 1);
    const int b_k   = lane & 8;
    uint32_t aaddr[4], baddr[2];
#pragma unroll
    for (int mt = 0; mt < 4; mt++)
        aaddr[mt] = sA0 + ((warpM*64 + mt*16 + a_row)*PB + a_k)*2;
#pragma unroll
    for (int p = 0; p < 2; p++)
        baddr[p] = sW0 + ((warpN*32 + p*16 + b_row)*PB + b_k)*2;

    float acc[4][4][4];
#pragma unroll
    for (int mt = 0; mt < 4; mt++)
#pragma unroll
        for (int nt = 0; nt < 4; nt++)
#pragma unroll
            for (int r = 0; r < 4; r++) acc[mt][nt][r] = 0.f;

    const int KT = K >> 5;

    cp16(sAst,      Ag);
    cp16(sAst + 16, Ag + 8);
    cp16(sWst,      Wg);
    cp16(sWst + 16, Wg + 8);
    asm volatile("cp.async.commit_group;" ::: "memory");

    for (int kt = 0; kt < KT; kt++) {
        const uint32_t boff = (kt & 1) * stageB;
        if (kt + 1 < KT) {
            const uint32_t nb = ((kt + 1) & 1) * stageB;
            const __nv_bfloat16* ag = Ag + (kt + 1) * 32;
            const __nv_bfloat16* wg = Wg + (kt + 1) * 32;
            cp16(sAst + nb,      ag);
            cp16(sAst + nb + 16, ag + 8);
            cp16(sWst + nb,      wg);
            cp16(sWst + nb + 16, wg + 8);
            asm volatile("cp.async.commit_group;" ::: "memory");
            asm volatile("cp.async.wait_group 1;" ::: "memory");
        } else {
            asm volatile("cp.async.wait_group 0;" ::: "memory");
        }
        __syncthreads();

#pragma unroll
        for (int kk = 0; kk < 2; kk++) {
            uint32_t af[4][4], bfr[2][4];
#pragma unroll
            for (int mt = 0; mt < 4; mt++)
                ldsm4(af[mt], aaddr[mt] + boff + kk*32);
#pragma unroll
            for (int p = 0; p < 2; p++)
                ldsm4(bfr[p], baddr[p] + boff + kk*32);
#pragma unroll
            for (int mt = 0; mt < 4; mt++)
#pragma unroll
                for (int nt = 0; nt < 4; nt++) {
                    float* d = acc[mt][nt];
                    asm volatile(
                        "mma.sync.aligned.m16n8k16.row.col.f32.bf16.bf16.f32 "
                        "{%0,%1,%2,%3},{%4,%5,%6,%7},{%8,%9},{%0,%1,%2,%3};"
                        : "+f"(d[0]), "+f"(d[1]), "+f"(d[2]), "+f"(d[3])
                        : "r"(af[mt][0]), "r"(af[mt][1]), "r"(af[mt][2]), "r"(af[mt][3]),
                          "r"(bfr[nt>>1][(nt&1)*2]), "r"(bfr[nt>>1][(nt&1)*2+1]));
                }
        }
        __syncthreads();
    }

#pragma unroll
    for (int mt = 0; mt < 4; mt++) {
        int row = bm + warpM*64 + mt*16 + gid;
#pragma unroll
        for (int nt = 0; nt < 4; nt++) {
            int col = bn + warpN*32 + nt*8 + tig*2;
            float b0 = bias ? bias[col]     : 0.f;
            float b1 = bias ? bias[col + 1] : 0.f;
            float v0 = acc[mt][nt][0] + b0;
            float v1 = acc[mt][nt][1] + b1;
            float v2 = acc[mt][nt][2] + b0;
            float v3 = acc[mt][nt][3] + b1;
            if (act) { v0 = tanhf(v0); v1 = tanhf(v1); v2 = tanhf(v2); v3 = tanhf(v3); }
            if (out_bf16) {
                __nv_bfloat16* Cb = (__nv_bfloat16*)Cout;
                __nv_bfloat162 lo; lo.x = __float2bfloat16(v0); lo.y = __float2bfloat16(v1);
                __nv_bfloat162 hi; hi.x = __float2bfloat16(v2); hi.y = __float2bfloat16(v3);
                *(__nv_bfloat162*)&Cb[(size_t)row       * N + col] = lo;
                *(__nv_bfloat162*)&Cb[(size_t)(row + 8) * N + col] = hi;
            } else {
                float* Cf = (float*)Cout;
                *(float2*)&Cf[(size_t)row       * N + col] = make_float2(v0, v1);
                *(float2*)&Cf[(size_t)(row + 8) * N + col] = make_float2(v2, v3);
            }
        }
    }
}

__global__ __launch_bounds__(256)
void gemm_bf16_k(const __nv_bfloat16* __restrict__ A, const __nv_bfloat16* __restrict__ W,
                 const float* __restrict__ bias, void* __restrict__ Cout,
                 int N, int K, int ldA, int ldW, int act, int out_bf16)
{
    gemm_bf16_body(A, W, bias, Cout, N, K, ldA, ldW, act, out_bf16,
                   blockIdx.y*128, blockIdx.x*128);
}

// ---------------- mega1: vocab(t-1) GEMM + bcast_tanh(t) ----------------
__global__ __launch_bounds__(256)
void bcast_vocab_k(const __nv_bfloat16* __restrict__ encpb, const float* __restrict__ hgh,
                   __nv_bfloat16* __restrict__ a1b,
                   const __nv_bfloat16* __restrict__ hidb,
                   const __nv_bfloat16* __restrict__ outWb, const float* __restrict__ out_b,
                   float* __restrict__ logits, int do_vocab)
{
    if (blockIdx.x < NVB) {
        if (!do_vocab) return;
        gemm_bf16_body(hidb, outWb, out_b, logits, VOCAB, HH, HH, HH, 0, 0,
                       0, blockIdx.x*128);
    } else {
        int idx = (blockIdx.x - NVB)*256 + threadIdx.x;
        int base = idx * 8;                 // < BL*HH
        int b  = base >> 15;
        int j0 = base & 511;
        uint4 ev = *(const uint4*)(encpb + base);
        float4 h0 = *(const float4*)(hgh + b*2048 + j0);
        float4 h1 = *(const float4*)(hgh + b*2048 + j0 + 4);
        const __nv_bfloat162* e2 = (const __nv_bfloat162*)&ev;
        float hf[8] = {h0.x,h0.y,h0.z,h0.w,h1.x,h1.y,h1.z,h1.w};
        uint4 ov;
        __nv_bfloat162* o2 = (__nv_bfloat162*)&ov;
#pragma unroll
        for (int q = 0; q < 4; q++) {
            float2 ef = __bfloat1622float2(e2[q]);
            __nv_bfloat162 r;
            r.x = __float2bfloat16(tanhf(ef.x + hf[q*2]));
            r.y = __float2bfloat16(tanhf(ef.y + hf[q*2+1]));
            o2[q] = r;
        }
        *(uint4*)(a1b + base) = ov;
    }
}

// ---------------- mega2: L2 GEMM + logsoftmax(t-1) ----------------
__global__ __launch_bounds__(256)
void gemm_lsm_k(const __nv_bfloat16* __restrict__ a1b, const __nv_bfloat16* __restrict__ W2b,
                const float* __restrict__ b2, __nv_bfloat16* __restrict__ a2b,
                const float* __restrict__ logits, float* __restrict__ out,
                int t_lsm, int ngemm)
{
    const int tid = threadIdx.x;
    if ((int)blockIdx.x < ngemm) {
        gemm_bf16_body(a1b, W2b, b2, a2b, HH, HH, HH, HH, 1, 1,
                       (blockIdx.x >> 2)*128, (blockIdx.x & 3)*128);
    } else {
        if (t_lsm < 0) return;
        int b = blockIdx.x - ngemm;
        const float4* row = (const float4*)(logits + (size_t)b * VOCAB);
        __shared__ float rm[256], rs[256];
        float m = -1e30f, s = 0.f;
        for (int i = tid; i < VOCAB/4; i += 256) {
            float4 v = row[i];
#define ONLN(x) { float d = (x) - m; if (d > 0.f) { s = s*expf(-d) + 1.f; m = (x); } else s += expf(d); }
            ONLN(v.x) ONLN(v.y) ONLN(v.z) ONLN(v.w)
#undef ONLN
        }
        rm[tid] = m; rs[tid] = s; __syncthreads();
        for (int st = 128; st > 0; st >>= 1) {
            if (tid < st) {
                float m2 = rm[tid+st], s2 = rs[tid+st];
                float M = fmaxf(rm[tid], m2);
                rs[tid] = rs[tid]*expf(rm[tid]-M) + s2*expf(m2-M);
                rm[tid] = M;
            }
            __syncthreads();
        }
        float lse = rm[0] + logf(rs[0]);
        float4* orow = (float4*)(out + ((size_t)b * NSTEP + t_lsm) * VOCAB);
        for (int i = tid; i < VOCAB/4; i += 256) {
            float4 v = row[i];
            v.x -= lse; v.y -= lse; v.z -= lse; v.w -= lse;
            orow[i] = v;
        }
    }
}

// ---------------- fused: e-dot -> softmax -> gic (alpha @ encWc) -> GRU ----------------
__global__ __launch_bounds__(256)
void alpha_gic_gru_k(const __nv_bfloat16* __restrict__ a3b, const float* __restrict__ v,
                     const __nv_bfloat16* __restrict__ encWc,
                     const float* __restrict__ gix, const float* __restrict__ hgh,
                     float* __restrict__ hid, __nv_bfloat16* __restrict__ hidb, int t)
{
    const int b = blockIdx.x, tid = threadIdx.x;
    const int warp = tid >> 5, lane = tid & 31;
    __shared__ float e[LL];

    // e[l] = a3[b,l,:] . v
    for (int l = warp; l < LL; l += 8) {
        const __nv_bfloat16* arow = a3b + (size_t)(b*LL + l) * HH;
        float s = 0.f;
        for (int j = lane*2; j < HH; j += 64) {
            float2 a = __bfloat1622float2(*(const __nv_bfloat162*)(arow + j));
            s += a.x * v[j] + a.y * v[j+1];
        }
#pragma unroll
        for (int o = 16; o > 0; o >>= 1) s += __shfl_down_sync(0xffffffffu, s, o);
        if (lane == 0) e[l] = s;
    }
    __syncthreads();
    if (tid == 0) {
        float mx = -1e30f;
        for (int l = 0; l < LL; l++) mx = fmaxf(mx, e[l]);
        float sum = 0.f;
        for (int l = 0; l < LL; l++) { e[l] = expf(e[l] - mx); sum += e[l]; }
        float inv = 1.f / sum;
        for (int l = 0; l < LL; l++) e[l] *= inv;
    }
    __syncthreads();

    // gic pairs: thread handles cols (2tid, 2tid+1) of each gate segment
    float2 ar = make_float2(0.f,0.f), az = make_float2(0.f,0.f), an = make_float2(0.f,0.f);
    const int j0 = tid * 2;
    const __nv_bfloat16* base = encWc + (size_t)b*LL*1536;
#pragma unroll 4
    for (int l = 0; l < LL; l++) {
        float al = e[l];
        const __nv_bfloat16* row = base + (size_t)l*1536;
        float2 r0 = __bfloat1622float2(*(const __nv_bfloat162*)(row + j0));
        float2 r1 = __bfloat1622float2(*(const __nv_bfloat162*)(row + 512 + j0));
        float2 r2 = __bfloat1622float2(*(const __nv_bfloat162*)(row + 1024 + j0));
        ar.x += al*r0.x; ar.y += al*r0.y;
        az.x += al*r1.x; az.y += al*r1.y;
        an.x += al*r2.x; an.y += al*r2.y;
    }

    // GRU update for columns j0, j0+1
    const float* gx = gix + ((size_t)t*BB + b)*1536;
    const float* gh = hgh + b*2048 + 512;
    float gr[2] = {ar.x, ar.y}, gz[2] = {az.x, az.y}, gn[2] = {an.x, an.y};
#pragma unroll
    for (int q = 0; q < 2; q++) {
        int j = j0 + q;
        float rr = gx[j]        + gr[q] + gh[j];
        float zz = gx[512 + j]  + gz[q] + gh[512 + j];
        float nn = gx[1024 + j] + gn[q];
        float r = 1.f / (1.f + expf(-rr));
        float z = 1.f / (1.f + expf(-zz));
        float n = tanhf(nn + r * gh[1024 + j]);
        float h = (1.f - z) * n + z * hid[b*HH + j];
        hid[b*HH + j]  = h;
        hidb[b*HH + j] = __float2bfloat16(h);
    }
}

// ---------------- launch ----------------
extern "C" void kernel_launch(void* const* d_in, const int* in_sizes, int n_in,
                              void* d_out, int out_size)
{
    const float* enc     = (const float*)d_in[0];
    const float* enc_hid = (const float*)d_in[1];
    const int*   traw    = (const int*)  d_in[2];
    const float* embed_W = (const float*)d_in[3];
    const float* att_W1  = (const float*)d_in[4];
    const float* att_b1  = (const float*)d_in[5];
    const float* att_W2  = (const float*)d_in[6];
    const float* att_b2  = (const float*)d_in[7];
    const float* att_W3  = (const float*)d_in[8];
    const float* att_b3  = (const float*)d_in[9];
    const float* att_v   = (const float*)d_in[10];
    const float* gru_Wih = (const float*)d_in[11];
    const float* gru_Whh = (const float*)d_in[12];
    const float* gru_bih = (const float*)d_in[13];
    const float* gru_bhh = (const float*)d_in[14];
    const float* out_W   = (const float*)d_in[15];
    const float* out_b   = (const float*)d_in[16];
    float* out = (float*)d_out;

    float *encpart, *hid, *hgh, *gix, *logits, *bpack;
    __nv_bfloat16 *encpb, *encb, *a1b, *a2b, *a3b, *W2b, *W3b, *outWb, *hidb;
    __nv_bfloat16 *Wpackb, *Wihx, *Wihc, *ebx, *encWc;
    int *tgt;
    cudaGetSymbolAddress((void**)&encpart, g_encpart);
    cudaGetSymbolAddress((void**)&encpb,   g_encpb);
    cudaGetSymbolAddress((void**)&encb,    g_encb);
    cudaGetSymbolAddress((void**)&a1b,     g_a1b);
    cudaGetSymbolAddress((void**)&a2b,     g_a2b);
    cudaGetSymbolAddress((void**)&a3b,     g_a3b);
    cudaGetSymbolAddress((void**)&W2b,     g_W2b);
    cudaGetSymbolAddress((void**)&W3b,     g_W3b);
    cudaGetSymbolAddress((void**)&outWb,   g_outWb);
    cudaGetSymbolAddress((void**)&Wpackb,  g_Wpackb);
    cudaGetSymbolAddress((void**)&bpack,   g_bpack);
    cudaGetSymbolAddress((void**)&Wihx,    g_Wihx);
    cudaGetSymbolAddress((void**)&Wihc,    g_Wihc);
    cudaGetSymbolAddress((void**)&ebx,     g_ebx);
    cudaGetSymbolAddress((void**)&gix,     g_gix);
    cudaGetSymbolAddress((void**)&encWc,   g_encWc);
    cudaGetSymbolAddress((void**)&hidb,    g_hidb);
    cudaGetSymbolAddress((void**)&hid,     g_hid);
    cudaGetSymbolAddress((void**)&hgh,     g_hgh);
    cudaGetSymbolAddress((void**)&logits,  g_logits);
    cudaGetSymbolAddress((void**)&tgt,     g_tgt);

    // ---- setup ----
    convert_targets_k<<<1, 256>>>(traw, tgt, BB*TT);
    copyf_k<<<(BB*HH + 255)/256, 256>>>(hid, enc_hid, BB*HH);
    cvtf2b_k<<<(BB*HH)/256, 256>>>(enc_hid, hidb, BB*HH);
    pack_whhb_k<<<(2048*HH)/256, 256>>>(att_W1, gru_Whh, gru_bhh, Wpackb, bpack);
    pack_wih_k<<<(3*HH*HH)/256, 256>>>(gru_Wih, Wihx, Wihc);
    cvtf2b_k<<<(HH*HH)/256, 256>>>(att_W2, W2b, HH*HH);
    cvtf2b_k<<<(HH*HH)/256, 256>>>(att_W3, W3b, HH*HH);
    cvtf2b_k<<<(VOCAB*HH)/256, 256>>>(out_W, outWb, VOCAB*HH);
    cvtf2b_k<<<(BL*HH)/256, 256>>>(enc, encb, BL*HH);

    gather_embed_k<<<NSTEP*BB, 128>>>(embed_W, tgt, ebx);
    // gi embed-part for all steps
    gemm_bf16_k<<<dim3(1536/128, NSTEP*BB/128), 256>>>(ebx, Wihx, gru_bih, gix,
                                                       1536, HH, HH, HH, 0, 0);
    // encWc = enc @ Wihc^T (bf16 out)
    gemm_bf16_k<<<dim3(1536/128, BL/128), 256>>>(encb, Wihc, nullptr, encWc,
                                                 1536, HH, HH, HH, 0, 1);
    // encpart (tf32 for precision), then bf16
    gemm_tf32_k<<<dim3(HH/128, BL/128), 256>>>(enc, att_W1, att_b1, encpart,
                                               BL, HH, HH, HH, 2*HH, 0);
    cvtf2b_k<<<(BL*HH)/256, 256>>>(encpart, encpb, BL*HH);
    // hgh(0)
    gemm_bf16_k<<<dim3(2048/128, 1), 256>>>(hidb, Wpackb, bpack, hgh,
                                            2048, HH, HH, HH, 0, 0);

    // ---- recurrent loop ----
    for (int t = 0; t < NSTEP; t++) {
        // vocab(t-1) + bcast_tanh(t)
        bcast_vocab_k<<<NVB + 2048, 256>>>(encpb, hgh, a1b, hidb, outWb, out_b,
                                           logits, t > 0);
        // L2 GEMM + logsoftmax(t-1)
        gemm_lsm_k<<<256 + BB, 256>>>(a1b, W2b, att_b2, a2b, logits, out, t - 1, 256);
        // L3
        gemm_bf16_k<<<dim3(HH/128, BL/128), 256>>>(a2b, W3b, att_b3, a3b,
                                                   HH, HH, HH, HH, 1, 1);
        // e -> softmax -> gic -> GRU (per-batch fused)
        alpha_gic_gru_k<<<BB, 256>>>(a3b, att_v, encWc, gix, hgh, hid, hidb, t);
        // hgh(t+1)
        if (t + 1 < NSTEP)
            gemm_bf16_k<<<dim3(2048/128, 1), 256>>>(hidb, Wpackb, bpack, hgh,
                                                    2048, HH, HH, HH, 0, 0);
    }
    // tail: vocab(30) + logsoftmax(30)
    bcast_vocab_k<<<NVB, 256>>>(encpb, hgh, a1b, hidb, outWb, out_b, logits, 1);
    gemm_lsm_k<<<BB, 256>>>(a1b, W2b, att_b2, a2b, logits, out, NSTEP - 1, 0);

    (void)in_sizes; (void)n_in; (void)out_size;
}

// round 7
// speedup vs baseline: 6.2183x; 1.1269x over previous
#include <cuda_runtime.h>
#include <cuda_bf16.h>
#include <math.h>
#include <stdint.h>

#define BB 128
#define LL 64
#define HH 512
#define VOCAB 32000
#define TT 32
#define NSTEP 31
#define BL (BB*LL)       // 8192
#define NVB (VOCAB/128)  // 250

// ---------------- scratch (device globals; no allocation) ----------------
__device__ float g_encpart[BL*HH];
__device__ __nv_bfloat16 g_encpb[BL*HH];
__device__ __nv_bfloat16 g_encb[BL*HH];
__device__ __nv_bfloat16 g_a2b[BL*HH];
__device__ __nv_bfloat16 g_W2b[HH*HH];
__device__ __nv_bfloat16 g_W3b[HH*HH];
__device__ __nv_bfloat16 g_outWb[(size_t)VOCAB*HH];
__device__ __nv_bfloat16 g_Wpackb[2048*HH];
__device__ float g_bpack[2048];
__device__ __nv_bfloat16 g_Wihx[3*HH*HH];
__device__ __nv_bfloat16 g_Wihc[3*HH*HH];
__device__ __nv_bfloat16 g_ebx[NSTEP*BB*HH];
__device__ float g_gix[(size_t)NSTEP*BB*3*HH];
__device__ __nv_bfloat16 g_encWc[(size_t)BL*3*HH];
__device__ float g_epart[4*BL];                  // e partial sums (4 col-blocks)
__device__ __nv_bfloat16 g_hidb[BB*HH];
__device__ float g_hid[BB*HH];
__device__ float g_hgh[BB*2048];                 // [hidatt(512) | gh(1536)]
__device__ float g_logits[BB*VOCAB];
__device__ int   g_tgt[BB*TT];

__device__ __forceinline__ float tanha(float x) {
    float y; asm("tanh.approx.f32 %0, %1;" : "=f"(y) : "f"(x)); return y;
}

// ---------------- setup helpers ----------------
__global__ void convert_targets_k(const int* __restrict__ raw, int* __restrict__ tgt, int n)
{
    __shared__ int nonzero;
    if (threadIdx.x == 0) nonzero = 0;
    __syncthreads();
    int bad = 0;
    for (int i = 2*threadIdx.x + 1; i < n; i += 2*blockDim.x) bad |= raw[i];
    if (bad) atomicOr(&nonzero, 1);
    __syncthreads();
    int is64 = (nonzero == 0);
    for (int i = threadIdx.x; i < n; i += blockDim.x)
        tgt[i] = is64 ? raw[2*i] : raw[i];
}

__global__ void copyf_k(float* __restrict__ dst, const float* __restrict__ src, int n)
{
    int i = blockIdx.x*blockDim.x + threadIdx.x;
    if (i < n) dst[i] = src[i];
}

__global__ void cvtf2b_k(const float* __restrict__ src, __nv_bfloat16* __restrict__ dst, int n)
{
    int i = blockIdx.x*256 + threadIdx.x;
    if (i < n) dst[i] = __float2bfloat16(src[i]);
}

__global__ void pack_whhb_k(const float* __restrict__ W1, const float* __restrict__ Whh,
                            const float* __restrict__ bhh,
                            __nv_bfloat16* __restrict__ Wp, float* __restrict__ bp)
{
    int idx = blockIdx.x * 256 + threadIdx.x;   // < 2048*512
    int nn = idx >> 9, k = idx & 511;
    float v = (nn < 512) ? W1[nn*1024 + 512 + k] : Whh[(nn-512)*512 + k];
    Wp[idx] = __float2bfloat16(v);
    if (idx < 2048) bp[idx] = (idx < 512) ? 0.f : bhh[idx - 512];
}

__global__ void pack_wih_k(const float* __restrict__ Wih,
                           __nv_bfloat16* __restrict__ Wx, __nv_bfloat16* __restrict__ Wc)
{
    int idx = blockIdx.x * 256 + threadIdx.x;   // < 1536*512
    int n = idx >> 9, k = idx & 511;
    Wx[idx] = __float2bfloat16(Wih[n*1024 + k]);
    Wc[idx] = __float2bfloat16(Wih[n*1024 + 512 + k]);
}

__global__ void gather_embed_k(const float* __restrict__ embed_W, const int* __restrict__ tgt,
                               __nv_bfloat16* __restrict__ ebx)
{
    int r = blockIdx.x;          // t*BB + b
    int t = r >> 7, b = r & 127;
    int row = tgt[b*TT + t];
    const float4* src = (const float4*)(embed_W + (size_t)row*HH);
    __nv_bfloat16* dst = ebx + (size_t)r*HH;
    for (int c = threadIdx.x; c < HH/4; c += 128) {
        float4 v = src[c];
        __nv_bfloat162 p0; p0.x = __float2bfloat16(v.x); p0.y = __float2bfloat16(v.y);
        __nv_bfloat162 p1; p1.x = __float2bfloat16(v.z); p1.y = __float2bfloat16(v.w);
        *(__nv_bfloat162*)(dst + c*4)     = p0;
        *(__nv_bfloat162*)(dst + c*4 + 2) = p1;
    }
}

// ---------------- TF32 GEMM (one-time encpart only) ----------------
#define PITCH 20
__device__ __forceinline__ uint32_t f2tf(float x) {
    uint32_t u; asm("cvt.rna.tf32.f32 %0, %1;" : "=r"(u) : "f"(x)); return u;
}

__global__ __launch_bounds__(256)
void gemm_tf32_k(const float* __restrict__ A, const float* __restrict__ W,
                 const float* __restrict__ bias, float* __restrict__ C,
                 int M, int N, int K, int ldA, int ldW, int act)
{
    __shared__ float As[128*PITCH];
    __shared__ float Ws[128*PITCH];
    const int tid  = threadIdx.x;
    const int lane = tid & 31;
    const int wid  = tid >> 5;
    const int warpM = wid >> 2;
    const int warpN = wid & 3;
    const int gid = lane >> 2;
    const int tig = lane & 3;
    const int bm = blockIdx.y * 128;
    const int bn = blockIdx.x * 128;

    const int r0 = tid >> 2;
    const int q0 = (tid & 3) * 4;
    const float* Ag0 = A + (size_t)(bm + r0)      * ldA + q0;
    const float* Ag1 = A + (size_t)(bm + r0 + 64) * ldA + q0;
    const float* Wg0 = W + (size_t)(bn + r0)      * ldW + q0;
    const float* Wg1 = W + (size_t)(bn + r0 + 64) * ldW + q0;
    const int s0 = r0 * PITCH + q0;
    const int s1 = s0 + 64 * PITCH;

    float acc[4][4][4];
#pragma unroll
    for (int mt = 0; mt < 4; mt++)
#pragma unroll
        for (int nt = 0; nt < 4; nt++)
#pragma unroll
            for (int r = 0; r < 4; r++) acc[mt][nt][r] = 0.f;

    const int KT = K >> 4;
    float4 av0, av1, wv0, wv1;
    av0 = *(const float4*)(Ag0); av1 = *(const float4*)(Ag1);
    wv0 = *(const float4*)(Wg0); wv1 = *(const float4*)(Wg1);
    {
        uint4 t;
        t.x=f2tf(av0.x); t.y=f2tf(av0.y); t.z=f2tf(av0.z); t.w=f2tf(av0.w);
        *(uint4*)(As + s0) = t;
        t.x=f2tf(av1.x); t.y=f2tf(av1.y); t.z=f2tf(av1.z); t.w=f2tf(av1.w);
        *(uint4*)(As + s1) = t;
        t.x=f2tf(wv0.x); t.y=f2tf(wv0.y); t.z=f2tf(wv0.z); t.w=f2tf(wv0.w);
        *(uint4*)(Ws + s0) = t;
        t.x=f2tf(wv1.x); t.y=f2tf(wv1.y); t.z=f2tf(wv1.z); t.w=f2tf(wv1.w);
        *(uint4*)(Ws + s1) = t;
    }

    for (int kt = 0; kt < KT; kt++) {
        __syncthreads();
        if (kt + 1 < KT) {
            int k0 = (kt + 1) << 4;
            av0 = *(const float4*)(Ag0 + k0); av1 = *(const float4*)(Ag1 + k0);
            wv0 = *(const float4*)(Wg0 + k0); wv1 = *(const float4*)(Wg1 + k0);
        }
#pragma unroll
        for (int ks = 0; ks < 16; ks += 8) {
            uint32_t af[4][4], bf[4][2];
#pragma unroll
            for (int mt = 0; mt < 4; mt++) {
                const float* p = &As[(warpM*64 + mt*16 + gid) * PITCH + ks + tig];
                af[mt][0] = __float_as_uint(p[0]);
                af[mt][1] = __float_as_uint(p[8*PITCH]);
                af[mt][2] = __float_as_uint(p[4]);
                af[mt][3] = __float_as_uint(p[8*PITCH + 4]);
            }
#pragma unroll
            for (int nt = 0; nt < 4; nt++) {
                const float* p = &Ws[(warpN*32 + nt*8 + gid) * PITCH + ks + tig];
                bf[nt][0] = __float_as_uint(p[0]);
                bf[nt][1] = __float_as_uint(p[4]);
            }
#pragma unroll
            for (int mt = 0; mt < 4; mt++)
#pragma unroll
                for (int nt = 0; nt < 4; nt++) {
                    float* d = acc[mt][nt];
                    asm volatile(
                        "mma.sync.aligned.m16n8k8.row.col.f32.tf32.tf32.f32 "
                        "{%0,%1,%2,%3},{%4,%5,%6,%7},{%8,%9},{%0,%1,%2,%3};"
                        : "+f"(d[0]), "+f"(d[1]), "+f"(d[2]), "+f"(d[3])
                        : "r"(af[mt][0]), "r"(af[mt][1]), "r"(af[mt][2]), "r"(af[mt][3]),
                          "r"(bf[nt][0]), "r"(bf[nt][1]));
                }
        }
        __syncthreads();
        if (kt + 1 < KT) {
            uint4 t;
            t.x=f2tf(av0.x); t.y=f2tf(av0.y); t.z=f2tf(av0.z); t.w=f2tf(av0.w);
            *(uint4*)(As + s0) = t;
            t.x=f2tf(av1.x); t.y=f2tf(av1.y); t.z=f2tf(av1.z); t.w=f2tf(av1.w);
            *(uint4*)(As + s1) = t;
            t.x=f2tf(wv0.x); t.y=f2tf(wv0.y); t.z=f2tf(wv0.z); t.w=f2tf(wv0.w);
            *(uint4*)(Ws + s0) = t;
            t.x=f2tf(wv1.x); t.y=f2tf(wv1.y); t.z=f2tf(wv1.z); t.w=f2tf(wv1.w);
            *(uint4*)(Ws + s1) = t;
        }
    }

#pragma unroll
    for (int mt = 0; mt < 4; mt++) {
        int row = bm + warpM*64 + mt*16 + gid;
#pragma unroll
        for (int nt = 0; nt < 4; nt++) {
            int col = bn + warpN*32 + nt*8 + tig*2;
            float b0 = bias ? bias[col]     : 0.f;
            float b1 = bias ? bias[col + 1] : 0.f;
            float v0 = acc[mt][nt][0] + b0;
            float v1 = acc[mt][nt][1] + b1;
            float v2 = acc[mt][nt][2] + b0;
            float v3 = acc[mt][nt][3] + b1;
            if (act) { v0 = tanhf(v0); v1 = tanhf(v1); v2 = tanhf(v2); v3 = tanhf(v3); }
            *(float2*)&C[(size_t)row       * N + col] = make_float2(v0, v1);
            *(float2*)&C[(size_t)(row + 8) * N + col] = make_float2(v2, v3);
        }
    }
}

// ---------------- BF16 GEMM core (cp.async 2-stage + ldmatrix) ----------------
#define PB 40
#define STAGE_ELEMS (128*PB)

__device__ __forceinline__ void cp16(uint32_t dst, const void* src) {
    asm volatile("cp.async.cg.shared.global [%0], [%1], 16;" :: "r"(dst), "l"(src));
}
__device__ __forceinline__ void ldsm4(uint32_t* r, uint32_t addr) {
    asm volatile("ldmatrix.sync.aligned.m8n8.x4.shared.b16 {%0,%1,%2,%3}, [%4];"
        : "=r"(r[0]), "=r"(r[1]), "=r"(r[2]), "=r"(r[3]) : "r"(addr));
}

__device__ __forceinline__ void gemm_bf16_body(
    __nv_bfloat16* As, __nv_bfloat16* Ws,
    const __nv_bfloat16* __restrict__ A, const __nv_bfloat16* __restrict__ W,
    const float* __restrict__ bias, void* __restrict__ Cout,
    int N, int K, int ldA, int ldW, int act, int out_bf16, int bm, int bn)
{
    const int tid  = threadIdx.x;
    const int lane = tid & 31;
    const int wid  = tid >> 5;
    const int warpM = wid >> 2;
    const int warpN = wid & 3;
    const int gid = lane >> 2;
    const int tig = lane & 3;

    const int row_ld = tid >> 1;
    const int col_ld = (tid & 1) * 16;
    const __nv_bfloat16* Ag = A + (size_t)(bm + row_ld) * ldA + col_ld;
    const __nv_bfloat16* Wg = W + (size_t)(bn + row_ld) * ldW + col_ld;
    const uint32_t sA0 = (uint32_t)__cvta_generic_to_shared(As);
    const uint32_t sW0 = (uint32_t)__cvta_generic_to_shared(Ws);
    const uint32_t sAst = sA0 + (row_ld*PB + col_ld)*2;
    const uint32_t sWst = sW0 + (row_ld*PB + col_ld)*2;
    const uint32_t stageB = STAGE_ELEMS*2;

    const int a_row = lane & 15;
    const int a_k   = (lane >> 4) << 3;
    const int b_row = (lane & 7) | ((lane & 16) >> 1);
    const int b_k   = lane & 8;
    uint32_t aaddr[4], baddr[2];
#pragma unroll
    for (int mt = 0; mt < 4; mt++)
        aaddr[mt] = sA0 + ((warpM*64 + mt*16 + a_row)*PB + a_k)*2;
#pragma unroll
    for (int p = 0; p < 2; p++)
        baddr[p] = sW0 + ((warpN*32 + p*16 + b_row)*PB + b_k)*2;

    float acc[4][4][4];
#pragma unroll
    for (int mt = 0; mt < 4; mt++)
#pragma unroll
        for (int nt = 0; nt < 4; nt++)
#pragma unroll
            for (int r = 0; r < 4; r++) acc[mt][nt][r] = 0.f;

    const int KT = K >> 5;

    cp16(sAst,      Ag);
    cp16(sAst + 16, Ag + 8);
    cp16(sWst,      Wg);
    cp16(sWst + 16, Wg + 8);
    asm volatile("cp.async.commit_group;" ::: "memory");

    for (int kt = 0; kt < KT; kt++) {
        const uint32_t boff = (kt & 1) * stageB;
        if (kt + 1 < KT) {
            const uint32_t nb = ((kt + 1) & 1) * stageB;
            const __nv_bfloat16* ag = Ag + (kt + 1) * 32;
            const __nv_bfloat16* wg = Wg + (kt + 1) * 32;
            cp16(sAst + nb,      ag);
            cp16(sAst + nb + 16, ag + 8);
            cp16(sWst + nb,      wg);
            cp16(sWst + nb + 16, wg + 8);
            asm volatile("cp.async.commit_group;" ::: "memory");
            asm volatile("cp.async.wait_group 1;" ::: "memory");
        } else {
            asm volatile("cp.async.wait_group 0;" ::: "memory");
        }
        __syncthreads();

#pragma unroll
        for (int kk = 0; kk < 2; kk++) {
            uint32_t af[4][4], bfr[2][4];
#pragma unroll
            for (int mt = 0; mt < 4; mt++)
                ldsm4(af[mt], aaddr[mt] + boff + kk*32);
#pragma unroll
            for (int p = 0; p < 2; p++)
                ldsm4(bfr[p], baddr[p] + boff + kk*32);
#pragma unroll
            for (int mt = 0; mt < 4; mt++)
#pragma unroll
                for (int nt = 0; nt < 4; nt++) {
                    float* d = acc[mt][nt];
                    asm volatile(
                        "mma.sync.aligned.m16n8k16.row.col.f32.bf16.bf16.f32 "
                        "{%0,%1,%2,%3},{%4,%5,%6,%7},{%8,%9},{%0,%1,%2,%3};"
                        : "+f"(d[0]), "+f"(d[1]), "+f"(d[2]), "+f"(d[3])
                        : "r"(af[mt][0]), "r"(af[mt][1]), "r"(af[mt][2]), "r"(af[mt][3]),
                          "r"(bfr[nt>>1][(nt&1)*2]), "r"(bfr[nt>>1][(nt&1)*2+1]));
                }
        }
        __syncthreads();
    }

#pragma unroll
    for (int mt = 0; mt < 4; mt++) {
        int row = bm + warpM*64 + mt*16 + gid;
#pragma unroll
        for (int nt = 0; nt < 4; nt++) {
            int col = bn + warpN*32 + nt*8 + tig*2;
            float b0 = bias ? bias[col]     : 0.f;
            float b1 = bias ? bias[col + 1] : 0.f;
            float v0 = acc[mt][nt][0] + b0;
            float v1 = acc[mt][nt][1] + b1;
            float v2 = acc[mt][nt][2] + b0;
            float v3 = acc[mt][nt][3] + b1;
            if (act) { v0 = tanha(v0); v1 = tanha(v1); v2 = tanha(v2); v3 = tanha(v3); }
            if (out_bf16) {
                __nv_bfloat16* Cb = (__nv_bfloat16*)Cout;
                __nv_bfloat162 lo; lo.x = __float2bfloat16(v0); lo.y = __float2bfloat16(v1);
                __nv_bfloat162 hi; hi.x = __float2bfloat16(v2); hi.y = __float2bfloat16(v3);
                *(__nv_bfloat162*)&Cb[(size_t)row       * N + col] = lo;
                *(__nv_bfloat162*)&Cb[(size_t)(row + 8) * N + col] = hi;
            } else {
                float* Cf = (float*)Cout;
                *(float2*)&Cf[(size_t)row       * N + col] = make_float2(v0, v1);
                *(float2*)&Cf[(size_t)(row + 8) * N + col] = make_float2(v2, v3);
            }
        }
    }
}

__global__ __launch_bounds__(256)
void gemm_bf16_k(const __nv_bfloat16* __restrict__ A, const __nv_bfloat16* __restrict__ W,
                 const float* __restrict__ bias, void* __restrict__ Cout,
                 int N, int K, int ldA, int ldW, int act, int out_bf16)
{
    __shared__ __nv_bfloat16 As[2*STAGE_ELEMS];
    __shared__ __nv_bfloat16 Ws[2*STAGE_ELEMS];
    gemm_bf16_body(As, Ws, A, W, bias, Cout, N, K, ldA, ldW, act, out_bf16,
                   blockIdx.y*128, blockIdx.x*128);
}

// ---------------- mega1: L2 GEMM (fused tanh(encpb+hidatt) A-op) + vocab(t-1) ----------------
__global__ __launch_bounds__(256)
void mega1_k(const __nv_bfloat16* __restrict__ encpb, const float* __restrict__ hgh,
             const __nv_bfloat16* __restrict__ W2b, const float* __restrict__ b2,
             __nv_bfloat16* __restrict__ a2b,
             const __nv_bfloat16* __restrict__ hidb, const __nv_bfloat16* __restrict__ outWb,
             const float* __restrict__ out_b, float* __restrict__ logits, int do_vocab)
{
    __shared__ __nv_bfloat16 As[2*STAGE_ELEMS];
    __shared__ __nv_bfloat16 Ws[2*STAGE_ELEMS];
    if (blockIdx.x >= 256) {
        if (do_vocab)
            gemm_bf16_body(As, Ws, hidb, outWb, out_b, logits, VOCAB, HH, HH, HH, 0, 0,
                           0, (int)(blockIdx.x - 256)*128);
        return;
    }
    const int bm = (blockIdx.x >> 2) * 128;
    const int bn = (blockIdx.x & 3) * 128;
    const int tid  = threadIdx.x;
    const int lane = tid & 31;
    const int wid  = tid >> 5;
    const int warpM = wid >> 2;
    const int warpN = wid & 3;
    const int gid = lane >> 2;
    const int tig = lane & 3;

    const int row_ld = tid >> 1;
    const int col_ld = (tid & 1) * 16;
    const int brow = (bm + row_ld) >> 6;
    const __nv_bfloat16* Ag = encpb + (size_t)(bm + row_ld) * HH + col_ld;
    const float* Hg = hgh + brow*2048 + col_ld;
    const __nv_bfloat16* Wg = W2b + (size_t)(bn + row_ld) * HH + col_ld;
    const uint32_t sA0 = (uint32_t)__cvta_generic_to_shared(As);
    const uint32_t sW0 = (uint32_t)__cvta_generic_to_shared(Ws);
    const uint32_t sWst = sW0 + (row_ld*PB + col_ld)*2;
    const uint32_t stageB = STAGE_ELEMS*2;

    const int a_row = lane & 15;
    const int a_k   = (lane >> 4) << 3;
    const int b_row = (lane & 7) | ((lane & 16) >> 1);
    const int b_k   = lane & 8;
    uint32_t aaddr[4], baddr[2];
#pragma unroll
    for (int mt = 0; mt < 4; mt++)
        aaddr[mt] = sA0 + ((warpM*64 + mt*16 + a_row)*PB + a_k)*2;
#pragma unroll
    for (int p = 0; p < 2; p++)
        baddr[p] = sW0 + ((warpN*32 + p*16 + b_row)*PB + b_k)*2;

    float acc[4][4][4];
#pragma unroll
    for (int mt = 0; mt < 4; mt++)
#pragma unroll
        for (int nt = 0; nt < 4; nt++)
#pragma unroll
            for (int r = 0; r < 4; r++) acc[mt][nt][r] = 0.f;

    cp16(sWst,      Wg);
    cp16(sWst + 16, Wg + 8);
    asm volatile("cp.async.commit_group;" ::: "memory");

    for (int kt = 0; kt < 16; kt++) {
        const uint32_t boff = (kt & 1) * stageB;
        // stage A(kt): tanh(encpb + hidatt) -> bf16 -> smem
        {
            const __nv_bfloat16* ag = Ag + kt*32;
            uint4 e0 = *(const uint4*)(ag);
            uint4 e1 = *(const uint4*)(ag + 8);
            const float* hp = Hg + kt*32;
            float4 h0 = *(const float4*)(hp);
            float4 h1 = *(const float4*)(hp + 4);
            float4 h2 = *(const float4*)(hp + 8);
            float4 h3 = *(const float4*)(hp + 12);
            float hf[16] = {h0.x,h0.y,h0.z,h0.w, h1.x,h1.y,h1.z,h1.w,
                            h2.x,h2.y,h2.z,h2.w, h3.x,h3.y,h3.z,h3.w};
            uint4 o0, o1;
            const __nv_bfloat162* pe = (const __nv_bfloat162*)&e0;
            __nv_bfloat162* po = (__nv_bfloat162*)&o0;
#pragma unroll
            for (int q = 0; q < 4; q++) {
                float2 f = __bfloat1622float2(pe[q]);
                __nv_bfloat162 r;
                r.x = __float2bfloat16(tanha(f.x + hf[2*q]));
                r.y = __float2bfloat16(tanha(f.y + hf[2*q+1]));
                po[q] = r;
            }
            pe = (const __nv_bfloat162*)&e1;
            po = (__nv_bfloat162*)&o1;
#pragma unroll
            for (int q = 0; q < 4; q++) {
                float2 f = __bfloat1622float2(pe[q]);
                __nv_bfloat162 r;
                r.x = __float2bfloat16(tanha(f.x + hf[8 + 2*q]));
                r.y = __float2bfloat16(tanha(f.y + hf[8 + 2*q+1]));
                po[q] = r;
            }
            __nv_bfloat16* sA = As + (kt & 1)*STAGE_ELEMS + row_ld*PB + col_ld;
            *(uint4*)(sA)     = o0;
            *(uint4*)(sA + 8) = o1;
        }
        if (kt + 1 < 16) {
            const uint32_t nb = ((kt + 1) & 1) * stageB;
            const __nv_bfloat16* wg = Wg + (kt + 1) * 32;
            cp16(sWst + nb,      wg);
            cp16(sWst + nb + 16, wg + 8);
            asm volatile("cp.async.commit_group;" ::: "memory");
            asm volatile("cp.async.wait_group 1;" ::: "memory");
        } else {
            asm volatile("cp.async.wait_group 0;" ::: "memory");
        }
        __syncthreads();
#pragma unroll
        for (int kk = 0; kk < 2; kk++) {
            uint32_t af[4][4], bfr[2][4];
#pragma unroll
            for (int mt = 0; mt < 4; mt++)
                ldsm4(af[mt], aaddr[mt] + boff + kk*32);
#pragma unroll
            for (int p = 0; p < 2; p++)
                ldsm4(bfr[p], baddr[p] + boff + kk*32);
#pragma unroll
            for (int mt = 0; mt < 4; mt++)
#pragma unroll
                for (int nt = 0; nt < 4; nt++) {
                    float* d = acc[mt][nt];
                    asm volatile(
                        "mma.sync.aligned.m16n8k16.row.col.f32.bf16.bf16.f32 "
                        "{%0,%1,%2,%3},{%4,%5,%6,%7},{%8,%9},{%0,%1,%2,%3};"
                        : "+f"(d[0]), "+f"(d[1]), "+f"(d[2]), "+f"(d[3])
                        : "r"(af[mt][0]), "r"(af[mt][1]), "r"(af[mt][2]), "r"(af[mt][3]),
                          "r"(bfr[nt>>1][(nt&1)*2]), "r"(bfr[nt>>1][(nt&1)*2+1]));
                }
        }
        __syncthreads();
    }

    // epilogue: a2 = tanh(acc + b2) -> bf16
#pragma unroll
    for (int mt = 0; mt < 4; mt++) {
        int row = bm + warpM*64 + mt*16 + gid;
#pragma unroll
        for (int nt = 0; nt < 4; nt++) {
            int col = bn + warpN*32 + nt*8 + tig*2;
            float b0 = b2[col], b1 = b2[col + 1];
            __nv_bfloat162 lo, hi;
            lo.x = __float2bfloat16(tanha(acc[mt][nt][0] + b0));
            lo.y = __float2bfloat16(tanha(acc[mt][nt][1] + b1));
            hi.x = __float2bfloat16(tanha(acc[mt][nt][2] + b0));
            hi.y = __float2bfloat16(tanha(acc[mt][nt][3] + b1));
            *(__nv_bfloat162*)&a2b[(size_t)row       * HH + col] = lo;
            *(__nv_bfloat162*)&a2b[(size_t)(row + 8) * HH + col] = hi;
        }
    }
}

// ---------------- mega2: L3 GEMM + fused e-dot partials + logsoftmax(t-1) ----------------
__global__ __launch_bounds__(256)
void mega2_k(const __nv_bfloat16* __restrict__ a2b, const __nv_bfloat16* __restrict__ W3b,
             const float* __restrict__ b3, const float* __restrict__ v,
             float* __restrict__ epart,
             const float* __restrict__ logits, float* __restrict__ out,
             int t_lsm, int n_l3)
{
    const int tid = threadIdx.x;
    if ((int)blockIdx.x < n_l3) {
        __shared__ __nv_bfloat16 As[2*STAGE_ELEMS];
        __shared__ __nv_bfloat16 Ws[2*STAGE_ELEMS];
        __shared__ float vsh[128];
        __shared__ float esh4[4][128];
        const int bm = (blockIdx.x >> 2) * 128;
        const int bn = (blockIdx.x & 3) * 128;
        const int lane = tid & 31;
        const int wid  = tid >> 5;
        const int warpM = wid >> 2;
        const int warpN = wid & 3;
        const int gid = lane >> 2;
        const int tig = lane & 3;
        if (tid < 128) vsh[tid] = v[bn + tid];

        const int row_ld = tid >> 1;
        const int col_ld = (tid & 1) * 16;
        const __nv_bfloat16* Ag = a2b + (size_t)(bm + row_ld) * HH + col_ld;
        const __nv_bfloat16* Wg = W3b + (size_t)(bn + row_ld) * HH + col_ld;
        const uint32_t sA0 = (uint32_t)__cvta_generic_to_shared(As);
        const uint32_t sW0 = (uint32_t)__cvta_generic_to_shared(Ws);
        const uint32_t sAst = sA0 + (row_ld*PB + col_ld)*2;
        const uint32_t sWst = sW0 + (row_ld*PB + col_ld)*2;
        const uint32_t stageB = STAGE_ELEMS*2;

        const int a_row = lane & 15;
        const int a_k   = (lane >> 4) << 3;
        const int b_row = (lane & 7) | ((lane & 16) >> 1);
        const int b_k   = lane & 8;
        uint32_t aaddr[4], baddr[2];
#pragma unroll
        for (int mt = 0; mt < 4; mt++)
            aaddr[mt] = sA0 + ((warpM*64 + mt*16 + a_row)*PB + a_k)*2;
#pragma unroll
        for (int p = 0; p < 2; p++)
            baddr[p] = sW0 + ((warpN*32 + p*16 + b_row)*PB + b_k)*2;

        float acc[4][4][4];
#pragma unroll
        for (int mt = 0; mt < 4; mt++)
#pragma unroll
            for (int nt = 0; nt < 4; nt++)
#pragma unroll
                for (int r = 0; r < 4; r++) acc[mt][nt][r] = 0.f;

        cp16(sAst,      Ag);
        cp16(sAst + 16, Ag + 8);
        cp16(sWst,      Wg);
        cp16(sWst + 16, Wg + 8);
        asm volatile("cp.async.commit_group;" ::: "memory");

        for (int kt = 0; kt < 16; kt++) {
            const uint32_t boff = (kt & 1) * stageB;
            if (kt + 1 < 16) {
                const uint32_t nb = ((kt + 1) & 1) * stageB;
                const __nv_bfloat16* ag = Ag + (kt + 1) * 32;
                const __nv_bfloat16* wg = Wg + (kt + 1) * 32;
                cp16(sAst + nb,      ag);
                cp16(sAst + nb + 16, ag + 8);
                cp16(sWst + nb,      wg);
                cp16(sWst + nb + 16, wg + 8);
                asm volatile("cp.async.commit_group;" ::: "memory");
                asm volatile("cp.async.wait_group 1;" ::: "memory");
            } else {
                asm volatile("cp.async.wait_group 0;" ::: "memory");
            }
            __syncthreads();
#pragma unroll
            for (int kk = 0; kk < 2; kk++) {
                uint32_t af[4][4], bfr[2][4];
#pragma unroll
                for (int mt = 0; mt < 4; mt++)
                    ldsm4(af[mt], aaddr[mt] + boff + kk*32);
#pragma unroll
                for (int p = 0; p < 2; p++)
                    ldsm4(bfr[p], baddr[p] + boff + kk*32);
#pragma unroll
                for (int mt = 0; mt < 4; mt++)
#pragma unroll
                    for (int nt = 0; nt < 4; nt++) {
                        float* d = acc[mt][nt];
                        asm volatile(
                            "mma.sync.aligned.m16n8k16.row.col.f32.bf16.bf16.f32 "
                            "{%0,%1,%2,%3},{%4,%5,%6,%7},{%8,%9},{%0,%1,%2,%3};"
                            : "+f"(d[0]), "+f"(d[1]), "+f"(d[2]), "+f"(d[3])
                            : "r"(af[mt][0]), "r"(af[mt][1]), "r"(af[mt][2]), "r"(af[mt][3]),
                              "r"(bfr[nt>>1][(nt&1)*2]), "r"(bfr[nt>>1][(nt&1)*2+1]));
                    }
            }
            __syncthreads();
        }

        // epilogue: e-partials, no a3 materialization
        float rsum[4][2];
#pragma unroll
        for (int mt = 0; mt < 4; mt++) { rsum[mt][0] = 0.f; rsum[mt][1] = 0.f; }
#pragma unroll
        for (int mt = 0; mt < 4; mt++) {
#pragma unroll
            for (int nt = 0; nt < 4; nt++) {
                int cl = warpN*32 + nt*8 + tig*2;
                float b0 = b3[bn + cl], b1 = b3[bn + cl + 1];
                float vv0 = vsh[cl], vv1 = vsh[cl + 1];
                rsum[mt][0] += tanha(acc[mt][nt][0] + b0)*vv0 + tanha(acc[mt][nt][1] + b1)*vv1;
                rsum[mt][1] += tanha(acc[mt][nt][2] + b0)*vv0 + tanha(acc[mt][nt][3] + b1)*vv1;
            }
        }
#pragma unroll
        for (int mt = 0; mt < 4; mt++) {
#pragma unroll
            for (int r = 0; r < 2; r++) {
                float val = rsum[mt][r];
                val += __shfl_xor_sync(0xffffffffu, val, 1);
                val += __shfl_xor_sync(0xffffffffu, val, 2);
                if (tig == 0)
                    esh4[warpN][warpM*64 + mt*16 + gid + r*8] = val;
            }
        }
        __syncthreads();
        if (tid < 128)
            epart[(blockIdx.x & 3)*BL + bm + tid] =
                (esh4[0][tid] + esh4[1][tid]) + (esh4[2][tid] + esh4[3][tid]);
    } else {
        if (t_lsm < 0) return;
        int b = blockIdx.x - n_l3;
        const float4* row = (const float4*)(logits + (size_t)b * VOCAB);
        __shared__ float rm[256], rs[256];
        float m = -1e30f, s = 0.f;
        for (int i = tid; i < VOCAB/4; i += 256) {
            float4 vv = row[i];
#define ONLN(x) { float d = (x) - m; if (d > 0.f) { s = s*expf(-d) + 1.f; m = (x); } else s += expf(d); }
            ONLN(vv.x) ONLN(vv.y) ONLN(vv.z) ONLN(vv.w)
#undef ONLN
        }
        rm[tid] = m; rs[tid] = s; __syncthreads();
        for (int st = 128; st > 0; st >>= 1) {
            if (tid < st) {
                float m2 = rm[tid+st], s2 = rs[tid+st];
                float M = fmaxf(rm[tid], m2);
                rs[tid] = rs[tid]*expf(rm[tid]-M) + s2*expf(m2-M);
                rm[tid] = M;
            }
            __syncthreads();
        }
        float lse = rm[0] + logf(rs[0]);
        float4* orow = (float4*)(out + ((size_t)b * NSTEP + t_lsm) * VOCAB);
        for (int i = tid; i < VOCAB/4; i += 256) {
            float4 vv = row[i];
            vv.x -= lse; vv.y -= lse; vv.z -= lse; vv.w -= lse;
            orow[i] = vv;
        }
    }
}

// ---------------- alpha2: softmax(e) -> gic -> GRU ----------------
__global__ __launch_bounds__(256)
void alpha2_k(const float* __restrict__ epart, const __nv_bfloat16* __restrict__ encWc,
              const float* __restrict__ gix, const float* __restrict__ hgh,
              float* __restrict__ hid, __nv_bfloat16* __restrict__ hidb, int t)
{
    const int b = blockIdx.x, tid = threadIdx.x;
    __shared__ float e[LL];
    if (tid < LL) {
        int r = b*LL + tid;
        e[tid] = (epart[r] + epart[BL + r]) + (epart[2*BL + r] + epart[3*BL + r]);
    }
    __syncthreads();
    if (tid == 0) {
        float mx = -1e30f;
        for (int l = 0; l < LL; l++) mx = fmaxf(mx, e[l]);
        float sum = 0.f;
        for (int l = 0; l < LL; l++) { e[l] = expf(e[l] - mx); sum += e[l]; }
        float inv = 1.f / sum;
        for (int l = 0; l < LL; l++) e[l] *= inv;
    }
    __syncthreads();

    float2 ar = make_float2(0.f,0.f), az = make_float2(0.f,0.f), an = make_float2(0.f,0.f);
    const int j0 = tid * 2;
    const __nv_bfloat16* base = encWc + (size_t)b*LL*1536;
#pragma unroll 4
    for (int l = 0; l < LL; l++) {
        float al = e[l];
        const __nv_bfloat16* row = base + (size_t)l*1536;
        float2 r0 = __bfloat1622float2(*(const __nv_bfloat162*)(row + j0));
        float2 r1 = __bfloat1622float2(*(const __nv_bfloat162*)(row + 512 + j0));
        float2 r2 = __bfloat1622float2(*(const __nv_bfloat162*)(row + 1024 + j0));
        ar.x += al*r0.x; ar.y += al*r0.y;
        az.x += al*r1.x; az.y += al*r1.y;
        an.x += al*r2.x; an.y += al*r2.y;
    }

    const float* gx = gix + ((size_t)t*BB + b)*1536;
    const float* gh = hgh + b*2048 + 512;
    float gr[2] = {ar.x, ar.y}, gz[2] = {az.x, az.y}, gn[2] = {an.x, an.y};
#pragma unroll
    for (int q = 0; q < 2; q++) {
        int j = j0 + q;
        float rr = gx[j]        + gr[q] + gh[j];
        float zz = gx[512 + j]  + gz[q] + gh[512 + j];
        float nn = gx[1024 + j] + gn[q];
        float r = 1.f / (1.f + expf(-rr));
        float z = 1.f / (1.f + expf(-zz));
        float n = tanhf(nn + r * gh[1024 + j]);
        float h = (1.f - z) * n + z * hid[b*HH + j];
        hid[b*HH + j]  = h;
        hidb[b*HH + j] = __float2bfloat16(h);
    }
}

// ---------------- launch ----------------
extern "C" void kernel_launch(void* const* d_in, const int* in_sizes, int n_in,
                              void* d_out, int out_size)
{
    const float* enc     = (const float*)d_in[0];
    const float* enc_hid = (const float*)d_in[1];
    const int*   traw    = (const int*)  d_in[2];
    const float* embed_W = (const float*)d_in[3];
    const float* att_W1  = (const float*)d_in[4];
    const float* att_b1  = (const float*)d_in[5];
    const float* att_W2  = (const float*)d_in[6];
    const float* att_b2  = (const float*)d_in[7];
    const float* att_W3  = (const float*)d_in[8];
    const float* att_b3  = (const float*)d_in[9];
    const float* att_v   = (const float*)d_in[10];
    const float* gru_Wih = (const float*)d_in[11];
    const float* gru_Whh = (const float*)d_in[12];
    const float* gru_bih = (const float*)d_in[13];
    const float* gru_bhh = (const float*)d_in[14];
    const float* out_W   = (const float*)d_in[15];
    const float* out_b   = (const float*)d_in[16];
    float* out = (float*)d_out;

    float *encpart, *hid, *hgh, *gix, *logits, *bpack, *epart;
    __nv_bfloat16 *encpb, *encb, *a2b, *W2b, *W3b, *outWb, *hidb;
    __nv_bfloat16 *Wpackb, *Wihx, *Wihc, *ebx, *encWc;
    int *tgt;
    cudaGetSymbolAddress((void**)&encpart, g_encpart);
    cudaGetSymbolAddress((void**)&encpb,   g_encpb);
    cudaGetSymbolAddress((void**)&encb,    g_encb);
    cudaGetSymbolAddress((void**)&a2b,     g_a2b);
    cudaGetSymbolAddress((void**)&W2b,     g_W2b);
    cudaGetSymbolAddress((void**)&W3b,     g_W3b);
    cudaGetSymbolAddress((void**)&outWb,   g_outWb);
    cudaGetSymbolAddress((void**)&Wpackb,  g_Wpackb);
    cudaGetSymbolAddress((void**)&bpack,   g_bpack);
    cudaGetSymbolAddress((void**)&Wihx,    g_Wihx);
    cudaGetSymbolAddress((void**)&Wihc,    g_Wihc);
    cudaGetSymbolAddress((void**)&ebx,     g_ebx);
    cudaGetSymbolAddress((void**)&gix,     g_gix);
    cudaGetSymbolAddress((void**)&encWc,   g_encWc);
    cudaGetSymbolAddress((void**)&epart,   g_epart);
    cudaGetSymbolAddress((void**)&hidb,    g_hidb);
    cudaGetSymbolAddress((void**)&hid,     g_hid);
    cudaGetSymbolAddress((void**)&hgh,     g_hgh);
    cudaGetSymbolAddress((void**)&logits,  g_logits);
    cudaGetSymbolAddress((void**)&tgt,     g_tgt);

    // ---- setup ----
    convert_targets_k<<<1, 256>>>(traw, tgt, BB*TT);
    copyf_k<<<(BB*HH + 255)/256, 256>>>(hid, enc_hid, BB*HH);
    cvtf2b_k<<<(BB*HH)/256, 256>>>(enc_hid, hidb, BB*HH);
    pack_whhb_k<<<(2048*HH)/256, 256>>>(att_W1, gru_Whh, gru_bhh, Wpackb, bpack);
    pack_wih_k<<<(3*HH*HH)/256, 256>>>(gru_Wih, Wihx, Wihc);
    cvtf2b_k<<<(HH*HH)/256, 256>>>(att_W2, W2b, HH*HH);
    cvtf2b_k<<<(HH*HH)/256, 256>>>(att_W3, W3b, HH*HH);
    cvtf2b_k<<<(VOCAB*HH)/256, 256>>>(out_W, outWb, VOCAB*HH);
    cvtf2b_k<<<(BL*HH)/256, 256>>>(enc, encb, BL*HH);

    gather_embed_k<<<NSTEP*BB, 128>>>(embed_W, tgt, ebx);
    gemm_bf16_k<<<dim3(1536/128, NSTEP*BB/128), 256>>>(ebx, Wihx, gru_bih, gix,
                                                       1536, HH, HH, HH, 0, 0);
    gemm_bf16_k<<<dim3(1536/128, BL/128), 256>>>(encb, Wihc, nullptr, encWc,
                                                 1536, HH, HH, HH, 0, 1);
    gemm_tf32_k<<<dim3(HH/128, BL/128), 256>>>(enc, att_W1, att_b1, encpart,
                                               BL, HH, HH, HH, 2*HH, 0);
    cvtf2b_k<<<(BL*HH)/256, 256>>>(encpart, encpb, BL*HH);
    gemm_bf16_k<<<dim3(2048/128, 1), 256>>>(hidb, Wpackb, bpack, hgh,
                                            2048, HH, HH, HH, 0, 0);

    // ---- recurrent loop (4 launches/step) ----
    for (int t = 0; t < NSTEP; t++) {
        mega1_k<<<256 + NVB, 256>>>(encpb, hgh, W2b, att_b2, a2b,
                                    hidb, outWb, out_b, logits, t > 0);
        mega2_k<<<256 + BB, 256>>>(a2b, W3b, att_b3, att_v, epart,
                                   logits, out, t - 1, 256);
        alpha2_k<<<BB, 256>>>(epart, encWc, gix, hgh, hid, hidb, t);
        if (t + 1 < NSTEP)
            gemm_bf16_k<<<dim3(2048/128, 1), 256>>>(hidb, Wpackb, bpack, hgh,
                                                    2048, HH, HH, HH, 0, 0);
    }
    // tail: vocab(30) then logsoftmax(30)
    gemm_bf16_k<<<dim3(NVB, 1), 256>>>(hidb, outWb, out_b, logits,
                                       VOCAB, HH, HH, HH, 0, 0);
    mega2_k<<<BB, 256>>>(a2b, W3b, att_b3, att_v, epart, logits, out, NSTEP - 1, 0);

    (void)in_sizes; (void)n_in; (void)out_size;
}

// round 8
// speedup vs baseline: 7.0941x; 1.1409x over previous
#include <cuda_runtime.h>
#include <cuda_bf16.h>
#include <math.h>
#include <stdint.h>

#define BB 128
#define LL 64
#define HH 512
#define VOCAB 32000
#define TT 32
#define NSTEP 31
#define BL (BB*LL)       // 8192
#define NVB (VOCAB/128)  // 250

// ---------------- scratch (device globals; no allocation) ----------------
__device__ float g_encpart[BL*HH];
__device__ __nv_bfloat16 g_encpb[BL*HH];
__device__ __nv_bfloat16 g_encb[BL*HH];
__device__ __nv_bfloat16 g_a2b[BL*HH];
__device__ __nv_bfloat16 g_W2b[HH*HH];
__device__ __nv_bfloat16 g_W3b[HH*HH];
__device__ __nv_bfloat16 g_outWb[(size_t)VOCAB*HH];
__device__ __nv_bfloat16 g_Wpackb[2048*HH];
__device__ float g_bpack[2048];
__device__ __nv_bfloat16 g_Wihx[3*HH*HH];
__device__ __nv_bfloat16 g_Wihc[3*HH*HH];
__device__ __nv_bfloat16 g_ebx[NSTEP*BB*HH];
__device__ float g_gix[(size_t)NSTEP*BB*3*HH];
__device__ __nv_bfloat16 g_encWc[(size_t)BL*3*HH];
__device__ float g_epart[4*BL];
__device__ __nv_bfloat16 g_hidb0[BB*HH];
__device__ __nv_bfloat16 g_hidb1[BB*HH];
__device__ float g_hid[BB*HH];
__device__ float g_hgh[BB*2048];                 // [hidatt(512) | gh(1536)]
__device__ float g_logits[BB*VOCAB];
__device__ int   g_tgt[BB*TT];
__device__ unsigned int g_sync;

__device__ __forceinline__ float tanha(float x) {
    float y; asm("tanh.approx.f32 %0, %1;" : "=f"(y) : "f"(x)); return y;
}

// ---------------- setup helpers ----------------
__global__ void convert_targets_k(const int* __restrict__ raw, int* __restrict__ tgt, int n)
{
    __shared__ int nonzero;
    if (threadIdx.x == 0) nonzero = 0;
    __syncthreads();
    int bad = 0;
    for (int i = 2*threadIdx.x + 1; i < n; i += 2*blockDim.x) bad |= raw[i];
    if (bad) atomicOr(&nonzero, 1);
    __syncthreads();
    int is64 = (nonzero == 0);
    for (int i = threadIdx.x; i < n; i += blockDim.x)
        tgt[i] = is64 ? raw[2*i] : raw[i];
}

__global__ void copyf_k(float* __restrict__ dst, const float* __restrict__ src, int n)
{
    int i = blockIdx.x*blockDim.x + threadIdx.x;
    if (i < n) dst[i] = src[i];
}

__global__ void cvtf2b_k(const float* __restrict__ src, __nv_bfloat16* __restrict__ dst, int n)
{
    int i = blockIdx.x*256 + threadIdx.x;
    if (i < n) dst[i] = __float2bfloat16(src[i]);
}

__global__ void pack_whhb_k(const float* __restrict__ W1, const float* __restrict__ Whh,
                            const float* __restrict__ bhh,
                            __nv_bfloat16* __restrict__ Wp, float* __restrict__ bp)
{
    int idx = blockIdx.x * 256 + threadIdx.x;   // < 2048*512
    int nn = idx >> 9, k = idx & 511;
    float v = (nn < 512) ? W1[nn*1024 + 512 + k] : Whh[(nn-512)*512 + k];
    Wp[idx] = __float2bfloat16(v);
    if (idx < 2048) bp[idx] = (idx < 512) ? 0.f : bhh[idx - 512];
}

__global__ void pack_wih_k(const float* __restrict__ Wih,
                           __nv_bfloat16* __restrict__ Wx, __nv_bfloat16* __restrict__ Wc)
{
    int idx = blockIdx.x * 256 + threadIdx.x;   // < 1536*512
    int n = idx >> 9, k = idx & 511;
    Wx[idx] = __float2bfloat16(Wih[n*1024 + k]);
    Wc[idx] = __float2bfloat16(Wih[n*1024 + 512 + k]);
}

__global__ void gather_embed_k(const float* __restrict__ embed_W, const int* __restrict__ tgt,
                               __nv_bfloat16* __restrict__ ebx)
{
    int r = blockIdx.x;          // t*BB + b
    int t = r >> 7, b = r & 127;
    int row = tgt[b*TT + t];
    const float4* src = (const float4*)(embed_W + (size_t)row*HH);
    __nv_bfloat16* dst = ebx + (size_t)r*HH;
    for (int c = threadIdx.x; c < HH/4; c += 128) {
        float4 v = src[c];
        __nv_bfloat162 p0; p0.x = __float2bfloat16(v.x); p0.y = __float2bfloat16(v.y);
        __nv_bfloat162 p1; p1.x = __float2bfloat16(v.z); p1.y = __float2bfloat16(v.w);
        *(__nv_bfloat162*)(dst + c*4)     = p0;
        *(__nv_bfloat162*)(dst + c*4 + 2) = p1;
    }
}

// ---------------- TF32 GEMM (one-time encpart only) ----------------
#define PITCH 20
__device__ __forceinline__ uint32_t f2tf(float x) {
    uint32_t u; asm("cvt.rna.tf32.f32 %0, %1;" : "=r"(u) : "f"(x)); return u;
}

__global__ __launch_bounds__(256)
void gemm_tf32_k(const float* __restrict__ A, const float* __restrict__ W,
                 const float* __restrict__ bias, float* __restrict__ C,
                 int M, int N, int K, int ldA, int ldW, int act)
{
    __shared__ float As[128*PITCH];
    __shared__ float Ws[128*PITCH];
    const int tid  = threadIdx.x;
    const int lane = tid & 31;
    const int wid  = tid >> 5;
    const int warpM = wid >> 2;
    const int warpN = wid & 3;
    const int gid = lane >> 2;
    const int tig = lane & 3;
    const int bm = blockIdx.y * 128;
    const int bn = blockIdx.x * 128;

    const int r0 = tid >> 2;
    const int q0 = (tid & 3) * 4;
    const float* Ag0 = A + (size_t)(bm + r0)      * ldA + q0;
    const float* Ag1 = A + (size_t)(bm + r0 + 64) * ldA + q0;
    const float* Wg0 = W + (size_t)(bn + r0)      * ldW + q0;
    const float* Wg1 = W + (size_t)(bn + r0 + 64) * ldW + q0;
    const int s0 = r0 * PITCH + q0;
    const int s1 = s0 + 64 * PITCH;

    float acc[4][4][4];
#pragma unroll
    for (int mt = 0; mt < 4; mt++)
#pragma unroll
        for (int nt = 0; nt < 4; nt++)
#pragma unroll
            for (int r = 0; r < 4; r++) acc[mt][nt][r] = 0.f;

    const int KT = K >> 4;
    float4 av0, av1, wv0, wv1;
    av0 = *(const float4*)(Ag0); av1 = *(const float4*)(Ag1);
    wv0 = *(const float4*)(Wg0); wv1 = *(const float4*)(Wg1);
    {
        uint4 t;
        t.x=f2tf(av0.x); t.y=f2tf(av0.y); t.z=f2tf(av0.z); t.w=f2tf(av0.w);
        *(uint4*)(As + s0) = t;
        t.x=f2tf(av1.x); t.y=f2tf(av1.y); t.z=f2tf(av1.z); t.w=f2tf(av1.w);
        *(uint4*)(As + s1) = t;
        t.x=f2tf(wv0.x); t.y=f2tf(wv0.y); t.z=f2tf(wv0.z); t.w=f2tf(wv0.w);
        *(uint4*)(Ws + s0) = t;
        t.x=f2tf(wv1.x); t.y=f2tf(wv1.y); t.z=f2tf(wv1.z); t.w=f2tf(wv1.w);
        *(uint4*)(Ws + s1) = t;
    }

    for (int kt = 0; kt < KT; kt++) {
        __syncthreads();
        if (kt + 1 < KT) {
            int k0 = (kt + 1) << 4;
            av0 = *(const float4*)(Ag0 + k0); av1 = *(const float4*)(Ag1 + k0);
            wv0 = *(const float4*)(Wg0 + k0); wv1 = *(const float4*)(Wg1 + k0);
        }
#pragma unroll
        for (int ks = 0; ks < 16; ks += 8) {
            uint32_t af[4][4], bf[4][2];
#pragma unroll
            for (int mt = 0; mt < 4; mt++) {
                const float* p = &As[(warpM*64 + mt*16 + gid) * PITCH + ks + tig];
                af[mt][0] = __float_as_uint(p[0]);
                af[mt][1] = __float_as_uint(p[8*PITCH]);
                af[mt][2] = __float_as_uint(p[4]);
                af[mt][3] = __float_as_uint(p[8*PITCH + 4]);
            }
#pragma unroll
            for (int nt = 0; nt < 4; nt++) {
                const float* p = &Ws[(warpN*32 + nt*8 + gid) * PITCH + ks + tig];
                bf[nt][0] = __float_as_uint(p[0]);
                bf[nt][1] = __float_as_uint(p[4]);
            }
#pragma unroll
            for (int mt = 0; mt < 4; mt++)
#pragma unroll
                for (int nt = 0; nt < 4; nt++) {
                    float* d = acc[mt][nt];
                    asm volatile(
                        "mma.sync.aligned.m16n8k8.row.col.f32.tf32.tf32.f32 "
                        "{%0,%1,%2,%3},{%4,%5,%6,%7},{%8,%9},{%0,%1,%2,%3};"
                        : "+f"(d[0]), "+f"(d[1]), "+f"(d[2]), "+f"(d[3])
                        : "r"(af[mt][0]), "r"(af[mt][1]), "r"(af[mt][2]), "r"(af[mt][3]),
                          "r"(bf[nt][0]), "r"(bf[nt][1]));
                }
        }
        __syncthreads();
        if (kt + 1 < KT) {
            uint4 t;
            t.x=f2tf(av0.x); t.y=f2tf(av0.y); t.z=f2tf(av0.z); t.w=f2tf(av0.w);
            *(uint4*)(As + s0) = t;
            t.x=f2tf(av1.x); t.y=f2tf(av1.y); t.z=f2tf(av1.z); t.w=f2tf(av1.w);
            *(uint4*)(As + s1) = t;
            t.x=f2tf(wv0.x); t.y=f2tf(wv0.y); t.z=f2tf(wv0.z); t.w=f2tf(wv0.w);
            *(uint4*)(Ws + s0) = t;
            t.x=f2tf(wv1.x); t.y=f2tf(wv1.y); t.z=f2tf(wv1.z); t.w=f2tf(wv1.w);
            *(uint4*)(Ws + s1) = t;
        }
    }

#pragma unroll
    for (int mt = 0; mt < 4; mt++) {
        int row = bm + warpM*64 + mt*16 + gid;
#pragma unroll
        for (int nt = 0; nt < 4; nt++) {
            int col = bn + warpN*32 + nt*8 + tig*2;
            float b0 = bias ? bias[col]     : 0.f;
            float b1 = bias ? bias[col + 1] : 0.f;
            float v0 = acc[mt][nt][0] + b0;
            float v1 = acc[mt][nt][1] + b1;
            float v2 = acc[mt][nt][2] + b0;
            float v3 = acc[mt][nt][3] + b1;
            if (act) { v0 = tanhf(v0); v1 = tanhf(v1); v2 = tanhf(v2); v3 = tanhf(v3); }
            *(float2*)&C[(size_t)row       * N + col] = make_float2(v0, v1);
            *(float2*)&C[(size_t)(row + 8) * N + col] = make_float2(v2, v3);
        }
    }
}

// ---------------- BF16 GEMM core (cp.async 2-stage + ldmatrix) ----------------
#define PB 40
#define STAGE_ELEMS (128*PB)

__device__ __forceinline__ void cp16(uint32_t dst, const void* src) {
    asm volatile("cp.async.cg.shared.global [%0], [%1], 16;" :: "r"(dst), "l"(src));
}
__device__ __forceinline__ void ldsm4(uint32_t* r, uint32_t addr) {
    asm volatile("ldmatrix.sync.aligned.m8n8.x4.shared.b16 {%0,%1,%2,%3}, [%4];"
        : "=r"(r[0]), "=r"(r[1]), "=r"(r[2]), "=r"(r[3]) : "r"(addr));
}

__device__ __forceinline__ void gemm_bf16_body(
    __nv_bfloat16* As, __nv_bfloat16* Ws,
    const __nv_bfloat16* __restrict__ A, const __nv_bfloat16* __restrict__ W,
    const float* __restrict__ bias, void* __restrict__ Cout,
    int N, int K, int ldA, int ldW, int act, int out_bf16, int bm, int bn)
{
    const int tid  = threadIdx.x;
    const int lane = tid & 31;
    const int wid  = tid >> 5;
    const int warpM = wid >> 2;
    const int warpN = wid & 3;
    const int gid = lane >> 2;
    const int tig = lane & 3;

    const int row_ld = tid >> 1;
    const int col_ld = (tid & 1) * 16;
    const __nv_bfloat16* Ag = A + (size_t)(bm + row_ld) * ldA + col_ld;
    const __nv_bfloat16* Wg = W + (size_t)(bn + row_ld) * ldW + col_ld;
    const uint32_t sA0 = (uint32_t)__cvta_generic_to_shared(As);
    const uint32_t sW0 = (uint32_t)__cvta_generic_to_shared(Ws);
    const uint32_t sAst = sA0 + (row_ld*PB + col_ld)*2;
    const uint32_t sWst = sW0 + (row_ld*PB + col_ld)*2;
    const uint32_t stageB = STAGE_ELEMS*2;

    const int a_row = lane & 15;
    const int a_k   = (lane >> 4) << 3;
    const int b_row = (lane & 7) | ((lane & 16) >> 1);
    const int b_k   = lane & 8;
    uint32_t aaddr[4], baddr[2];
#pragma unroll
    for (int mt = 0; mt < 4; mt++)
        aaddr[mt] = sA0 + ((warpM*64 + mt*16 + a_row)*PB + a_k)*2;
#pragma unroll
    for (int p = 0; p < 2; p++)
        baddr[p] = sW0 + ((warpN*32 + p*16 + b_row)*PB + b_k)*2;

    float acc[4][4][4];
#pragma unroll
    for (int mt = 0; mt < 4; mt++)
#pragma unroll
        for (int nt = 0; nt < 4; nt++)
#pragma unroll
            for (int r = 0; r < 4; r++) acc[mt][nt][r] = 0.f;

    const int KT = K >> 5;

    cp16(sAst,      Ag);
    cp16(sAst + 16, Ag + 8);
    cp16(sWst,      Wg);
    cp16(sWst + 16, Wg + 8);
    asm volatile("cp.async.commit_group;" ::: "memory");

    for (int kt = 0; kt < KT; kt++) {
        const uint32_t boff = (kt & 1) * stageB;
        if (kt + 1 < KT) {
            const uint32_t nb = ((kt + 1) & 1) * stageB;
            const __nv_bfloat16* ag = Ag + (kt + 1) * 32;
            const __nv_bfloat16* wg = Wg + (kt + 1) * 32;
            cp16(sAst + nb,      ag);
            cp16(sAst + nb + 16, ag + 8);
            cp16(sWst + nb,      wg);
            cp16(sWst + nb + 16, wg + 8);
            asm volatile("cp.async.commit_group;" ::: "memory");
            asm volatile("cp.async.wait_group 1;" ::: "memory");
        } else {
            asm volatile("cp.async.wait_group 0;" ::: "memory");
        }
        __syncthreads();

#pragma unroll
        for (int kk = 0; kk < 2; kk++) {
            uint32_t af[4][4], bfr[2][4];
#pragma unroll
            for (int mt = 0; mt < 4; mt++)
                ldsm4(af[mt], aaddr[mt] + boff + kk*32);
#pragma unroll
            for (int p = 0; p < 2; p++)
                ldsm4(bfr[p], baddr[p] + boff + kk*32);
#pragma unroll
            for (int mt = 0; mt < 4; mt++)
#pragma unroll
                for (int nt = 0; nt < 4; nt++) {
                    float* d = acc[mt][nt];
                    asm volatile(
                        "mma.sync.aligned.m16n8k16.row.col.f32.bf16.bf16.f32 "
                        "{%0,%1,%2,%3},{%4,%5,%6,%7},{%8,%9},{%0,%1,%2,%3};"
                        : "+f"(d[0]), "+f"(d[1]), "+f"(d[2]), "+f"(d[3])
                        : "r"(af[mt][0]), "r"(af[mt][1]), "r"(af[mt][2]), "r"(af[mt][3]),
                          "r"(bfr[nt>>1][(nt&1)*2]), "r"(bfr[nt>>1][(nt&1)*2+1]));
                }
        }
        __syncthreads();
    }

#pragma unroll
    for (int mt = 0; mt < 4; mt++) {
        int row = bm + warpM*64 + mt*16 + gid;
#pragma unroll
        for (int nt = 0; nt < 4; nt++) {
            int col = bn + warpN*32 + nt*8 + tig*2;
            float b0 = bias ? bias[col]     : 0.f;
            float b1 = bias ? bias[col + 1] : 0.f;
            float v0 = acc[mt][nt][0] + b0;
            float v1 = acc[mt][nt][1] + b1;
            float v2 = acc[mt][nt][2] + b0;
            float v3 = acc[mt][nt][3] + b1;
            if (act) { v0 = tanha(v0); v1 = tanha(v1); v2 = tanha(v2); v3 = tanha(v3); }
            if (out_bf16) {
                __nv_bfloat16* Cb = (__nv_bfloat16*)Cout;
                __nv_bfloat162 lo; lo.x = __float2bfloat16(v0); lo.y = __float2bfloat16(v1);
                __nv_bfloat162 hi; hi.x = __float2bfloat16(v2); hi.y = __float2bfloat16(v3);
                *(__nv_bfloat162*)&Cb[(size_t)row       * N + col] = lo;
                *(__nv_bfloat162*)&Cb[(size_t)(row + 8) * N + col] = hi;
            } else {
                float* Cf = (float*)Cout;
                *(float2*)&Cf[(size_t)row       * N + col] = make_float2(v0, v1);
                *(float2*)&Cf[(size_t)(row + 8) * N + col] = make_float2(v2, v3);
            }
        }
    }
}

__global__ __launch_bounds__(256)
void gemm_bf16_k(const __nv_bfloat16* __restrict__ A, const __nv_bfloat16* __restrict__ W,
                 const float* __restrict__ bias, void* __restrict__ Cout,
                 int N, int K, int ldA, int ldW, int act, int out_bf16)
{
    __shared__ __nv_bfloat16 As[2*STAGE_ELEMS];
    __shared__ __nv_bfloat16 Ws[2*STAGE_ELEMS];
    gemm_bf16_body(As, Ws, A, W, bias, Cout, N, K, ldA, ldW, act, out_bf16,
                   blockIdx.y*128, blockIdx.x*128);
}

// ---------------- L2 GEMM with fused tanh(encpb + hidatt) A-operand ----------------
__global__ __launch_bounds__(256)
void megaL2_k(const __nv_bfloat16* __restrict__ encpb, const float* __restrict__ hgh,
              const __nv_bfloat16* __restrict__ W2b, const float* __restrict__ b2,
              __nv_bfloat16* __restrict__ a2b)
{
    __shared__ __nv_bfloat16 As[2*STAGE_ELEMS];
    __shared__ __nv_bfloat16 Ws[2*STAGE_ELEMS];
    const int bm = (blockIdx.x >> 2) * 128;
    const int bn = (blockIdx.x & 3) * 128;
    const int tid  = threadIdx.x;
    const int lane = tid & 31;
    const int wid  = tid >> 5;
    const int warpM = wid >> 2;
    const int warpN = wid & 3;
    const int gid = lane >> 2;
    const int tig = lane & 3;

    const int row_ld = tid >> 1;
    const int col_ld = (tid & 1) * 16;
    const int brow = (bm + row_ld) >> 6;
    const __nv_bfloat16* Ag = encpb + (size_t)(bm + row_ld) * HH + col_ld;
    const float* Hg = hgh + brow*2048 + col_ld;
    const __nv_bfloat16* Wg = W2b + (size_t)(bn + row_ld) * HH + col_ld;
    const uint32_t sA0 = (uint32_t)__cvta_generic_to_shared(As);
    const uint32_t sW0 = (uint32_t)__cvta_generic_to_shared(Ws);
    const uint32_t sWst = sW0 + (row_ld*PB + col_ld)*2;
    const uint32_t stageB = STAGE_ELEMS*2;

    const int a_row = lane & 15;
    const int a_k   = (lane >> 4) << 3;
    const int b_row = (lane & 7) | ((lane & 16) >> 1);
    const int b_k   = lane & 8;
    uint32_t aaddr[4], baddr[2];
#pragma unroll
    for (int mt = 0; mt < 4; mt++)
        aaddr[mt] = sA0 + ((warpM*64 + mt*16 + a_row)*PB + a_k)*2;
#pragma unroll
    for (int p = 0; p < 2; p++)
        baddr[p] = sW0 + ((warpN*32 + p*16 + b_row)*PB + b_k)*2;

    float acc[4][4][4];
#pragma unroll
    for (int mt = 0; mt < 4; mt++)
#pragma unroll
        for (int nt = 0; nt < 4; nt++)
#pragma unroll
            for (int r = 0; r < 4; r++) acc[mt][nt][r] = 0.f;

    cp16(sWst,      Wg);
    cp16(sWst + 16, Wg + 8);
    asm volatile("cp.async.commit_group;" ::: "memory");

    for (int kt = 0; kt < 16; kt++) {
        const uint32_t boff = (kt & 1) * stageB;
        {
            const __nv_bfloat16* ag = Ag + kt*32;
            uint4 e0 = *(const uint4*)(ag);
            uint4 e1 = *(const uint4*)(ag + 8);
            const float* hp = Hg + kt*32;
            float4 h0 = *(const float4*)(hp);
            float4 h1 = *(const float4*)(hp + 4);
            float4 h2 = *(const float4*)(hp + 8);
            float4 h3 = *(const float4*)(hp + 12);
            float hf[16] = {h0.x,h0.y,h0.z,h0.w, h1.x,h1.y,h1.z,h1.w,
                            h2.x,h2.y,h2.z,h2.w, h3.x,h3.y,h3.z,h3.w};
            uint4 o0, o1;
            const __nv_bfloat162* pe = (const __nv_bfloat162*)&e0;
            __nv_bfloat162* po = (__nv_bfloat162*)&o0;
#pragma unroll
            for (int q = 0; q < 4; q++) {
                float2 f = __bfloat1622float2(pe[q]);
                __nv_bfloat162 r;
                r.x = __float2bfloat16(tanha(f.x + hf[2*q]));
                r.y = __float2bfloat16(tanha(f.y + hf[2*q+1]));
                po[q] = r;
            }
            pe = (const __nv_bfloat162*)&e1;
            po = (__nv_bfloat162*)&o1;
#pragma unroll
            for (int q = 0; q < 4; q++) {
                float2 f = __bfloat1622float2(pe[q]);
                __nv_bfloat162 r;
                r.x = __float2bfloat16(tanha(f.x + hf[8 + 2*q]));
                r.y = __float2bfloat16(tanha(f.y + hf[8 + 2*q+1]));
                po[q] = r;
            }
            __nv_bfloat16* sA = As + (kt & 1)*STAGE_ELEMS + row_ld*PB + col_ld;
            *(uint4*)(sA)     = o0;
            *(uint4*)(sA + 8) = o1;
        }
        if (kt + 1 < 16) {
            const uint32_t nb = ((kt + 1) & 1) * stageB;
            const __nv_bfloat16* wg = Wg + (kt + 1) * 32;
            cp16(sWst + nb,      wg);
            cp16(sWst + nb + 16, wg + 8);
            asm volatile("cp.async.commit_group;" ::: "memory");
            asm volatile("cp.async.wait_group 1;" ::: "memory");
        } else {
            asm volatile("cp.async.wait_group 0;" ::: "memory");
        }
        __syncthreads();
#pragma unroll
        for (int kk = 0; kk < 2; kk++) {
            uint32_t af[4][4], bfr[2][4];
#pragma unroll
            for (int mt = 0; mt < 4; mt++)
                ldsm4(af[mt], aaddr[mt] + boff + kk*32);
#pragma unroll
            for (int p = 0; p < 2; p++)
                ldsm4(bfr[p], baddr[p] + boff + kk*32);
#pragma unroll
            for (int mt = 0; mt < 4; mt++)
#pragma unroll
                for (int nt = 0; nt < 4; nt++) {
                    float* d = acc[mt][nt];
                    asm volatile(
                        "mma.sync.aligned.m16n8k16.row.col.f32.bf16.bf16.f32 "
                        "{%0,%1,%2,%3},{%4,%5,%6,%7},{%8,%9},{%0,%1,%2,%3};"
                        : "+f"(d[0]), "+f"(d[1]), "+f"(d[2]), "+f"(d[3])
                        : "r"(af[mt][0]), "r"(af[mt][1]), "r"(af[mt][2]), "r"(af[mt][3]),
                          "r"(bfr[nt>>1][(nt&1)*2]), "r"(bfr[nt>>1][(nt&1)*2+1]));
                }
        }
        __syncthreads();
    }

#pragma unroll
    for (int mt = 0; mt < 4; mt++) {
        int row = bm + warpM*64 + mt*16 + gid;
#pragma unroll
        for (int nt = 0; nt < 4; nt++) {
            int col = bn + warpN*32 + nt*8 + tig*2;
            float b0 = b2[col], b1 = b2[col + 1];
            __nv_bfloat162 lo, hi;
            lo.x = __float2bfloat16(tanha(acc[mt][nt][0] + b0));
            lo.y = __float2bfloat16(tanha(acc[mt][nt][1] + b1));
            hi.x = __float2bfloat16(tanha(acc[mt][nt][2] + b0));
            hi.y = __float2bfloat16(tanha(acc[mt][nt][3] + b1));
            *(__nv_bfloat162*)&a2b[(size_t)row       * HH + col] = lo;
            *(__nv_bfloat162*)&a2b[(size_t)(row + 8) * HH + col] = hi;
        }
    }
}

// ---------------- L3 GEMM + fused e-dot partials (also resets spin counter) ----------------
__global__ __launch_bounds__(256)
void megaL3e_k(const __nv_bfloat16* __restrict__ a2b, const __nv_bfloat16* __restrict__ W3b,
               const float* __restrict__ b3, const float* __restrict__ v,
               float* __restrict__ epart)
{
    if (blockIdx.x == 0 && threadIdx.x == 0) g_sync = 0;
    __shared__ __nv_bfloat16 As[2*STAGE_ELEMS];
    __shared__ __nv_bfloat16 Ws[2*STAGE_ELEMS];
    __shared__ float vsh[128];
    __shared__ float esh4[4][128];
    const int tid = threadIdx.x;
    const int bm = (blockIdx.x >> 2) * 128;
    const int bn = (blockIdx.x & 3) * 128;
    const int lane = tid & 31;
    const int wid  = tid >> 5;
    const int warpM = wid >> 2;
    const int warpN = wid & 3;
    const int gid = lane >> 2;
    const int tig = lane & 3;
    if (tid < 128) vsh[tid] = v[bn + tid];

    const int row_ld = tid >> 1;
    const int col_ld = (tid & 1) * 16;
    const __nv_bfloat16* Ag = a2b + (size_t)(bm + row_ld) * HH + col_ld;
    const __nv_bfloat16* Wg = W3b + (size_t)(bn + row_ld) * HH + col_ld;
    const uint32_t sA0 = (uint32_t)__cvta_generic_to_shared(As);
    const uint32_t sW0 = (uint32_t)__cvta_generic_to_shared(Ws);
    const uint32_t sAst = sA0 + (row_ld*PB + col_ld)*2;
    const uint32_t sWst = sW0 + (row_ld*PB + col_ld)*2;
    const uint32_t stageB = STAGE_ELEMS*2;

    const int a_row = lane & 15;
    const int a_k   = (lane >> 4) << 3;
    const int b_row = (lane & 7) | ((lane & 16) >> 1);
    const int b_k   = lane & 8;
    uint32_t aaddr[4], baddr[2];
#pragma unroll
    for (int mt = 0; mt < 4; mt++)
        aaddr[mt] = sA0 + ((warpM*64 + mt*16 + a_row)*PB + a_k)*2;
#pragma unroll
    for (int p = 0; p < 2; p++)
        baddr[p] = sW0 + ((warpN*32 + p*16 + b_row)*PB + b_k)*2;

    float acc[4][4][4];
#pragma unroll
    for (int mt = 0; mt < 4; mt++)
#pragma unroll
        for (int nt = 0; nt < 4; nt++)
#pragma unroll
            for (int r = 0; r < 4; r++) acc[mt][nt][r] = 0.f;

    cp16(sAst,      Ag);
    cp16(sAst + 16, Ag + 8);
    cp16(sWst,      Wg);
    cp16(sWst + 16, Wg + 8);
    asm volatile("cp.async.commit_group;" ::: "memory");

    for (int kt = 0; kt < 16; kt++) {
        const uint32_t boff = (kt & 1) * stageB;
        if (kt + 1 < 16) {
            const uint32_t nb = ((kt + 1) & 1) * stageB;
            const __nv_bfloat16* ag = Ag + (kt + 1) * 32;
            const __nv_bfloat16* wg = Wg + (kt + 1) * 32;
            cp16(sAst + nb,      ag);
            cp16(sAst + nb + 16, ag + 8);
            cp16(sWst + nb,      wg);
            cp16(sWst + nb + 16, wg + 8);
            asm volatile("cp.async.commit_group;" ::: "memory");
            asm volatile("cp.async.wait_group 1;" ::: "memory");
        } else {
            asm volatile("cp.async.wait_group 0;" ::: "memory");
        }
        __syncthreads();
#pragma unroll
        for (int kk = 0; kk < 2; kk++) {
            uint32_t af[4][4], bfr[2][4];
#pragma unroll
            for (int mt = 0; mt < 4; mt++)
                ldsm4(af[mt], aaddr[mt] + boff + kk*32);
#pragma unroll
            for (int p = 0; p < 2; p++)
                ldsm4(bfr[p], baddr[p] + boff + kk*32);
#pragma unroll
            for (int mt = 0; mt < 4; mt++)
#pragma unroll
                for (int nt = 0; nt < 4; nt++) {
                    float* d = acc[mt][nt];
                    asm volatile(
                        "mma.sync.aligned.m16n8k16.row.col.f32.bf16.bf16.f32 "
                        "{%0,%1,%2,%3},{%4,%5,%6,%7},{%8,%9},{%0,%1,%2,%3};"
                        : "+f"(d[0]), "+f"(d[1]), "+f"(d[2]), "+f"(d[3])
                        : "r"(af[mt][0]), "r"(af[mt][1]), "r"(af[mt][2]), "r"(af[mt][3]),
                          "r"(bfr[nt>>1][(nt&1)*2]), "r"(bfr[nt>>1][(nt&1)*2+1]));
                }
        }
        __syncthreads();
    }

    float rsum[4][2];
#pragma unroll
    for (int mt = 0; mt < 4; mt++) { rsum[mt][0] = 0.f; rsum[mt][1] = 0.f; }
#pragma unroll
    for (int mt = 0; mt < 4; mt++) {
#pragma unroll
        for (int nt = 0; nt < 4; nt++) {
            int cl = warpN*32 + nt*8 + tig*2;
            float b0 = b3[bn + cl], b1 = b3[bn + cl + 1];
            float vv0 = vsh[cl], vv1 = vsh[cl + 1];
            rsum[mt][0] += tanha(acc[mt][nt][0] + b0)*vv0 + tanha(acc[mt][nt][1] + b1)*vv1;
            rsum[mt][1] += tanha(acc[mt][nt][2] + b0)*vv0 + tanha(acc[mt][nt][3] + b1)*vv1;
        }
    }
#pragma unroll
    for (int mt = 0; mt < 4; mt++) {
#pragma unroll
        for (int r = 0; r < 2; r++) {
            float val = rsum[mt][r];
            val += __shfl_xor_sync(0xffffffffu, val, 1);
            val += __shfl_xor_sync(0xffffffffu, val, 2);
            if (tig == 0)
                esh4[warpN][warpM*64 + mt*16 + gid + r*8] = val;
        }
    }
    __syncthreads();
    if (tid < 128)
        epart[(blockIdx.x & 3)*BL + bm + tid] =
            (esh4[0][tid] + esh4[1][tid]) + (esh4[2][tid] + esh4[3][tid]);
}

// ---------------- standalone log-softmax ----------------
__global__ __launch_bounds__(256)
void lsm_k(const float* __restrict__ logits, float* __restrict__ out, int t_lsm)
{
    const int tid = threadIdx.x;
    int b = blockIdx.x;
    const float4* row = (const float4*)(logits + (size_t)b * VOCAB);
    __shared__ float rm[256], rs[256];
    float m = -1e30f, s = 0.f;
    for (int i = tid; i < VOCAB/4; i += 256) {
        float4 vv = row[i];
#define ONLN(x) { float d = (x) - m; if (d > 0.f) { s = s*expf(-d) + 1.f; m = (x); } else s += expf(d); }
        ONLN(vv.x) ONLN(vv.y) ONLN(vv.z) ONLN(vv.w)
#undef ONLN
    }
    rm[tid] = m; rs[tid] = s; __syncthreads();
    for (int st = 128; st > 0; st >>= 1) {
        if (tid < st) {
            float m2 = rm[tid+st], s2 = rs[tid+st];
            float M = fmaxf(rm[tid], m2);
            rs[tid] = rs[tid]*expf(rm[tid]-M) + s2*expf(m2-M);
            rm[tid] = M;
        }
        __syncthreads();
    }
    float lse = rm[0] + logf(rs[0]);
    float4* orow = (float4*)(out + ((size_t)b * NSTEP + t_lsm) * VOCAB);
    for (int i = tid; i < VOCAB/4; i += 256) {
        float4 vv = row[i];
        vv.x -= lse; vv.y -= lse; vv.z -= lse; vv.w -= lse;
        orow[i] = vv;
    }
}

// ---------------- alphahgh: softmax->gic->GRU (128 blks) + hgh GEMM (16 blks, spin) ----------------
__global__ __launch_bounds__(256)
void alphahgh_k(const float* __restrict__ epart, const __nv_bfloat16* __restrict__ encWc,
                const float* __restrict__ gix, float* __restrict__ hgh,
                float* __restrict__ hid, __nv_bfloat16* __restrict__ hidb_next,
                const __nv_bfloat16* __restrict__ Wpackb, const float* __restrict__ bpack,
                int t)
{
    __shared__ __nv_bfloat16 As[2*STAGE_ELEMS];
    __shared__ __nv_bfloat16 Ws[2*STAGE_ELEMS];
    const int tid = threadIdx.x;

    if (blockIdx.x >= BB) {
        // hgh GEMM blocks: wait for all alpha blocks to commit hidb_next
        if (tid == 0) {
            while (atomicAdd(&g_sync, 0u) < BB) __nanosleep(64);
        }
        __syncthreads();
        __threadfence();
        gemm_bf16_body(As, Ws, hidb_next, Wpackb, bpack, hgh, 2048, HH, HH, HH, 0, 0,
                       0, (int)(blockIdx.x - BB)*128);
        return;
    }

    const int b = blockIdx.x;
    __shared__ float e[LL];
    if (tid < LL) {
        int r = b*LL + tid;
        e[tid] = (epart[r] + epart[BL + r]) + (epart[2*BL + r] + epart[3*BL + r]);
    }
    __syncthreads();
    if (tid == 0) {
        float mx = -1e30f;
        for (int l = 0; l < LL; l++) mx = fmaxf(mx, e[l]);
        float sum = 0.f;
        for (int l = 0; l < LL; l++) { e[l] = expf(e[l] - mx); sum += e[l]; }
        float inv = 1.f / sum;
        for (int l = 0; l < LL; l++) e[l] *= inv;
    }
    __syncthreads();

    float2 ar = make_float2(0.f,0.f), az = make_float2(0.f,0.f), an = make_float2(0.f,0.f);
    const int j0 = tid * 2;
    const __nv_bfloat16* base = encWc + (size_t)b*LL*1536;
#pragma unroll 4
    for (int l = 0; l < LL; l++) {
        float al = e[l];
        const __nv_bfloat16* row = base + (size_t)l*1536;
        float2 r0 = __bfloat1622float2(*(const __nv_bfloat162*)(row + j0));
        float2 r1 = __bfloat1622float2(*(const __nv_bfloat162*)(row + 512 + j0));
        float2 r2 = __bfloat1622float2(*(const __nv_bfloat162*)(row + 1024 + j0));
        ar.x += al*r0.x; ar.y += al*r0.y;
        az.x += al*r1.x; az.y += al*r1.y;
        an.x += al*r2.x; an.y += al*r2.y;
    }

    const float* gx = gix + ((size_t)t*BB + b)*1536;
    const float* gh = hgh + b*2048 + 512;
    float gr[2] = {ar.x, ar.y}, gz[2] = {az.x, az.y}, gn[2] = {an.x, an.y};
#pragma unroll
    for (int q = 0; q < 2; q++) {
        int j = j0 + q;
        float rr = gx[j]        + gr[q] + gh[j];
        float zz = gx[512 + j]  + gz[q] + gh[512 + j];
        float nn = gx[1024 + j] + gn[q];
        float r = 1.f / (1.f + expf(-rr));
        float z = 1.f / (1.f + expf(-zz));
        float n = tanhf(nn + r * gh[1024 + j]);
        float h = (1.f - z) * n + z * hid[b*HH + j];
        hid[b*HH + j]       = h;
        hidb_next[b*HH + j] = __float2bfloat16(h);
    }
    __threadfence();
    __syncthreads();
    if (tid == 0) atomicAdd(&g_sync, 1u);
}

// ---------------- launch ----------------
extern "C" void kernel_launch(void* const* d_in, const int* in_sizes, int n_in,
                              void* d_out, int out_size)
{
    const float* enc     = (const float*)d_in[0];
    const float* enc_hid = (const float*)d_in[1];
    const int*   traw    = (const int*)  d_in[2];
    const float* embed_W = (const float*)d_in[3];
    const float* att_W1  = (const float*)d_in[4];
    const float* att_b1  = (const float*)d_in[5];
    const float* att_W2  = (const float*)d_in[6];
    const float* att_b2  = (const float*)d_in[7];
    const float* att_W3  = (const float*)d_in[8];
    const float* att_b3  = (const float*)d_in[9];
    const float* att_v   = (const float*)d_in[10];
    const float* gru_Wih = (const float*)d_in[11];
    const float* gru_Whh = (const float*)d_in[12];
    const float* gru_bih = (const float*)d_in[13];
    const float* gru_bhh = (const float*)d_in[14];
    const float* out_W   = (const float*)d_in[15];
    const float* out_b   = (const float*)d_in[16];
    float* out = (float*)d_out;

    float *encpart, *hid, *hgh, *gix, *logits, *bpack, *epart;
    __nv_bfloat16 *encpb, *encb, *a2b, *W2b, *W3b, *outWb, *hidb0, *hidb1;
    __nv_bfloat16 *Wpackb, *Wihx, *Wihc, *ebx, *encWc;
    int *tgt;
    cudaGetSymbolAddress((void**)&encpart, g_encpart);
    cudaGetSymbolAddress((void**)&encpb,   g_encpb);
    cudaGetSymbolAddress((void**)&encb,    g_encb);
    cudaGetSymbolAddress((void**)&a2b,     g_a2b);
    cudaGetSymbolAddress((void**)&W2b,     g_W2b);
    cudaGetSymbolAddress((void**)&W3b,     g_W3b);
    cudaGetSymbolAddress((void**)&outWb,   g_outWb);
    cudaGetSymbolAddress((void**)&Wpackb,  g_Wpackb);
    cudaGetSymbolAddress((void**)&bpack,   g_bpack);
    cudaGetSymbolAddress((void**)&Wihx,    g_Wihx);
    cudaGetSymbolAddress((void**)&Wihc,    g_Wihc);
    cudaGetSymbolAddress((void**)&ebx,     g_ebx);
    cudaGetSymbolAddress((void**)&gix,     g_gix);
    cudaGetSymbolAddress((void**)&encWc,   g_encWc);
    cudaGetSymbolAddress((void**)&epart,   g_epart);
    cudaGetSymbolAddress((void**)&hidb0,   g_hidb0);
    cudaGetSymbolAddress((void**)&hidb1,   g_hidb1);
    cudaGetSymbolAddress((void**)&hid,     g_hid);
    cudaGetSymbolAddress((void**)&hgh,     g_hgh);
    cudaGetSymbolAddress((void**)&logits,  g_logits);
    cudaGetSymbolAddress((void**)&tgt,     g_tgt);
    __nv_bfloat16* hb[2] = {hidb0, hidb1};

    // persistent stream/events (created once, outside graph capture)
    static cudaStream_t s2 = nullptr;
    static cudaEvent_t evF = nullptr, evJ = nullptr, evV = nullptr;
    if (!s2) {
        cudaStreamCreateWithFlags(&s2, cudaStreamNonBlocking);
        cudaEventCreateWithFlags(&evF, cudaEventDisableTiming);
        cudaEventCreateWithFlags(&evJ, cudaEventDisableTiming);
        cudaEventCreateWithFlags(&evV, cudaEventDisableTiming);
    }

    // ---- setup (fork: encpart tf32 chain + vocab weight cvt on s2) ----
    cudaEventRecord(evF, 0);
    cudaStreamWaitEvent(s2, evF, 0);
    gemm_tf32_k<<<dim3(HH/128, BL/128), 256, 0, s2>>>(enc, att_W1, att_b1, encpart,
                                                      BL, HH, HH, HH, 2*HH, 0);
    cvtf2b_k<<<(BL*HH)/256, 256, 0, s2>>>(encpart, encpb, BL*HH);
    cvtf2b_k<<<(VOCAB*HH)/256, 256, 0, s2>>>(out_W, outWb, VOCAB*HH);

    convert_targets_k<<<1, 256>>>(traw, tgt, BB*TT);
    copyf_k<<<(BB*HH + 255)/256, 256>>>(hid, enc_hid, BB*HH);
    cvtf2b_k<<<(BB*HH)/256, 256>>>(enc_hid, hidb0, BB*HH);
    pack_whhb_k<<<(2048*HH)/256, 256>>>(att_W1, gru_Whh, gru_bhh, Wpackb, bpack);
    pack_wih_k<<<(3*HH*HH)/256, 256>>>(gru_Wih, Wihx, Wihc);
    cvtf2b_k<<<(HH*HH)/256, 256>>>(att_W2, W2b, HH*HH);
    cvtf2b_k<<<(HH*HH)/256, 256>>>(att_W3, W3b, HH*HH);
    cvtf2b_k<<<(BL*HH)/256, 256>>>(enc, encb, BL*HH);
    gather_embed_k<<<NSTEP*BB, 128>>>(embed_W, tgt, ebx);
    gemm_bf16_k<<<dim3(1536/128, NSTEP*BB/128), 256>>>(ebx, Wihx, gru_bih, gix,
                                                       1536, HH, HH, HH, 0, 0);
    gemm_bf16_k<<<dim3(1536/128, BL/128), 256>>>(encb, Wihc, nullptr, encWc,
                                                 1536, HH, HH, HH, 0, 1);
    gemm_bf16_k<<<dim3(2048/128, 1), 256>>>(hidb0, Wpackb, bpack, hgh,
                                            2048, HH, HH, HH, 0, 0);
    cudaEventRecord(evJ, s2);
    cudaStreamWaitEvent(0, evJ, 0);

    // ---- recurrent loop ----
    for (int t = 0; t < NSTEP; t++) {
        if (t > 0) {
            // branch A (s2): vocab(t-1) + logsoftmax(t-1), overlapped with branch B
            cudaEventRecord(evF, 0);                 // after alphahgh(t-1)
            cudaStreamWaitEvent(s2, evF, 0);
            gemm_bf16_k<<<dim3(NVB, 1), 256, 0, s2>>>(hb[t & 1], outWb, out_b, logits,
                                                      VOCAB, HH, HH, HH, 0, 0);
            cudaEventRecord(evV, s2);                // hidb read complete
            lsm_k<<<BB, 256, 0, s2>>>(logits, out, t - 1);
        }
        // branch B (stream 0): attention chain
        megaL2_k<<<256, 256>>>(encpb, hgh, W2b, att_b2, a2b);
        megaL3e_k<<<256, 256>>>(a2b, W3b, att_b3, att_v, epart);
        if (t > 0) cudaStreamWaitEvent(0, evV, 0);   // alphahgh(t) overwrites hb[(t+1)&1]
        alphahgh_k<<<BB + 16, 256>>>(epart, encWc, gix, hgh, hid, hb[(t + 1) & 1],
                                     Wpackb, bpack, t);
    }
    // join + tail: vocab(30) + logsoftmax(30)
    cudaEventRecord(evJ, s2);
    cudaStreamWaitEvent(0, evJ, 0);
    gemm_bf16_k<<<dim3(NVB, 1), 256>>>(hb[NSTEP & 1], outWb, out_b, logits,
                                       VOCAB, HH, HH, HH, 0, 0);
    lsm_k<<<BB, 256>>>(logits, out, NSTEP - 1);

    (void)in_sizes; (void)n_in; (void)out_size;
}